// round 9
// baseline (speedup 1.0000x reference)
#include <cuda_runtime.h>
#include <cuda_bf16.h>
#include <math.h>
#include <stdint.h>

// ---------------- problem constants ----------------
#define D_MODEL   1536
#define N_HEADS_C 24
#define DH        64
#define B_SZ      4
#define L_SEQ     2048
#define M_ROWS    (B_SZ * L_SEQ)     // 8192
#define QKV_COLS  (3 * D_MODEL)      // 4608
#define K_DIM     1536

// single dynamic smem symbol shared by all kernels
extern __shared__ char dyn_smem[];

// ---------------- scratch (device globals; no allocation allowed) ---------
__device__ __nv_bfloat16 g_qkvh[(size_t)M_ROWS * QKV_COLS];
__device__ __nv_bfloat16 g_qkvl[(size_t)M_ROWS * QKV_COLS];
__device__ __nv_bfloat16 g_xh[(size_t)M_ROWS * K_DIM];
__device__ __nv_bfloat16 g_xl[(size_t)M_ROWS * K_DIM];
__device__ __nv_bfloat16 g_wqh[(size_t)QKV_COLS * K_DIM];
__device__ __nv_bfloat16 g_wql[(size_t)QKV_COLS * K_DIM];
__device__ __nv_bfloat16 g_ah[(size_t)M_ROWS * K_DIM];
__device__ __nv_bfloat16 g_al[(size_t)M_ROWS * K_DIM];
__device__ __nv_bfloat16 g_woh[(size_t)D_MODEL * K_DIM];
__device__ __nv_bfloat16 g_wol[(size_t)D_MODEL * K_DIM];

// inv_freq[d] = 10000^(-d/32) = 10^(-d/8)
__constant__ float c_invf[32] = {
    1.0f, 0.7498942093324559f, 0.5623413251903491f, 0.42169650342858224f,
    0.31622776601683794f, 0.23713737056616552f, 0.1778279410038923f, 0.1333521432163324f,
    0.1f, 0.07498942093324558f, 0.05623413251903491f, 0.042169650342858224f,
    0.031622776601683794f, 0.023713737056616552f, 0.01778279410038923f, 0.01333521432163324f,
    0.01f, 0.007498942093324558f, 0.005623413251903491f, 0.0042169650342858224f,
    0.0031622776601683794f, 0.0023713737056616552f, 0.001778279410038923f, 0.0013335214321633241f,
    0.001f, 0.0007498942093324558f, 0.0005623413251903491f, 0.00042169650342858224f,
    0.00031622776601683794f, 0.00023713737056616552f, 0.0001778279410038923f, 0.00013335214321633242f
};

// ---------------- helpers --------------------------------------------------
__device__ __forceinline__ uint32_t smem_u32(const void* p) {
    uint32_t a;
    asm("{ .reg .u64 t; cvta.to.shared.u64 t, %1; cvt.u32.u64 %0, t; }" : "=r"(a) : "l"(p));
    return a;
}

#define CP_ASYNC16(dst, src) \
    asm volatile("cp.async.cg.shared.global [%0], [%1], 16;" :: "r"(dst), "l"(src))
#define CP_COMMIT() asm volatile("cp.async.commit_group;" ::: "memory")
#define CP_WAIT(N)  asm volatile("cp.async.wait_group %0;" :: "n"(N) : "memory")

#define LDSM_X4(r0, r1, r2, r3, addr) \
    asm volatile("ldmatrix.sync.aligned.m8n8.x4.shared.b16 {%0,%1,%2,%3}, [%4];" \
        : "=r"(r0), "=r"(r1), "=r"(r2), "=r"(r3) : "r"(addr))

#define LDSM_X4_T(r0, r1, r2, r3, addr) \
    asm volatile("ldmatrix.sync.aligned.m8n8.x4.trans.shared.b16 {%0,%1,%2,%3}, [%4];" \
        : "=r"(r0), "=r"(r1), "=r"(r2), "=r"(r3) : "r"(addr))

#define MMA_BF16(c, a, b0_, b1_) \
    asm volatile("mma.sync.aligned.m16n8k16.row.col.f32.bf16.bf16.f32 " \
        "{%0,%1,%2,%3}, {%4,%5,%6,%7}, {%8,%9}, {%0,%1,%2,%3};" \
        : "+f"((c)[0]), "+f"((c)[1]), "+f"((c)[2]), "+f"((c)[3]) \
        : "r"((a)[0]), "r"((a)[1]), "r"((a)[2]), "r"((a)[3]), "r"(b0_), "r"(b1_))

__device__ __forceinline__ uint32_t sw128(uint32_t off) {
    return off ^ ((off >> 3) & 0x70);
}

__device__ __forceinline__ uint32_t pack_bf16(float lo, float hi) {
    uint32_t d;
    asm("cvt.rn.bf16x2.f32 %0, %1, %2;" : "=r"(d) : "f"(hi), "f"(lo));
    return d;
}

__device__ __forceinline__ void sincos_rope(float fr, float* s, float* c) {
    float n  = rintf(fr * 0.15915494309189535f);
    float r1 = fmaf(n, -6.2831855f, fr);
    float r  = fmaf(n,  1.7484556e-7f, r1);
    __sincosf(r, s, c);
}

// ===========================================================================
// split fp32 -> bf16 hi + bf16 lo
// ===========================================================================
__global__ __launch_bounds__(256) void split_bf16(
    const float* __restrict__ s, __nv_bfloat16* __restrict__ hi,
    __nv_bfloat16* __restrict__ lo, int n4)
{
    int i = blockIdx.x * blockDim.x + threadIdx.x;
    if (i >= n4) return;
    float4 v = ((const float4*)s)[i];
    uint32_t h01 = pack_bf16(v.x, v.y);
    uint32_t h23 = pack_bf16(v.z, v.w);
    float f0 = __uint_as_float(h01 << 16), f1 = __uint_as_float(h01 & 0xFFFF0000u);
    float f2 = __uint_as_float(h23 << 16), f3 = __uint_as_float(h23 & 0xFFFF0000u);
    uint32_t l01 = pack_bf16(v.x - f0, v.y - f1);
    uint32_t l23 = pack_bf16(v.z - f2, v.w - f3);
    ((uint2*)hi)[i] = make_uint2(h01, h23);
    ((uint2*)lo)[i] = make_uint2(l01, l23);
}

// ===========================================================================
// Split-bf16 3-product GEMM via mma.sync — products OUTERMOST in the inner
// block so same-accumulator MMAs are 16 apart (RAW stall fix).
// ===========================================================================
#define GK_CHUNKS 24
#define TILE_B    16384
#define STAGE_B   (4 * TILE_B)
#define GEMM_SMEM (2 * STAGE_B)

__global__ __launch_bounds__(256, 1) void gemm_bf16x3(
    const __nv_bfloat16* __restrict__ Ah, const __nv_bfloat16* __restrict__ Al,
    const __nv_bfloat16* __restrict__ Bh, const __nv_bfloat16* __restrict__ Bl,
    float* __restrict__ C,
    __nv_bfloat16* __restrict__ Chi, __nv_bfloat16* __restrict__ Clo,
    const int* __restrict__ pos, int N)
{
    const uint32_t sbu = smem_u32(dyn_smem);

    const int tid  = threadIdx.x;
    const int wid  = tid >> 5;
    const int lane = tid & 31;
    const int wm   = wid & 1;
    const int wn   = wid >> 1;
    const int m0   = blockIdx.y * 128;
    const int n0   = blockIdx.x * 128;

    const __nv_bfloat16* srcs[4] = {
        Ah + (size_t)m0 * K_DIM, Al + (size_t)m0 * K_DIM,
        Bh + (size_t)n0 * K_DIM, Bl + (size_t)n0 * K_DIM };

    int unit_row[4], unit_u[4];
#pragma unroll
    for (int i = 0; i < 4; i++) {
        int unit = tid + i * 256;
        unit_row[i] = unit >> 3;
        unit_u[i]   = unit & 7;
    }

    auto load_stage = [&](int c, int s) {
        uint32_t sb = sbu + s * STAGE_B;
#pragma unroll
        for (int op = 0; op < 4; op++) {
            const __nv_bfloat16* src = srcs[op] + c * 64;
            uint32_t ob = sb + op * TILE_B;
#pragma unroll
            for (int i = 0; i < 4; i++) {
                const __nv_bfloat16* g = src + (size_t)unit_row[i] * K_DIM + unit_u[i] * 8;
                uint32_t d = ob + sw128(unit_row[i] * 128 + unit_u[i] * 16);
                CP_ASYNC16(d, g);
            }
        }
        CP_COMMIT();
    };

    float acc[4][4][4];
#pragma unroll
    for (int i = 0; i < 4; i++)
#pragma unroll
        for (int j = 0; j < 4; j++)
#pragma unroll
            for (int k = 0; k < 4; k++) acc[i][j][k] = 0.f;

    load_stage(0, 0);
    load_stage(1, 1);

    const int lrow = lane & 15;
    const int lhalf = (lane >> 4) * 16;

    for (int c = 0; c < GK_CHUNKS; c++) {
        if (c + 2 < GK_CHUNKS) { CP_WAIT(1); } else { CP_WAIT(0); }
        __syncthreads();

        const uint32_t sb = sbu + (c & 1) * STAGE_B;
        const uint32_t aH = sb + 0 * TILE_B;
        const uint32_t aL = sb + 1 * TILE_B;
        const uint32_t bH = sb + 2 * TILE_B;
        const uint32_t bL = sb + 3 * TILE_B;

#pragma unroll
        for (int k16 = 0; k16 < 4; k16++) {
            const uint32_t kb = k16 * 32 + lhalf;
            uint32_t ah[4][4], al[4][4];
#pragma unroll
            for (int i = 0; i < 4; i++) {
                int row = wm * 64 + i * 16 + lrow;
                uint32_t o = sw128(row * 128 + kb);
                LDSM_X4(ah[i][0], ah[i][1], ah[i][2], ah[i][3], aH + o);
                LDSM_X4(al[i][0], al[i][1], al[i][2], al[i][3], aL + o);
            }
            uint32_t bh[2][4], bl[2][4];
#pragma unroll
            for (int j = 0; j < 2; j++) {
                int row = wn * 32 + j * 16 + lrow;
                uint32_t o = sw128(row * 128 + kb);
                LDSM_X4(bh[j][0], bh[j][1], bh[j][2], bh[j][3], bH + o);
                LDSM_X4(bl[j][0], bl[j][1], bl[j][2], bl[j][3], bL + o);
            }
            // product-outermost: same-acc MMAs are 16 apart
#pragma unroll
            for (int i = 0; i < 4; i++)
#pragma unroll
                for (int jn = 0; jn < 4; jn++)
                    MMA_BF16(acc[i][jn], ah[i], bh[jn >> 1][jn & 1], bh[jn >> 1][(jn & 1) + 2]);
#pragma unroll
            for (int i = 0; i < 4; i++)
#pragma unroll
                for (int jn = 0; jn < 4; jn++)
                    MMA_BF16(acc[i][jn], ah[i], bl[jn >> 1][jn & 1], bl[jn >> 1][(jn & 1) + 2]);
#pragma unroll
            for (int i = 0; i < 4; i++)
#pragma unroll
                for (int jn = 0; jn < 4; jn++)
                    MMA_BF16(acc[i][jn], al[i], bh[jn >> 1][jn & 1], bh[jn >> 1][(jn & 1) + 2]);
        }
        __syncthreads();
        if (c + 2 < GK_CHUNKS) load_stage(c + 2, c & 1);
    }

    const int er = lane >> 2;
    const int ec = (lane & 3) * 2;

    if (!Chi) {
#pragma unroll
        for (int i = 0; i < 4; i++) {
            int r0 = m0 + wm * 64 + i * 16 + er;
#pragma unroll
            for (int jn = 0; jn < 4; jn++) {
                int col = n0 + wn * 32 + jn * 8 + ec;
                *(float2*)(C + (size_t)r0 * N + col)       = make_float2(acc[i][jn][0], acc[i][jn][1]);
                *(float2*)(C + (size_t)(r0 + 8) * N + col) = make_float2(acc[i][jn][2], acc[i][jn][3]);
            }
        }
    } else if (n0 >= 2 * D_MODEL) {
        // v section: direct register split-store (no rope)
#pragma unroll
        for (int i = 0; i < 4; i++) {
#pragma unroll
            for (int jn = 0; jn < 4; jn++) {
                int col = n0 + wn * 32 + jn * 8 + ec;
#pragma unroll
                for (int half = 0; half < 2; half++) {
                    int r = m0 + wm * 64 + i * 16 + er + half * 8;
                    float a0 = acc[i][jn][2 * half], a1 = acc[i][jn][2 * half + 1];
                    uint32_t hh = pack_bf16(a0, a1);
                    float f0 = __uint_as_float(hh << 16), f1 = __uint_as_float(hh & 0xFFFF0000u);
                    uint32_t ll = pack_bf16(a0 - f0, a1 - f1);
                    size_t o = (size_t)r * N + col;
                    *(uint32_t*)(Chi + o) = hh;
                    *(uint32_t*)(Clo + o) = ll;
                }
            }
        }
    } else {
        // q/k section: stage tile in smem, apply RoPE, split-store
        float* Ct = (float*)dyn_smem;                    // [128][130]
#pragma unroll
        for (int i = 0; i < 4; i++) {
            int rl = wm * 64 + i * 16 + er;
#pragma unroll
            for (int jn = 0; jn < 4; jn++) {
                int cl = wn * 32 + jn * 8 + ec;
                Ct[rl * 130 + cl]           = acc[i][jn][0];
                Ct[rl * 130 + cl + 1]       = acc[i][jn][1];
                Ct[(rl + 8) * 130 + cl]     = acc[i][jn][2];
                Ct[(rl + 8) * 130 + cl + 1] = acc[i][jn][3];
            }
        }
        __syncthreads();
        const int po = *pos;
#pragma unroll
        for (int it = 0; it < 32; it++) {
            int idx = tid + it * 256;
            int hd  = idx & 63;
            int row = idx >> 6;
            int d   = hd & 31;
            int cl  = (hd >> 5) * 64 + d;
            float x1 = Ct[row * 130 + cl];
            float x2 = Ct[row * 130 + cl + 32];
            int l = (m0 + row) & (L_SEQ - 1);
            float s, c;
            sincos_rope((float)(l + po) * c_invf[d], &s, &c);
            float y1 = x1 * c - x2 * s;
            float y2 = x2 * c + x1 * s;
            __nv_bfloat16 h1 = __float2bfloat16_rn(y1);
            __nv_bfloat16 h2 = __float2bfloat16_rn(y2);
            size_t o = (size_t)(m0 + row) * N + n0 + cl;
            Chi[o]      = h1;
            Chi[o + 32] = h2;
            Clo[o]      = __float2bfloat16_rn(y1 - __bfloat162float(h1));
            Clo[o + 32] = __float2bfloat16_rn(y2 - __bfloat162float(h2));
        }
    }
}

// ===========================================================================
// Tensor-core causal flash attention — product-outermost MMA ordering.
// ===========================================================================
#define FQH 0
#define FQL 16384
#define FST 32768
#define FSTG 32768
#define FA_SMEM (FST + 2 * FSTG)   // 98304

__global__ __launch_bounds__(256, 1) void attn_mma(
    const __nv_bfloat16* __restrict__ qkvh,
    const __nv_bfloat16* __restrict__ qkvl,
    __nv_bfloat16* __restrict__ ohp,
    __nv_bfloat16* __restrict__ olp)
{
    const uint32_t sbu = smem_u32(dyn_smem);
    const int tid  = threadIdx.x;
    const int wid  = tid >> 5;
    const int lane = tid & 31;
    const int lrow = lane & 15;
    const int lhalf = (lane >> 4) * 16;

    const int qt = gridDim.x - 1 - blockIdx.x;
    const int bh = blockIdx.y;
    const int b  = bh / N_HEADS_C;
    const int h  = bh % N_HEADS_C;
    const size_t rowbase = (size_t)b * L_SEQ;

    {
        int op  = tid >> 7;
        int row = tid & 127;
        const __nv_bfloat16* src = (op ? qkvl : qkvh)
            + (rowbase + qt * 128 + row) * QKV_COLS + h * DH;
        uint32_t dstb = sbu + (op ? FQL : FQH);
#pragma unroll
        for (int c = 0; c < 8; c++)
            CP_ASYNC16(dstb + sw128(row * 128 + c * 16), src + c * 8);
        CP_COMMIT();
    }

    const int ktmax = 2 * qt + 1;

    auto load_kv = [&](int kt, int s) {
        int op  = tid >> 6;
        int row = tid & 63;
        const __nv_bfloat16* base = (op & 1) ? qkvl : qkvh;
        int colofs = (op >> 1) ? (2 * D_MODEL + h * DH) : (D_MODEL + h * DH);
        const __nv_bfloat16* src = base + (rowbase + kt * 64 + row) * QKV_COLS + colofs;
        uint32_t dstb = sbu + FST + s * FSTG + op * 8192;
#pragma unroll
        for (int c = 0; c < 8; c++)
            CP_ASYNC16(dstb + sw128(row * 128 + c * 16), src + c * 8);
        CP_COMMIT();
    };

    load_kv(0, 0);
    load_kv(1, 1);

    CP_WAIT(2);
    __syncthreads();
    uint32_t qh[4][4], ql[4][4];
#pragma unroll
    for (int c = 0; c < 4; c++) {
        uint32_t o = sw128((wid * 16 + lrow) * 128 + c * 32 + lhalf);
        LDSM_X4(qh[c][0], qh[c][1], qh[c][2], qh[c][3], sbu + FQH + o);
        LDSM_X4(ql[c][0], ql[c][1], ql[c][2], ql[c][3], sbu + FQL + o);
    }

    float oa[8][4];
#pragma unroll
    for (int nt = 0; nt < 8; nt++)
#pragma unroll
        for (int r = 0; r < 4; r++) oa[nt][r] = 0.f;
    float m0 = -INFINITY, m1 = -INFINITY, l0 = 0.f, l1 = 0.f;

    const int row0 = qt * 128 + wid * 16 + (lane >> 2);
    const int row1 = row0 + 8;
    const int colq = 2 * (lane & 3);

    for (int kt = 0; kt <= ktmax; kt++) {
        if (kt + 2 <= ktmax) { CP_WAIT(1); } else { CP_WAIT(0); }
        __syncthreads();

        const uint32_t su = sbu + FST + (kt & 1) * FSTG;
        const uint32_t KH = su, KL = su + 8192, VH = su + 16384, VL = su + 24576;

        float sc[8][4];
#pragma unroll
        for (int nt = 0; nt < 8; nt++)
#pragma unroll
            for (int r = 0; r < 4; r++) sc[nt][r] = 0.f;

        // ---- scores: K frags for all 4 groups loaded per c; products outer ----
#pragma unroll
        for (int c = 0; c < 4; c++) {
            const uint32_t kb = c * 32 + lhalf;
            uint32_t kh4[4][4], kl4[4][4];
#pragma unroll
            for (int g = 0; g < 4; g++) {
                uint32_t o = sw128((g * 16 + lrow) * 128 + kb);
                LDSM_X4(kh4[g][0], kh4[g][1], kh4[g][2], kh4[g][3], KH + o);
                LDSM_X4(kl4[g][0], kl4[g][1], kl4[g][2], kl4[g][3], KL + o);
            }
#pragma unroll
            for (int g = 0; g < 4; g++) {
                MMA_BF16(sc[2 * g],     qh[c], kh4[g][0], kh4[g][2]);
                MMA_BF16(sc[2 * g + 1], qh[c], kh4[g][1], kh4[g][3]);
            }
#pragma unroll
            for (int g = 0; g < 4; g++) {
                MMA_BF16(sc[2 * g],     qh[c], kl4[g][0], kl4[g][2]);
                MMA_BF16(sc[2 * g + 1], qh[c], kl4[g][1], kl4[g][3]);
            }
#pragma unroll
            for (int g = 0; g < 4; g++) {
                MMA_BF16(sc[2 * g],     ql[c], kh4[g][0], kh4[g][2]);
                MMA_BF16(sc[2 * g + 1], ql[c], kh4[g][1], kh4[g][3]);
            }
        }

        const bool diag = (kt >= 2 * qt);
#pragma unroll
        for (int nt = 0; nt < 8; nt++) {
            int colg = kt * 64 + nt * 8 + colq;
#pragma unroll
            for (int r = 0; r < 4; r++) {
                float s = sc[nt][r] * 0.125f;
                if (diag) {
                    int cg = colg + (r & 1);
                    int rg = (r < 2) ? row0 : row1;
                    if (cg > rg) s = -1e30f;
                }
                sc[nt][r] = s;
            }
        }

        float rm0 = -INFINITY, rm1 = -INFINITY;
#pragma unroll
        for (int nt = 0; nt < 8; nt++) {
            rm0 = fmaxf(rm0, fmaxf(sc[nt][0], sc[nt][1]));
            rm1 = fmaxf(rm1, fmaxf(sc[nt][2], sc[nt][3]));
        }
        rm0 = fmaxf(rm0, __shfl_xor_sync(0xffffffffu, rm0, 1));
        rm0 = fmaxf(rm0, __shfl_xor_sync(0xffffffffu, rm0, 2));
        rm1 = fmaxf(rm1, __shfl_xor_sync(0xffffffffu, rm1, 1));
        rm1 = fmaxf(rm1, __shfl_xor_sync(0xffffffffu, rm1, 2));

        float m0n = fmaxf(m0, rm0), m1n = fmaxf(m1, rm1);
        float cr0 = __expf(m0 - m0n), cr1 = __expf(m1 - m1n);
        l0 *= cr0; l1 *= cr1;
#pragma unroll
        for (int nt = 0; nt < 8; nt++) {
            oa[nt][0] *= cr0; oa[nt][1] *= cr0;
            oa[nt][2] *= cr1; oa[nt][3] *= cr1;
        }
        m0 = m0n; m1 = m1n;

        uint32_t pha[8], phb[8], pla[8], plb[8];
#pragma unroll
        for (int nt = 0; nt < 8; nt++) {
            float p0 = __expf(sc[nt][0] - m0n);
            float p1 = __expf(sc[nt][1] - m0n);
            float p2 = __expf(sc[nt][2] - m1n);
            float p3 = __expf(sc[nt][3] - m1n);
            l0 += p0 + p1; l1 += p2 + p3;
            uint32_t h01 = pack_bf16(p0, p1);
            uint32_t h23 = pack_bf16(p2, p3);
            pha[nt] = h01; phb[nt] = h23;
            float f0 = __uint_as_float(h01 << 16), f1 = __uint_as_float(h01 & 0xFFFF0000u);
            float f2 = __uint_as_float(h23 << 16), f3 = __uint_as_float(h23 & 0xFFFF0000u);
            pla[nt] = pack_bf16(p0 - f0, p1 - f1);
            plb[nt] = pack_bf16(p2 - f2, p3 - f3);
        }

        // ---- PV: V frags for all 4 dp loaded per kc; products outer ----
#pragma unroll
        for (int kc = 0; kc < 4; kc++) {
            uint32_t pah[4] = { pha[2 * kc], phb[2 * kc], pha[2 * kc + 1], phb[2 * kc + 1] };
            uint32_t pal[4] = { pla[2 * kc], plb[2 * kc], pla[2 * kc + 1], plb[2 * kc + 1] };
            uint32_t vh4[4][4], vl4[4][4];
#pragma unroll
            for (int dp = 0; dp < 4; dp++) {
                uint32_t o = sw128((kc * 16 + lrow) * 128 + dp * 32 + lhalf);
                LDSM_X4_T(vh4[dp][0], vh4[dp][1], vh4[dp][2], vh4[dp][3], VH + o);
                LDSM_X4_T(vl4[dp][0], vl4[dp][1], vl4[dp][2], vl4[dp][3], VL + o);
            }
#pragma unroll
            for (int dp = 0; dp < 4; dp++) {
                MMA_BF16(oa[2 * dp],     pah, vh4[dp][0], vh4[dp][1]);
                MMA_BF16(oa[2 * dp + 1], pah, vh4[dp][2], vh4[dp][3]);
            }
#pragma unroll
            for (int dp = 0; dp < 4; dp++) {
                MMA_BF16(oa[2 * dp],     pah, vl4[dp][0], vl4[dp][1]);
                MMA_BF16(oa[2 * dp + 1], pah, vl4[dp][2], vl4[dp][3]);
            }
#pragma unroll
            for (int dp = 0; dp < 4; dp++) {
                MMA_BF16(oa[2 * dp],     pal, vh4[dp][0], vh4[dp][1]);
                MMA_BF16(oa[2 * dp + 1], pal, vh4[dp][2], vh4[dp][3]);
            }
        }

        __syncthreads();
        if (kt + 2 <= ktmax) load_kv(kt + 2, kt & 1);
    }

    l0 += __shfl_xor_sync(0xffffffffu, l0, 1);
    l0 += __shfl_xor_sync(0xffffffffu, l0, 2);
    l1 += __shfl_xor_sync(0xffffffffu, l1, 1);
    l1 += __shfl_xor_sync(0xffffffffu, l1, 2);
    float i0 = 1.f / l0, i1 = 1.f / l1;

    size_t ob0 = (rowbase + row0) * D_MODEL + h * DH;
    size_t ob1 = (rowbase + row1) * D_MODEL + h * DH;
#pragma unroll
    for (int nt = 0; nt < 8; nt++) {
        int col = nt * 8 + colq;
        float a0 = oa[nt][0] * i0, a1 = oa[nt][1] * i0;
        float a2 = oa[nt][2] * i1, a3 = oa[nt][3] * i1;
        uint32_t h01 = pack_bf16(a0, a1);
        uint32_t h23 = pack_bf16(a2, a3);
        float f0 = __uint_as_float(h01 << 16), f1 = __uint_as_float(h01 & 0xFFFF0000u);
        float f2 = __uint_as_float(h23 << 16), f3 = __uint_as_float(h23 & 0xFFFF0000u);
        *(uint32_t*)(ohp + ob0 + col) = h01;
        *(uint32_t*)(olp + ob0 + col) = pack_bf16(a0 - f0, a1 - f1);
        *(uint32_t*)(ohp + ob1 + col) = h23;
        *(uint32_t*)(olp + ob1 + col) = pack_bf16(a2 - f2, a3 - f3);
    }
}

// ===========================================================================
// launch
// ===========================================================================
extern "C" void kernel_launch(void* const* d_in, const int* in_sizes, int n_in,
                              void* d_out, int out_size)
{
    const float* x     = (const float*)d_in[0];
    const float* w_qkv = (const float*)d_in[1];
    const float* w_out = (const float*)d_in[2];
    const int*   pos   = (const int*)d_in[3];
    float*       out   = (float*)d_out;

    __nv_bfloat16 *qkvh, *qkvl, *xh, *xl, *wqh, *wql, *ah, *al, *woh, *wol;
    cudaGetSymbolAddress((void**)&qkvh, g_qkvh); cudaGetSymbolAddress((void**)&qkvl, g_qkvl);
    cudaGetSymbolAddress((void**)&xh, g_xh);   cudaGetSymbolAddress((void**)&xl, g_xl);
    cudaGetSymbolAddress((void**)&wqh, g_wqh); cudaGetSymbolAddress((void**)&wql, g_wql);
    cudaGetSymbolAddress((void**)&ah, g_ah);   cudaGetSymbolAddress((void**)&al, g_al);
    cudaGetSymbolAddress((void**)&woh, g_woh); cudaGetSymbolAddress((void**)&wol, g_wol);

    cudaFuncSetAttribute(gemm_bf16x3, cudaFuncAttributeMaxDynamicSharedMemorySize, GEMM_SMEM);
    cudaFuncSetAttribute(attn_mma, cudaFuncAttributeMaxDynamicSharedMemorySize, FA_SMEM);

    // 1) split inputs to bf16 hi/lo
    split_bf16<<<(M_ROWS * K_DIM / 4 + 255) / 256, 256>>>(x, xh, xl, M_ROWS * K_DIM / 4);
    split_bf16<<<(QKV_COLS * K_DIM / 4 + 255) / 256, 256>>>(w_qkv, wqh, wql, QKV_COLS * K_DIM / 4);

    // 2) QKV projection with fused RoPE + hi/lo split epilogue
    gemm_bf16x3<<<dim3(QKV_COLS / 128, M_ROWS / 128), 256, GEMM_SMEM>>>(
        xh, xl, wqh, wql, nullptr, qkvh, qkvl, pos, QKV_COLS);

    // 3) tensor-core causal flash attention -> bf16 hi/lo
    attn_mma<<<dim3(L_SEQ / 128, B_SZ * N_HEADS_C), 256, FA_SMEM>>>(qkvh, qkvl, ah, al);

    // 4) output projection (plain fp32 epilogue to d_out)
    split_bf16<<<(D_MODEL * K_DIM / 4 + 255) / 256, 256>>>(w_out, woh, wol, D_MODEL * K_DIM / 4);
    gemm_bf16x3<<<dim3(D_MODEL / 128, M_ROWS / 128), 256, GEMM_SMEM>>>(
        ah, al, woh, wol, out, nullptr, nullptr, nullptr, D_MODEL);
}

// round 10
// speedup vs baseline: 1.4810x; 1.4810x over previous
#include <cuda_runtime.h>
#include <cuda_bf16.h>
#include <math.h>
#include <stdint.h>

// ---------------- problem constants ----------------
#define D_MODEL   1536
#define N_HEADS_C 24
#define DH        64
#define B_SZ      4
#define L_SEQ     2048
#define M_ROWS    (B_SZ * L_SEQ)     // 8192
#define QKV_COLS  (3 * D_MODEL)      // 4608
#define K_DIM     1536

// single dynamic smem symbol shared by all kernels
extern __shared__ char dyn_smem[];

// ---------------- scratch (device globals; no allocation allowed) ---------
__device__ __nv_bfloat16 g_qkvh[(size_t)M_ROWS * QKV_COLS];
__device__ __nv_bfloat16 g_qkvl[(size_t)M_ROWS * QKV_COLS];
__device__ __nv_bfloat16 g_xh[(size_t)M_ROWS * K_DIM];
__device__ __nv_bfloat16 g_xl[(size_t)M_ROWS * K_DIM];
__device__ __nv_bfloat16 g_wqh[(size_t)QKV_COLS * K_DIM];
__device__ __nv_bfloat16 g_wql[(size_t)QKV_COLS * K_DIM];
__device__ __nv_bfloat16 g_ah[(size_t)M_ROWS * K_DIM];
__device__ __nv_bfloat16 g_al[(size_t)M_ROWS * K_DIM];
__device__ __nv_bfloat16 g_woh[(size_t)D_MODEL * K_DIM];
__device__ __nv_bfloat16 g_wol[(size_t)D_MODEL * K_DIM];

// inv_freq[d] = 10000^(-d/32) = 10^(-d/8)
__constant__ float c_invf[32] = {
    1.0f, 0.7498942093324559f, 0.5623413251903491f, 0.42169650342858224f,
    0.31622776601683794f, 0.23713737056616552f, 0.1778279410038923f, 0.1333521432163324f,
    0.1f, 0.07498942093324558f, 0.05623413251903491f, 0.042169650342858224f,
    0.031622776601683794f, 0.023713737056616552f, 0.01778279410038923f, 0.01333521432163324f,
    0.01f, 0.007498942093324558f, 0.005623413251903491f, 0.0042169650342858224f,
    0.0031622776601683794f, 0.0023713737056616552f, 0.001778279410038923f, 0.0013335214321633241f,
    0.001f, 0.0007498942093324558f, 0.0005623413251903491f, 0.00042169650342858224f,
    0.00031622776601683794f, 0.00023713737056616552f, 0.0001778279410038923f, 0.00013335214321633242f
};

// ---------------- helpers --------------------------------------------------
__device__ __forceinline__ uint32_t smem_u32(const void* p) {
    uint32_t a;
    asm("{ .reg .u64 t; cvta.to.shared.u64 t, %1; cvt.u32.u64 %0, t; }" : "=r"(a) : "l"(p));
    return a;
}

#define CP_ASYNC16(dst, src) \
    asm volatile("cp.async.cg.shared.global [%0], [%1], 16;" :: "r"(dst), "l"(src))
#define CP_COMMIT() asm volatile("cp.async.commit_group;" ::: "memory")
#define CP_WAIT(N)  asm volatile("cp.async.wait_group %0;" :: "n"(N) : "memory")

#define LDSM_X4(r0, r1, r2, r3, addr) \
    asm volatile("ldmatrix.sync.aligned.m8n8.x4.shared.b16 {%0,%1,%2,%3}, [%4];" \
        : "=r"(r0), "=r"(r1), "=r"(r2), "=r"(r3) : "r"(addr))

#define LDSM_X4_T(r0, r1, r2, r3, addr) \
    asm volatile("ldmatrix.sync.aligned.m8n8.x4.trans.shared.b16 {%0,%1,%2,%3}, [%4];" \
        : "=r"(r0), "=r"(r1), "=r"(r2), "=r"(r3) : "r"(addr))

#define MMA_BF16(c, a, b0_, b1_) \
    asm volatile("mma.sync.aligned.m16n8k16.row.col.f32.bf16.bf16.f32 " \
        "{%0,%1,%2,%3}, {%4,%5,%6,%7}, {%8,%9}, {%0,%1,%2,%3};" \
        : "+f"((c)[0]), "+f"((c)[1]), "+f"((c)[2]), "+f"((c)[3]) \
        : "r"((a)[0]), "r"((a)[1]), "r"((a)[2]), "r"((a)[3]), "r"(b0_), "r"(b1_))

__device__ __forceinline__ uint32_t sw128(uint32_t off) {
    return off ^ ((off >> 3) & 0x70);
}

__device__ __forceinline__ uint32_t pack_bf16(float lo, float hi) {
    uint32_t d;
    asm("cvt.rn.bf16x2.f32 %0, %1, %2;" : "=r"(d) : "f"(hi), "f"(lo));
    return d;
}

__device__ __forceinline__ void sincos_rope(float fr, float* s, float* c) {
    float n  = rintf(fr * 0.15915494309189535f);
    float r1 = fmaf(n, -6.2831855f, fr);
    float r  = fmaf(n,  1.7484556e-7f, r1);
    __sincosf(r, s, c);
}

// ===========================================================================
// split fp32 -> bf16 hi + bf16 lo
// ===========================================================================
__global__ __launch_bounds__(256) void split_bf16(
    const float* __restrict__ s, __nv_bfloat16* __restrict__ hi,
    __nv_bfloat16* __restrict__ lo, int n4)
{
    int i = blockIdx.x * blockDim.x + threadIdx.x;
    if (i >= n4) return;
    float4 v = ((const float4*)s)[i];
    uint32_t h01 = pack_bf16(v.x, v.y);
    uint32_t h23 = pack_bf16(v.z, v.w);
    float f0 = __uint_as_float(h01 << 16), f1 = __uint_as_float(h01 & 0xFFFF0000u);
    float f2 = __uint_as_float(h23 << 16), f3 = __uint_as_float(h23 & 0xFFFF0000u);
    uint32_t l01 = pack_bf16(v.x - f0, v.y - f1);
    uint32_t l23 = pack_bf16(v.z - f2, v.w - f3);
    ((uint2*)hi)[i] = make_uint2(h01, h23);
    ((uint2*)lo)[i] = make_uint2(l01, l23);
}

// ===========================================================================
// Split-bf16 3-product GEMM via mma.sync.
// CTA tile 128(M) x 192(N), BK=64, 384 threads = 12 warps (2M x 6N),
// warp tile 64x32 with the round-7 inner loop (interleaved products).
// smem: Ah 16K | Al 16K | Bh 24K | Bl 24K = 80KB/stage, double buffered.
// ===========================================================================
#define GK_CHUNKS 24
#define BN_G      192
#define A_TILE_B  16384                       // 128 x 128B
#define B_TILE_B  24576                       // 192 x 128B
#define STAGE_B   (2 * A_TILE_B + 2 * B_TILE_B)   // 81920
#define OFF_AH    0
#define OFF_AL    16384
#define OFF_BH    32768
#define OFF_BL    57344
#define GEMM_SMEM (2 * STAGE_B)               // 163840

__global__ __launch_bounds__(384, 1) void gemm_bf16x3(
    const __nv_bfloat16* __restrict__ Ah, const __nv_bfloat16* __restrict__ Al,
    const __nv_bfloat16* __restrict__ Bh, const __nv_bfloat16* __restrict__ Bl,
    float* __restrict__ C,
    __nv_bfloat16* __restrict__ Chi, __nv_bfloat16* __restrict__ Clo,
    const int* __restrict__ pos, int N)
{
    const uint32_t sbu = smem_u32(dyn_smem);

    const int tid  = threadIdx.x;
    const int wid  = tid >> 5;
    const int lane = tid & 31;
    const int wm   = wid & 1;                  // 0..1 (M, 64 rows)
    const int wn   = wid >> 1;                 // 0..5 (N, 32 cols)
    const int m0   = blockIdx.y * 128;
    const int n0   = blockIdx.x * BN_G;

    const __nv_bfloat16* Ahp = Ah + (size_t)m0 * K_DIM;
    const __nv_bfloat16* Alp = Al + (size_t)m0 * K_DIM;
    const __nv_bfloat16* Bhp = Bh + (size_t)n0 * K_DIM;
    const __nv_bfloat16* Blp = Bl + (size_t)n0 * K_DIM;

    auto load_stage = [&](int c, int s) {
        uint32_t sb = sbu + s * STAGE_B;
        // A: 2 tiles x 128 rows x 8 units = 2048 units
        for (int u = tid; u < 2048; u += 384) {
            int t = u >> 10;                   // 0=Ah 1=Al
            int r = (u & 1023) >> 3;
            int q = u & 7;
            const __nv_bfloat16* g = (t ? Alp : Ahp) + (size_t)r * K_DIM + c * 64 + q * 8;
            CP_ASYNC16(sb + (t ? OFF_AL : OFF_AH) + sw128(r * 128 + q * 16), g);
        }
        // B: 2 tiles x 192 rows x 8 units = 3072 units
        for (int u = tid; u < 3072; u += 384) {
            int t = (u >= 1536);
            int v = u - t * 1536;
            int r = v >> 3;
            int q = v & 7;
            const __nv_bfloat16* g = (t ? Blp : Bhp) + (size_t)r * K_DIM + c * 64 + q * 8;
            CP_ASYNC16(sb + (t ? OFF_BL : OFF_BH) + sw128(r * 128 + q * 16), g);
        }
        CP_COMMIT();
    };

    float acc[4][4][4];
#pragma unroll
    for (int i = 0; i < 4; i++)
#pragma unroll
        for (int j = 0; j < 4; j++)
#pragma unroll
            for (int k = 0; k < 4; k++) acc[i][j][k] = 0.f;

    load_stage(0, 0);
    load_stage(1, 1);

    const int lrow = lane & 15;
    const int lhalf = (lane >> 4) * 16;

    for (int c = 0; c < GK_CHUNKS; c++) {
        if (c + 2 < GK_CHUNKS) { CP_WAIT(1); } else { CP_WAIT(0); }
        __syncthreads();

        const uint32_t sb = sbu + (c & 1) * STAGE_B;
        const uint32_t aH = sb + OFF_AH;
        const uint32_t aL = sb + OFF_AL;
        const uint32_t bH = sb + OFF_BH;
        const uint32_t bL = sb + OFF_BL;

#pragma unroll
        for (int k16 = 0; k16 < 4; k16++) {
            const uint32_t kb = k16 * 32 + lhalf;
            uint32_t ah[4][4], al[4][4];
#pragma unroll
            for (int i = 0; i < 4; i++) {
                int row = wm * 64 + i * 16 + lrow;
                uint32_t o = sw128(row * 128 + kb);
                LDSM_X4(ah[i][0], ah[i][1], ah[i][2], ah[i][3], aH + o);
                LDSM_X4(al[i][0], al[i][1], al[i][2], al[i][3], aL + o);
            }
            uint32_t bh[2][4], bl[2][4];
#pragma unroll
            for (int j = 0; j < 2; j++) {
                int row = wn * 32 + j * 16 + lrow;
                uint32_t o = sw128(row * 128 + kb);
                LDSM_X4(bh[j][0], bh[j][1], bh[j][2], bh[j][3], bH + o);
                LDSM_X4(bl[j][0], bl[j][1], bl[j][2], bl[j][3], bL + o);
            }
            // round-7 interleaved product order (ptxas schedules this well)
#pragma unroll
            for (int i = 0; i < 4; i++) {
#pragma unroll
                for (int jn = 0; jn < 4; jn++) {
                    const int j = jn >> 1, s = jn & 1;
                    MMA_BF16(acc[i][jn], ah[i], bh[j][s], bh[j][s + 2]);
                    MMA_BF16(acc[i][jn], ah[i], bl[j][s], bl[j][s + 2]);
                    MMA_BF16(acc[i][jn], al[i], bh[j][s], bh[j][s + 2]);
                }
            }
        }
        __syncthreads();
        if (c + 2 < GK_CHUNKS) load_stage(c + 2, c & 1);
    }

    const int er = lane >> 2;
    const int ec = (lane & 3) * 2;

    if (!Chi) {
#pragma unroll
        for (int i = 0; i < 4; i++) {
            int r0 = m0 + wm * 64 + i * 16 + er;
#pragma unroll
            for (int jn = 0; jn < 4; jn++) {
                int col = n0 + wn * 32 + jn * 8 + ec;
                *(float2*)(C + (size_t)r0 * N + col)       = make_float2(acc[i][jn][0], acc[i][jn][1]);
                *(float2*)(C + (size_t)(r0 + 8) * N + col) = make_float2(acc[i][jn][2], acc[i][jn][3]);
            }
        }
    } else if (n0 >= 2 * D_MODEL) {
        // v section: direct register split-store (no rope)
#pragma unroll
        for (int i = 0; i < 4; i++) {
#pragma unroll
            for (int jn = 0; jn < 4; jn++) {
                int col = n0 + wn * 32 + jn * 8 + ec;
#pragma unroll
                for (int half = 0; half < 2; half++) {
                    int r = m0 + wm * 64 + i * 16 + er + half * 8;
                    float a0 = acc[i][jn][2 * half], a1 = acc[i][jn][2 * half + 1];
                    uint32_t hh = pack_bf16(a0, a1);
                    float f0 = __uint_as_float(hh << 16), f1 = __uint_as_float(hh & 0xFFFF0000u);
                    uint32_t ll = pack_bf16(a0 - f0, a1 - f1);
                    size_t o = (size_t)r * N + col;
                    *(uint32_t*)(Chi + o) = hh;
                    *(uint32_t*)(Clo + o) = ll;
                }
            }
        }
    } else {
        // q/k section: stage tile in smem (128 x 192, stride 194), RoPE, store
        float* Ct = (float*)dyn_smem;
#pragma unroll
        for (int i = 0; i < 4; i++) {
            int rl = wm * 64 + i * 16 + er;
#pragma unroll
            for (int jn = 0; jn < 4; jn++) {
                int cl = wn * 32 + jn * 8 + ec;
                Ct[rl * 194 + cl]           = acc[i][jn][0];
                Ct[rl * 194 + cl + 1]       = acc[i][jn][1];
                Ct[(rl + 8) * 194 + cl]     = acc[i][jn][2];
                Ct[(rl + 8) * 194 + cl + 1] = acc[i][jn][3];
            }
        }
        __syncthreads();
        const int po = *pos;
        // 128 rows x 96 rotation pairs (3 heads x 32) = 12288 / 384 = 32 iters
#pragma unroll
        for (int it = 0; it < 32; it++) {
            int idx = tid + it * 384;
            int row = idx / 96;
            int p   = idx - row * 96;
            int hh  = p >> 5;                  // head within tile (0..2)
            int d   = p & 31;
            int cl  = hh * 64 + d;
            float x1 = Ct[row * 194 + cl];
            float x2 = Ct[row * 194 + cl + 32];
            int l = (m0 + row) & (L_SEQ - 1);
            float s, c;
            sincos_rope((float)(l + po) * c_invf[d], &s, &c);
            float y1 = x1 * c - x2 * s;
            float y2 = x2 * c + x1 * s;
            __nv_bfloat16 h1 = __float2bfloat16_rn(y1);
            __nv_bfloat16 h2 = __float2bfloat16_rn(y2);
            size_t o = (size_t)(m0 + row) * N + n0 + cl;
            Chi[o]      = h1;
            Chi[o + 32] = h2;
            Clo[o]      = __float2bfloat16_rn(y1 - __bfloat162float(h1));
            Clo[o + 32] = __float2bfloat16_rn(y2 - __bfloat162float(h2));
        }
    }
}

// ===========================================================================
// Tensor-core causal flash attention — round-7 version (reverted).
// ===========================================================================
#define FQH 0
#define FQL 16384
#define FST 32768
#define FSTG 32768
#define FA_SMEM (FST + 2 * FSTG)   // 98304

__global__ __launch_bounds__(256, 1) void attn_mma(
    const __nv_bfloat16* __restrict__ qkvh,
    const __nv_bfloat16* __restrict__ qkvl,
    __nv_bfloat16* __restrict__ ohp,
    __nv_bfloat16* __restrict__ olp)
{
    const uint32_t sbu = smem_u32(dyn_smem);
    const int tid  = threadIdx.x;
    const int wid  = tid >> 5;
    const int lane = tid & 31;
    const int lrow = lane & 15;
    const int lhalf = (lane >> 4) * 16;

    const int qt = gridDim.x - 1 - blockIdx.x;
    const int bh = blockIdx.y;
    const int b  = bh / N_HEADS_C;
    const int h  = bh % N_HEADS_C;
    const size_t rowbase = (size_t)b * L_SEQ;

    {
        int op  = tid >> 7;
        int row = tid & 127;
        const __nv_bfloat16* src = (op ? qkvl : qkvh)
            + (rowbase + qt * 128 + row) * QKV_COLS + h * DH;
        uint32_t dstb = sbu + (op ? FQL : FQH);
#pragma unroll
        for (int c = 0; c < 8; c++)
            CP_ASYNC16(dstb + sw128(row * 128 + c * 16), src + c * 8);
        CP_COMMIT();
    }

    const int ktmax = 2 * qt + 1;

    auto load_kv = [&](int kt, int s) {
        int op  = tid >> 6;
        int row = tid & 63;
        const __nv_bfloat16* base = (op & 1) ? qkvl : qkvh;
        int colofs = (op >> 1) ? (2 * D_MODEL + h * DH) : (D_MODEL + h * DH);
        const __nv_bfloat16* src = base + (rowbase + kt * 64 + row) * QKV_COLS + colofs;
        uint32_t dstb = sbu + FST + s * FSTG + op * 8192;
#pragma unroll
        for (int c = 0; c < 8; c++)
            CP_ASYNC16(dstb + sw128(row * 128 + c * 16), src + c * 8);
        CP_COMMIT();
    };

    load_kv(0, 0);
    load_kv(1, 1);

    CP_WAIT(2);
    __syncthreads();
    uint32_t qh[4][4], ql[4][4];
#pragma unroll
    for (int c = 0; c < 4; c++) {
        uint32_t o = sw128((wid * 16 + lrow) * 128 + c * 32 + lhalf);
        LDSM_X4(qh[c][0], qh[c][1], qh[c][2], qh[c][3], sbu + FQH + o);
        LDSM_X4(ql[c][0], ql[c][1], ql[c][2], ql[c][3], sbu + FQL + o);
    }

    float oa[8][4];
#pragma unroll
    for (int nt = 0; nt < 8; nt++)
#pragma unroll
        for (int r = 0; r < 4; r++) oa[nt][r] = 0.f;
    float m0 = -INFINITY, m1 = -INFINITY, l0 = 0.f, l1 = 0.f;

    const int row0 = qt * 128 + wid * 16 + (lane >> 2);
    const int row1 = row0 + 8;
    const int colq = 2 * (lane & 3);

    for (int kt = 0; kt <= ktmax; kt++) {
        if (kt + 2 <= ktmax) { CP_WAIT(1); } else { CP_WAIT(0); }
        __syncthreads();

        const uint32_t su = sbu + FST + (kt & 1) * FSTG;
        const uint32_t KH = su, KL = su + 8192, VH = su + 16384, VL = su + 24576;

        float sc[8][4];
#pragma unroll
        for (int nt = 0; nt < 8; nt++)
#pragma unroll
            for (int r = 0; r < 4; r++) sc[nt][r] = 0.f;

#pragma unroll
        for (int c = 0; c < 4; c++) {
            const uint32_t kb = c * 32 + lhalf;
#pragma unroll
            for (int g = 0; g < 4; g++) {
                uint32_t o = sw128((g * 16 + lrow) * 128 + kb);
                uint32_t kh4[4], kl4[4];
                LDSM_X4(kh4[0], kh4[1], kh4[2], kh4[3], KH + o);
                LDSM_X4(kl4[0], kl4[1], kl4[2], kl4[3], KL + o);
                MMA_BF16(sc[2 * g],     qh[c], kh4[0], kh4[2]);
                MMA_BF16(sc[2 * g + 1], qh[c], kh4[1], kh4[3]);
                MMA_BF16(sc[2 * g],     qh[c], kl4[0], kl4[2]);
                MMA_BF16(sc[2 * g + 1], qh[c], kl4[1], kl4[3]);
                MMA_BF16(sc[2 * g],     ql[c], kh4[0], kh4[2]);
                MMA_BF16(sc[2 * g + 1], ql[c], kh4[1], kh4[3]);
            }
        }

        const bool diag = (kt >= 2 * qt);
#pragma unroll
        for (int nt = 0; nt < 8; nt++) {
            int colg = kt * 64 + nt * 8 + colq;
#pragma unroll
            for (int r = 0; r < 4; r++) {
                float s = sc[nt][r] * 0.125f;
                if (diag) {
                    int cg = colg + (r & 1);
                    int rg = (r < 2) ? row0 : row1;
                    if (cg > rg) s = -1e30f;
                }
                sc[nt][r] = s;
            }
        }

        float rm0 = -INFINITY, rm1 = -INFINITY;
#pragma unroll
        for (int nt = 0; nt < 8; nt++) {
            rm0 = fmaxf(rm0, fmaxf(sc[nt][0], sc[nt][1]));
            rm1 = fmaxf(rm1, fmaxf(sc[nt][2], sc[nt][3]));
        }
        rm0 = fmaxf(rm0, __shfl_xor_sync(0xffffffffu, rm0, 1));
        rm0 = fmaxf(rm0, __shfl_xor_sync(0xffffffffu, rm0, 2));
        rm1 = fmaxf(rm1, __shfl_xor_sync(0xffffffffu, rm1, 1));
        rm1 = fmaxf(rm1, __shfl_xor_sync(0xffffffffu, rm1, 2));

        float m0n = fmaxf(m0, rm0), m1n = fmaxf(m1, rm1);
        float cr0 = __expf(m0 - m0n), cr1 = __expf(m1 - m1n);
        l0 *= cr0; l1 *= cr1;
#pragma unroll
        for (int nt = 0; nt < 8; nt++) {
            oa[nt][0] *= cr0; oa[nt][1] *= cr0;
            oa[nt][2] *= cr1; oa[nt][3] *= cr1;
        }
        m0 = m0n; m1 = m1n;

        uint32_t pha[8], phb[8], pla[8], plb[8];
#pragma unroll
        for (int nt = 0; nt < 8; nt++) {
            float p0 = __expf(sc[nt][0] - m0n);
            float p1 = __expf(sc[nt][1] - m0n);
            float p2 = __expf(sc[nt][2] - m1n);
            float p3 = __expf(sc[nt][3] - m1n);
            l0 += p0 + p1; l1 += p2 + p3;
            uint32_t h01 = pack_bf16(p0, p1);
            uint32_t h23 = pack_bf16(p2, p3);
            pha[nt] = h01; phb[nt] = h23;
            float f0 = __uint_as_float(h01 << 16), f1 = __uint_as_float(h01 & 0xFFFF0000u);
            float f2 = __uint_as_float(h23 << 16), f3 = __uint_as_float(h23 & 0xFFFF0000u);
            pla[nt] = pack_bf16(p0 - f0, p1 - f1);
            plb[nt] = pack_bf16(p2 - f2, p3 - f3);
        }

#pragma unroll
        for (int kc = 0; kc < 4; kc++) {
            uint32_t pah[4] = { pha[2 * kc], phb[2 * kc], pha[2 * kc + 1], phb[2 * kc + 1] };
            uint32_t pal[4] = { pla[2 * kc], plb[2 * kc], pla[2 * kc + 1], plb[2 * kc + 1] };
#pragma unroll
            for (int dp = 0; dp < 4; dp++) {
                uint32_t o = sw128((kc * 16 + lrow) * 128 + dp * 32 + lhalf);
                uint32_t vh4[4], vl4[4];
                LDSM_X4_T(vh4[0], vh4[1], vh4[2], vh4[3], VH + o);
                LDSM_X4_T(vl4[0], vl4[1], vl4[2], vl4[3], VL + o);
                MMA_BF16(oa[2 * dp],     pah, vh4[0], vh4[1]);
                MMA_BF16(oa[2 * dp + 1], pah, vh4[2], vh4[3]);
                MMA_BF16(oa[2 * dp],     pah, vl4[0], vl4[1]);
                MMA_BF16(oa[2 * dp + 1], pah, vl4[2], vl4[3]);
                MMA_BF16(oa[2 * dp],     pal, vh4[0], vh4[1]);
                MMA_BF16(oa[2 * dp + 1], pal, vh4[2], vh4[3]);
            }
        }

        __syncthreads();
        if (kt + 2 <= ktmax) load_kv(kt + 2, kt & 1);
    }

    l0 += __shfl_xor_sync(0xffffffffu, l0, 1);
    l0 += __shfl_xor_sync(0xffffffffu, l0, 2);
    l1 += __shfl_xor_sync(0xffffffffu, l1, 1);
    l1 += __shfl_xor_sync(0xffffffffu, l1, 2);
    float i0 = 1.f / l0, i1 = 1.f / l1;

    size_t ob0 = (rowbase + row0) * D_MODEL + h * DH;
    size_t ob1 = (rowbase + row1) * D_MODEL + h * DH;
#pragma unroll
    for (int nt = 0; nt < 8; nt++) {
        int col = nt * 8 + colq;
        float a0 = oa[nt][0] * i0, a1 = oa[nt][1] * i0;
        float a2 = oa[nt][2] * i1, a3 = oa[nt][3] * i1;
        uint32_t h01 = pack_bf16(a0, a1);
        uint32_t h23 = pack_bf16(a2, a3);
        float f0 = __uint_as_float(h01 << 16), f1 = __uint_as_float(h01 & 0xFFFF0000u);
        float f2 = __uint_as_float(h23 << 16), f3 = __uint_as_float(h23 & 0xFFFF0000u);
        *(uint32_t*)(ohp + ob0 + col) = h01;
        *(uint32_t*)(olp + ob0 + col) = pack_bf16(a0 - f0, a1 - f1);
        *(uint32_t*)(ohp + ob1 + col) = h23;
        *(uint32_t*)(olp + ob1 + col) = pack_bf16(a2 - f2, a3 - f3);
    }
}

// ===========================================================================
// launch
// ===========================================================================
extern "C" void kernel_launch(void* const* d_in, const int* in_sizes, int n_in,
                              void* d_out, int out_size)
{
    const float* x     = (const float*)d_in[0];
    const float* w_qkv = (const float*)d_in[1];
    const float* w_out = (const float*)d_in[2];
    const int*   pos   = (const int*)d_in[3];
    float*       out   = (float*)d_out;

    __nv_bfloat16 *qkvh, *qkvl, *xh, *xl, *wqh, *wql, *ah, *al, *woh, *wol;
    cudaGetSymbolAddress((void**)&qkvh, g_qkvh); cudaGetSymbolAddress((void**)&qkvl, g_qkvl);
    cudaGetSymbolAddress((void**)&xh, g_xh);   cudaGetSymbolAddress((void**)&xl, g_xl);
    cudaGetSymbolAddress((void**)&wqh, g_wqh); cudaGetSymbolAddress((void**)&wql, g_wql);
    cudaGetSymbolAddress((void**)&ah, g_ah);   cudaGetSymbolAddress((void**)&al, g_al);
    cudaGetSymbolAddress((void**)&woh, g_woh); cudaGetSymbolAddress((void**)&wol, g_wol);

    cudaFuncSetAttribute(gemm_bf16x3, cudaFuncAttributeMaxDynamicSharedMemorySize, GEMM_SMEM);
    cudaFuncSetAttribute(attn_mma, cudaFuncAttributeMaxDynamicSharedMemorySize, FA_SMEM);

    // 1) split inputs to bf16 hi/lo
    split_bf16<<<(M_ROWS * K_DIM / 4 + 255) / 256, 256>>>(x, xh, xl, M_ROWS * K_DIM / 4);
    split_bf16<<<(QKV_COLS * K_DIM / 4 + 255) / 256, 256>>>(w_qkv, wqh, wql, QKV_COLS * K_DIM / 4);

    // 2) QKV projection with fused RoPE + hi/lo split epilogue (128x192 CTAs)
    gemm_bf16x3<<<dim3(QKV_COLS / BN_G, M_ROWS / 128), 384, GEMM_SMEM>>>(
        xh, xl, wqh, wql, nullptr, qkvh, qkvl, pos, QKV_COLS);

    // 3) tensor-core causal flash attention -> bf16 hi/lo
    attn_mma<<<dim3(L_SEQ / 128, B_SZ * N_HEADS_C), 256, FA_SMEM>>>(qkvh, qkvl, ah, al);

    // 4) output projection (plain fp32 epilogue to d_out)
    split_bf16<<<(D_MODEL * K_DIM / 4 + 255) / 256, 256>>>(w_out, woh, wol, D_MODEL * K_DIM / 4);
    gemm_bf16x3<<<dim3(D_MODEL / BN_G, M_ROWS / 128), 384, GEMM_SMEM>>>(
        ah, al, woh, wol, out, nullptr, nullptr, nullptr, D_MODEL);
}

// round 11
// speedup vs baseline: 1.5413x; 1.0408x over previous
#include <cuda_runtime.h>
#include <cuda_bf16.h>
#include <math.h>
#include <stdint.h>

// ---------------- problem constants ----------------
#define D_MODEL   1536
#define N_HEADS_C 24
#define DH        64
#define B_SZ      4
#define L_SEQ     2048
#define M_ROWS    (B_SZ * L_SEQ)     // 8192
#define QKV_COLS  (3 * D_MODEL)      // 4608
#define K_DIM     1536

// single dynamic smem symbol shared by all kernels
extern __shared__ char dyn_smem[];

// ---------------- scratch (device globals; no allocation allowed) ---------
__device__ __nv_bfloat16 g_qkvh[(size_t)M_ROWS * QKV_COLS];
__device__ __nv_bfloat16 g_qkvl[(size_t)M_ROWS * QKV_COLS];
__device__ __nv_bfloat16 g_xh[(size_t)M_ROWS * K_DIM];
__device__ __nv_bfloat16 g_xl[(size_t)M_ROWS * K_DIM];
__device__ __nv_bfloat16 g_wqh[(size_t)QKV_COLS * K_DIM];
__device__ __nv_bfloat16 g_wql[(size_t)QKV_COLS * K_DIM];
__device__ __nv_bfloat16 g_ah[(size_t)M_ROWS * K_DIM];
__device__ __nv_bfloat16 g_al[(size_t)M_ROWS * K_DIM];
__device__ __nv_bfloat16 g_woh[(size_t)D_MODEL * K_DIM];
__device__ __nv_bfloat16 g_wol[(size_t)D_MODEL * K_DIM];

// inv_freq[d] = 10000^(-d/32) = 10^(-d/8)
__constant__ float c_invf[32] = {
    1.0f, 0.7498942093324559f, 0.5623413251903491f, 0.42169650342858224f,
    0.31622776601683794f, 0.23713737056616552f, 0.1778279410038923f, 0.1333521432163324f,
    0.1f, 0.07498942093324558f, 0.05623413251903491f, 0.042169650342858224f,
    0.031622776601683794f, 0.023713737056616552f, 0.01778279410038923f, 0.01333521432163324f,
    0.01f, 0.007498942093324558f, 0.005623413251903491f, 0.0042169650342858224f,
    0.0031622776601683794f, 0.0023713737056616552f, 0.001778279410038923f, 0.0013335214321633241f,
    0.001f, 0.0007498942093324558f, 0.0005623413251903491f, 0.00042169650342858224f,
    0.00031622776601683794f, 0.00023713737056616552f, 0.0001778279410038923f, 0.00013335214321633242f
};

// ---------------- helpers --------------------------------------------------
__device__ __forceinline__ uint32_t smem_u32(const void* p) {
    uint32_t a;
    asm("{ .reg .u64 t; cvta.to.shared.u64 t, %1; cvt.u32.u64 %0, t; }" : "=r"(a) : "l"(p));
    return a;
}

#define CP_ASYNC16(dst, src) \
    asm volatile("cp.async.cg.shared.global [%0], [%1], 16;" :: "r"(dst), "l"(src))
#define CP_COMMIT() asm volatile("cp.async.commit_group;" ::: "memory")
#define CP_WAIT(N)  asm volatile("cp.async.wait_group %0;" :: "n"(N) : "memory")

#define LDSM_X4(r0, r1, r2, r3, addr) \
    asm volatile("ldmatrix.sync.aligned.m8n8.x4.shared.b16 {%0,%1,%2,%3}, [%4];" \
        : "=r"(r0), "=r"(r1), "=r"(r2), "=r"(r3) : "r"(addr))

#define LDSM_X4_T(r0, r1, r2, r3, addr) \
    asm volatile("ldmatrix.sync.aligned.m8n8.x4.trans.shared.b16 {%0,%1,%2,%3}, [%4];" \
        : "=r"(r0), "=r"(r1), "=r"(r2), "=r"(r3) : "r"(addr))

#define MMA_BF16(c, a, b0_, b1_) \
    asm volatile("mma.sync.aligned.m16n8k16.row.col.f32.bf16.bf16.f32 " \
        "{%0,%1,%2,%3}, {%4,%5,%6,%7}, {%8,%9}, {%0,%1,%2,%3};" \
        : "+f"((c)[0]), "+f"((c)[1]), "+f"((c)[2]), "+f"((c)[3]) \
        : "r"((a)[0]), "r"((a)[1]), "r"((a)[2]), "r"((a)[3]), "r"(b0_), "r"(b1_))

__device__ __forceinline__ uint32_t sw128(uint32_t off) {
    return off ^ ((off >> 3) & 0x70);
}

__device__ __forceinline__ uint32_t pack_bf16(float lo, float hi) {
    uint32_t d;
    asm("cvt.rn.bf16x2.f32 %0, %1, %2;" : "=r"(d) : "f"(hi), "f"(lo));
    return d;
}

__device__ __forceinline__ void sincos_rope(float fr, float* s, float* c) {
    float n  = rintf(fr * 0.15915494309189535f);
    float r1 = fmaf(n, -6.2831855f, fr);
    float r  = fmaf(n,  1.7484556e-7f, r1);
    __sincosf(r, s, c);
}

// ===========================================================================
// split fp32 -> bf16 hi + bf16 lo
// ===========================================================================
__global__ __launch_bounds__(256) void split_bf16(
    const float* __restrict__ s, __nv_bfloat16* __restrict__ hi,
    __nv_bfloat16* __restrict__ lo, int n4)
{
    int i = blockIdx.x * blockDim.x + threadIdx.x;
    if (i >= n4) return;
    float4 v = ((const float4*)s)[i];
    uint32_t h01 = pack_bf16(v.x, v.y);
    uint32_t h23 = pack_bf16(v.z, v.w);
    float f0 = __uint_as_float(h01 << 16), f1 = __uint_as_float(h01 & 0xFFFF0000u);
    float f2 = __uint_as_float(h23 << 16), f3 = __uint_as_float(h23 & 0xFFFF0000u);
    uint32_t l01 = pack_bf16(v.x - f0, v.y - f1);
    uint32_t l23 = pack_bf16(v.z - f2, v.w - f3);
    ((uint2*)hi)[i] = make_uint2(h01, h23);
    ((uint2*)lo)[i] = make_uint2(l01, l23);
}

// ===========================================================================
// Split-bf16 3-product GEMM via mma.sync (round-7 config: 128x128, 256 thr).
// ONLY change vs r7: product-outermost MMA ordering (same-acc distance 16).
// ===========================================================================
#define GK_CHUNKS 24
#define TILE_B    16384
#define STAGE_B   (4 * TILE_B)
#define GEMM_SMEM (2 * STAGE_B)

__global__ __launch_bounds__(256, 1) void gemm_bf16x3(
    const __nv_bfloat16* __restrict__ Ah, const __nv_bfloat16* __restrict__ Al,
    const __nv_bfloat16* __restrict__ Bh, const __nv_bfloat16* __restrict__ Bl,
    float* __restrict__ C,
    __nv_bfloat16* __restrict__ Chi, __nv_bfloat16* __restrict__ Clo,
    const int* __restrict__ pos, int N)
{
    const uint32_t sbu = smem_u32(dyn_smem);

    const int tid  = threadIdx.x;
    const int wid  = tid >> 5;
    const int lane = tid & 31;
    const int wm   = wid & 1;
    const int wn   = wid >> 1;
    const int m0   = blockIdx.y * 128;
    const int n0   = blockIdx.x * 128;

    const __nv_bfloat16* srcs[4] = {
        Ah + (size_t)m0 * K_DIM, Al + (size_t)m0 * K_DIM,
        Bh + (size_t)n0 * K_DIM, Bl + (size_t)n0 * K_DIM };

    int unit_row[4], unit_u[4];
#pragma unroll
    for (int i = 0; i < 4; i++) {
        int unit = tid + i * 256;
        unit_row[i] = unit >> 3;
        unit_u[i]   = unit & 7;
    }

    auto load_stage = [&](int c, int s) {
        uint32_t sb = sbu + s * STAGE_B;
#pragma unroll
        for (int op = 0; op < 4; op++) {
            const __nv_bfloat16* src = srcs[op] + c * 64;
            uint32_t ob = sb + op * TILE_B;
#pragma unroll
            for (int i = 0; i < 4; i++) {
                const __nv_bfloat16* g = src + (size_t)unit_row[i] * K_DIM + unit_u[i] * 8;
                uint32_t d = ob + sw128(unit_row[i] * 128 + unit_u[i] * 16);
                CP_ASYNC16(d, g);
            }
        }
        CP_COMMIT();
    };

    float acc[4][4][4];
#pragma unroll
    for (int i = 0; i < 4; i++)
#pragma unroll
        for (int j = 0; j < 4; j++)
#pragma unroll
            for (int k = 0; k < 4; k++) acc[i][j][k] = 0.f;

    load_stage(0, 0);
    load_stage(1, 1);

    const int lrow = lane & 15;
    const int lhalf = (lane >> 4) * 16;

    for (int c = 0; c < GK_CHUNKS; c++) {
        if (c + 2 < GK_CHUNKS) { CP_WAIT(1); } else { CP_WAIT(0); }
        __syncthreads();

        const uint32_t sb = sbu + (c & 1) * STAGE_B;
        const uint32_t aH = sb + 0 * TILE_B;
        const uint32_t aL = sb + 1 * TILE_B;
        const uint32_t bH = sb + 2 * TILE_B;
        const uint32_t bL = sb + 3 * TILE_B;

#pragma unroll
        for (int k16 = 0; k16 < 4; k16++) {
            const uint32_t kb = k16 * 32 + lhalf;
            uint32_t ah[4][4], al[4][4];
#pragma unroll
            for (int i = 0; i < 4; i++) {
                int row = wm * 64 + i * 16 + lrow;
                uint32_t o = sw128(row * 128 + kb);
                LDSM_X4(ah[i][0], ah[i][1], ah[i][2], ah[i][3], aH + o);
                LDSM_X4(al[i][0], al[i][1], al[i][2], al[i][3], aL + o);
            }
            uint32_t bh[2][4], bl[2][4];
#pragma unroll
            for (int j = 0; j < 2; j++) {
                int row = wn * 32 + j * 16 + lrow;
                uint32_t o = sw128(row * 128 + kb);
                LDSM_X4(bh[j][0], bh[j][1], bh[j][2], bh[j][3], bH + o);
                LDSM_X4(bl[j][0], bl[j][1], bl[j][2], bl[j][3], bL + o);
            }
            // product-outermost: same-acc MMAs 16 apart; per-acc sum order
            // identical to r7 (AhBh, AhBl, AlBh) -> bit-identical result
#pragma unroll
            for (int i = 0; i < 4; i++)
#pragma unroll
                for (int jn = 0; jn < 4; jn++)
                    MMA_BF16(acc[i][jn], ah[i], bh[jn >> 1][jn & 1], bh[jn >> 1][(jn & 1) + 2]);
#pragma unroll
            for (int i = 0; i < 4; i++)
#pragma unroll
                for (int jn = 0; jn < 4; jn++)
                    MMA_BF16(acc[i][jn], ah[i], bl[jn >> 1][jn & 1], bl[jn >> 1][(jn & 1) + 2]);
#pragma unroll
            for (int i = 0; i < 4; i++)
#pragma unroll
                for (int jn = 0; jn < 4; jn++)
                    MMA_BF16(acc[i][jn], al[i], bh[jn >> 1][jn & 1], bh[jn >> 1][(jn & 1) + 2]);
        }
        __syncthreads();
        if (c + 2 < GK_CHUNKS) load_stage(c + 2, c & 1);
    }

    const int er = lane >> 2;
    const int ec = (lane & 3) * 2;

    if (!Chi) {
#pragma unroll
        for (int i = 0; i < 4; i++) {
            int r0 = m0 + wm * 64 + i * 16 + er;
#pragma unroll
            for (int jn = 0; jn < 4; jn++) {
                int col = n0 + wn * 32 + jn * 8 + ec;
                *(float2*)(C + (size_t)r0 * N + col)       = make_float2(acc[i][jn][0], acc[i][jn][1]);
                *(float2*)(C + (size_t)(r0 + 8) * N + col) = make_float2(acc[i][jn][2], acc[i][jn][3]);
            }
        }
    } else if (n0 >= 2 * D_MODEL) {
        // v section: direct register split-store (no rope)
#pragma unroll
        for (int i = 0; i < 4; i++) {
#pragma unroll
            for (int jn = 0; jn < 4; jn++) {
                int col = n0 + wn * 32 + jn * 8 + ec;
#pragma unroll
                for (int half = 0; half < 2; half++) {
                    int r = m0 + wm * 64 + i * 16 + er + half * 8;
                    float a0 = acc[i][jn][2 * half], a1 = acc[i][jn][2 * half + 1];
                    uint32_t hh = pack_bf16(a0, a1);
                    float f0 = __uint_as_float(hh << 16), f1 = __uint_as_float(hh & 0xFFFF0000u);
                    uint32_t ll = pack_bf16(a0 - f0, a1 - f1);
                    size_t o = (size_t)r * N + col;
                    *(uint32_t*)(Chi + o) = hh;
                    *(uint32_t*)(Clo + o) = ll;
                }
            }
        }
    } else {
        // q/k section: stage tile in smem, apply RoPE, split-store
        float* Ct = (float*)dyn_smem;                    // [128][130]
#pragma unroll
        for (int i = 0; i < 4; i++) {
            int rl = wm * 64 + i * 16 + er;
#pragma unroll
            for (int jn = 0; jn < 4; jn++) {
                int cl = wn * 32 + jn * 8 + ec;
                Ct[rl * 130 + cl]           = acc[i][jn][0];
                Ct[rl * 130 + cl + 1]       = acc[i][jn][1];
                Ct[(rl + 8) * 130 + cl]     = acc[i][jn][2];
                Ct[(rl + 8) * 130 + cl + 1] = acc[i][jn][3];
            }
        }
        __syncthreads();
        const int po = *pos;
#pragma unroll
        for (int it = 0; it < 32; it++) {
            int idx = tid + it * 256;
            int hd  = idx & 63;
            int row = idx >> 6;
            int d   = hd & 31;
            int cl  = (hd >> 5) * 64 + d;
            float x1 = Ct[row * 130 + cl];
            float x2 = Ct[row * 130 + cl + 32];
            int l = (m0 + row) & (L_SEQ - 1);
            float s, c;
            sincos_rope((float)(l + po) * c_invf[d], &s, &c);
            float y1 = x1 * c - x2 * s;
            float y2 = x2 * c + x1 * s;
            __nv_bfloat16 h1 = __float2bfloat16_rn(y1);
            __nv_bfloat16 h2 = __float2bfloat16_rn(y2);
            size_t o = (size_t)(m0 + row) * N + n0 + cl;
            Chi[o]      = h1;
            Chi[o + 32] = h2;
            Clo[o]      = __float2bfloat16_rn(y1 - __bfloat162float(h1));
            Clo[o + 32] = __float2bfloat16_rn(y2 - __bfloat162float(h2));
        }
    }
}

// ===========================================================================
// Tensor-core causal flash attention — round-7 version EXACT (unchanged).
// ===========================================================================
#define FQH 0
#define FQL 16384
#define FST 32768
#define FSTG 32768
#define FA_SMEM (FST + 2 * FSTG)   // 98304

__global__ __launch_bounds__(256, 1) void attn_mma(
    const __nv_bfloat16* __restrict__ qkvh,
    const __nv_bfloat16* __restrict__ qkvl,
    __nv_bfloat16* __restrict__ ohp,
    __nv_bfloat16* __restrict__ olp)
{
    const uint32_t sbu = smem_u32(dyn_smem);
    const int tid  = threadIdx.x;
    const int wid  = tid >> 5;
    const int lane = tid & 31;
    const int lrow = lane & 15;
    const int lhalf = (lane >> 4) * 16;

    const int qt = gridDim.x - 1 - blockIdx.x;
    const int bh = blockIdx.y;
    const int b  = bh / N_HEADS_C;
    const int h  = bh % N_HEADS_C;
    const size_t rowbase = (size_t)b * L_SEQ;

    {
        int op  = tid >> 7;
        int row = tid & 127;
        const __nv_bfloat16* src = (op ? qkvl : qkvh)
            + (rowbase + qt * 128 + row) * QKV_COLS + h * DH;
        uint32_t dstb = sbu + (op ? FQL : FQH);
#pragma unroll
        for (int c = 0; c < 8; c++)
            CP_ASYNC16(dstb + sw128(row * 128 + c * 16), src + c * 8);
        CP_COMMIT();
    }

    const int ktmax = 2 * qt + 1;

    auto load_kv = [&](int kt, int s) {
        int op  = tid >> 6;
        int row = tid & 63;
        const __nv_bfloat16* base = (op & 1) ? qkvl : qkvh;
        int colofs = (op >> 1) ? (2 * D_MODEL + h * DH) : (D_MODEL + h * DH);
        const __nv_bfloat16* src = base + (rowbase + kt * 64 + row) * QKV_COLS + colofs;
        uint32_t dstb = sbu + FST + s * FSTG + op * 8192;
#pragma unroll
        for (int c = 0; c < 8; c++)
            CP_ASYNC16(dstb + sw128(row * 128 + c * 16), src + c * 8);
        CP_COMMIT();
    };

    load_kv(0, 0);
    load_kv(1, 1);

    CP_WAIT(2);
    __syncthreads();
    uint32_t qh[4][4], ql[4][4];
#pragma unroll
    for (int c = 0; c < 4; c++) {
        uint32_t o = sw128((wid * 16 + lrow) * 128 + c * 32 + lhalf);
        LDSM_X4(qh[c][0], qh[c][1], qh[c][2], qh[c][3], sbu + FQH + o);
        LDSM_X4(ql[c][0], ql[c][1], ql[c][2], ql[c][3], sbu + FQL + o);
    }

    float oa[8][4];
#pragma unroll
    for (int nt = 0; nt < 8; nt++)
#pragma unroll
        for (int r = 0; r < 4; r++) oa[nt][r] = 0.f;
    float m0 = -INFINITY, m1 = -INFINITY, l0 = 0.f, l1 = 0.f;

    const int row0 = qt * 128 + wid * 16 + (lane >> 2);
    const int row1 = row0 + 8;
    const int colq = 2 * (lane & 3);

    for (int kt = 0; kt <= ktmax; kt++) {
        if (kt + 2 <= ktmax) { CP_WAIT(1); } else { CP_WAIT(0); }
        __syncthreads();

        const uint32_t su = sbu + FST + (kt & 1) * FSTG;
        const uint32_t KH = su, KL = su + 8192, VH = su + 16384, VL = su + 24576;

        float sc[8][4];
#pragma unroll
        for (int nt = 0; nt < 8; nt++)
#pragma unroll
            for (int r = 0; r < 4; r++) sc[nt][r] = 0.f;

#pragma unroll
        for (int c = 0; c < 4; c++) {
            const uint32_t kb = c * 32 + lhalf;
#pragma unroll
            for (int g = 0; g < 4; g++) {
                uint32_t o = sw128((g * 16 + lrow) * 128 + kb);
                uint32_t kh4[4], kl4[4];
                LDSM_X4(kh4[0], kh4[1], kh4[2], kh4[3], KH + o);
                LDSM_X4(kl4[0], kl4[1], kl4[2], kl4[3], KL + o);
                MMA_BF16(sc[2 * g],     qh[c], kh4[0], kh4[2]);
                MMA_BF16(sc[2 * g + 1], qh[c], kh4[1], kh4[3]);
                MMA_BF16(sc[2 * g],     qh[c], kl4[0], kl4[2]);
                MMA_BF16(sc[2 * g + 1], qh[c], kl4[1], kl4[3]);
                MMA_BF16(sc[2 * g],     ql[c], kh4[0], kh4[2]);
                MMA_BF16(sc[2 * g + 1], ql[c], kh4[1], kh4[3]);
            }
        }

        const bool diag = (kt >= 2 * qt);
#pragma unroll
        for (int nt = 0; nt < 8; nt++) {
            int colg = kt * 64 + nt * 8 + colq;
#pragma unroll
            for (int r = 0; r < 4; r++) {
                float s = sc[nt][r] * 0.125f;
                if (diag) {
                    int cg = colg + (r & 1);
                    int rg = (r < 2) ? row0 : row1;
                    if (cg > rg) s = -1e30f;
                }
                sc[nt][r] = s;
            }
        }

        float rm0 = -INFINITY, rm1 = -INFINITY;
#pragma unroll
        for (int nt = 0; nt < 8; nt++) {
            rm0 = fmaxf(rm0, fmaxf(sc[nt][0], sc[nt][1]));
            rm1 = fmaxf(rm1, fmaxf(sc[nt][2], sc[nt][3]));
        }
        rm0 = fmaxf(rm0, __shfl_xor_sync(0xffffffffu, rm0, 1));
        rm0 = fmaxf(rm0, __shfl_xor_sync(0xffffffffu, rm0, 2));
        rm1 = fmaxf(rm1, __shfl_xor_sync(0xffffffffu, rm1, 1));
        rm1 = fmaxf(rm1, __shfl_xor_sync(0xffffffffu, rm1, 2));

        float m0n = fmaxf(m0, rm0), m1n = fmaxf(m1, rm1);
        float cr0 = __expf(m0 - m0n), cr1 = __expf(m1 - m1n);
        l0 *= cr0; l1 *= cr1;
#pragma unroll
        for (int nt = 0; nt < 8; nt++) {
            oa[nt][0] *= cr0; oa[nt][1] *= cr0;
            oa[nt][2] *= cr1; oa[nt][3] *= cr1;
        }
        m0 = m0n; m1 = m1n;

        uint32_t pha[8], phb[8], pla[8], plb[8];
#pragma unroll
        for (int nt = 0; nt < 8; nt++) {
            float p0 = __expf(sc[nt][0] - m0n);
            float p1 = __expf(sc[nt][1] - m0n);
            float p2 = __expf(sc[nt][2] - m1n);
            float p3 = __expf(sc[nt][3] - m1n);
            l0 += p0 + p1; l1 += p2 + p3;
            uint32_t h01 = pack_bf16(p0, p1);
            uint32_t h23 = pack_bf16(p2, p3);
            pha[nt] = h01; phb[nt] = h23;
            float f0 = __uint_as_float(h01 << 16), f1 = __uint_as_float(h01 & 0xFFFF0000u);
            float f2 = __uint_as_float(h23 << 16), f3 = __uint_as_float(h23 & 0xFFFF0000u);
            pla[nt] = pack_bf16(p0 - f0, p1 - f1);
            plb[nt] = pack_bf16(p2 - f2, p3 - f3);
        }

#pragma unroll
        for (int kc = 0; kc < 4; kc++) {
            uint32_t pah[4] = { pha[2 * kc], phb[2 * kc], pha[2 * kc + 1], phb[2 * kc + 1] };
            uint32_t pal[4] = { pla[2 * kc], plb[2 * kc], pla[2 * kc + 1], plb[2 * kc + 1] };
#pragma unroll
            for (int dp = 0; dp < 4; dp++) {
                uint32_t o = sw128((kc * 16 + lrow) * 128 + dp * 32 + lhalf);
                uint32_t vh4[4], vl4[4];
                LDSM_X4_T(vh4[0], vh4[1], vh4[2], vh4[3], VH + o);
                LDSM_X4_T(vl4[0], vl4[1], vl4[2], vl4[3], VL + o);
                MMA_BF16(oa[2 * dp],     pah, vh4[0], vh4[1]);
                MMA_BF16(oa[2 * dp + 1], pah, vh4[2], vh4[3]);
                MMA_BF16(oa[2 * dp],     pah, vl4[0], vl4[1]);
                MMA_BF16(oa[2 * dp + 1], pah, vl4[2], vl4[3]);
                MMA_BF16(oa[2 * dp],     pal, vh4[0], vh4[1]);
                MMA_BF16(oa[2 * dp + 1], pal, vh4[2], vh4[3]);
            }
        }

        __syncthreads();
        if (kt + 2 <= ktmax) load_kv(kt + 2, kt & 1);
    }

    l0 += __shfl_xor_sync(0xffffffffu, l0, 1);
    l0 += __shfl_xor_sync(0xffffffffu, l0, 2);
    l1 += __shfl_xor_sync(0xffffffffu, l1, 1);
    l1 += __shfl_xor_sync(0xffffffffu, l1, 2);
    float i0 = 1.f / l0, i1 = 1.f / l1;

    size_t ob0 = (rowbase + row0) * D_MODEL + h * DH;
    size_t ob1 = (rowbase + row1) * D_MODEL + h * DH;
#pragma unroll
    for (int nt = 0; nt < 8; nt++) {
        int col = nt * 8 + colq;
        float a0 = oa[nt][0] * i0, a1 = oa[nt][1] * i0;
        float a2 = oa[nt][2] * i1, a3 = oa[nt][3] * i1;
        uint32_t h01 = pack_bf16(a0, a1);
        uint32_t h23 = pack_bf16(a2, a3);
        float f0 = __uint_as_float(h01 << 16), f1 = __uint_as_float(h01 & 0xFFFF0000u);
        float f2 = __uint_as_float(h23 << 16), f3 = __uint_as_float(h23 & 0xFFFF0000u);
        *(uint32_t*)(ohp + ob0 + col) = h01;
        *(uint32_t*)(olp + ob0 + col) = pack_bf16(a0 - f0, a1 - f1);
        *(uint32_t*)(ohp + ob1 + col) = h23;
        *(uint32_t*)(olp + ob1 + col) = pack_bf16(a2 - f2, a3 - f3);
    }
}

// ===========================================================================
// launch
// ===========================================================================
extern "C" void kernel_launch(void* const* d_in, const int* in_sizes, int n_in,
                              void* d_out, int out_size)
{
    const float* x     = (const float*)d_in[0];
    const float* w_qkv = (const float*)d_in[1];
    const float* w_out = (const float*)d_in[2];
    const int*   pos   = (const int*)d_in[3];
    float*       out   = (float*)d_out;

    __nv_bfloat16 *qkvh, *qkvl, *xh, *xl, *wqh, *wql, *ah, *al, *woh, *wol;
    cudaGetSymbolAddress((void**)&qkvh, g_qkvh); cudaGetSymbolAddress((void**)&qkvl, g_qkvl);
    cudaGetSymbolAddress((void**)&xh, g_xh);   cudaGetSymbolAddress((void**)&xl, g_xl);
    cudaGetSymbolAddress((void**)&wqh, g_wqh); cudaGetSymbolAddress((void**)&wql, g_wql);
    cudaGetSymbolAddress((void**)&ah, g_ah);   cudaGetSymbolAddress((void**)&al, g_al);
    cudaGetSymbolAddress((void**)&woh, g_woh); cudaGetSymbolAddress((void**)&wol, g_wol);

    cudaFuncSetAttribute(gemm_bf16x3, cudaFuncAttributeMaxDynamicSharedMemorySize, GEMM_SMEM);
    cudaFuncSetAttribute(attn_mma, cudaFuncAttributeMaxDynamicSharedMemorySize, FA_SMEM);

    // 1) split inputs to bf16 hi/lo
    split_bf16<<<(M_ROWS * K_DIM / 4 + 255) / 256, 256>>>(x, xh, xl, M_ROWS * K_DIM / 4);
    split_bf16<<<(QKV_COLS * K_DIM / 4 + 255) / 256, 256>>>(w_qkv, wqh, wql, QKV_COLS * K_DIM / 4);

    // 2) QKV projection with fused RoPE + hi/lo split epilogue
    gemm_bf16x3<<<dim3(QKV_COLS / 128, M_ROWS / 128), 256, GEMM_SMEM>>>(
        xh, xl, wqh, wql, nullptr, qkvh, qkvl, pos, QKV_COLS);

    // 3) tensor-core causal flash attention -> bf16 hi/lo
    attn_mma<<<dim3(L_SEQ / 128, B_SZ * N_HEADS_C), 256, FA_SMEM>>>(qkvh, qkvl, ah, al);

    // 4) output projection (plain fp32 epilogue to d_out)
    split_bf16<<<(D_MODEL * K_DIM / 4 + 255) / 256, 256>>>(w_out, woh, wol, D_MODEL * K_DIM / 4);
    gemm_bf16x3<<<dim3(D_MODEL / 128, M_ROWS / 128), 256, GEMM_SMEM>>>(
        ah, al, woh, wol, out, nullptr, nullptr, nullptr, D_MODEL);
}

// round 12
// speedup vs baseline: 1.5697x; 1.0184x over previous
#include <cuda_runtime.h>
#include <cuda_bf16.h>
#include <math.h>
#include <stdint.h>

// ---------------- problem constants ----------------
#define D_MODEL   1536
#define N_HEADS_C 24
#define DH        64
#define B_SZ      4
#define L_SEQ     2048
#define M_ROWS    (B_SZ * L_SEQ)     // 8192
#define QKV_COLS  (3 * D_MODEL)      // 4608
#define K_DIM     1536

// single dynamic smem symbol shared by all kernels
extern __shared__ char dyn_smem[];

// ---------------- scratch (device globals; no allocation allowed) ---------
__device__ __nv_bfloat16 g_qkvh[(size_t)M_ROWS * QKV_COLS];
__device__ __nv_bfloat16 g_qkvl[(size_t)M_ROWS * QKV_COLS];
__device__ __nv_bfloat16 g_xh[(size_t)M_ROWS * K_DIM];
__device__ __nv_bfloat16 g_xl[(size_t)M_ROWS * K_DIM];
__device__ __nv_bfloat16 g_wqh[(size_t)QKV_COLS * K_DIM];
__device__ __nv_bfloat16 g_wql[(size_t)QKV_COLS * K_DIM];
__device__ __nv_bfloat16 g_ah[(size_t)M_ROWS * K_DIM];
__device__ __nv_bfloat16 g_al[(size_t)M_ROWS * K_DIM];
__device__ __nv_bfloat16 g_woh[(size_t)D_MODEL * K_DIM];
__device__ __nv_bfloat16 g_wol[(size_t)D_MODEL * K_DIM];

// inv_freq[d] = 10000^(-d/32) = 10^(-d/8)
__constant__ float c_invf[32] = {
    1.0f, 0.7498942093324559f, 0.5623413251903491f, 0.42169650342858224f,
    0.31622776601683794f, 0.23713737056616552f, 0.1778279410038923f, 0.1333521432163324f,
    0.1f, 0.07498942093324558f, 0.05623413251903491f, 0.042169650342858224f,
    0.031622776601683794f, 0.023713737056616552f, 0.01778279410038923f, 0.01333521432163324f,
    0.01f, 0.007498942093324558f, 0.005623413251903491f, 0.0042169650342858224f,
    0.0031622776601683794f, 0.0023713737056616552f, 0.001778279410038923f, 0.0013335214321633241f,
    0.001f, 0.0007498942093324558f, 0.0005623413251903491f, 0.00042169650342858224f,
    0.00031622776601683794f, 0.00023713737056616552f, 0.0001778279410038923f, 0.00013335214321633242f
};

// ---------------- helpers --------------------------------------------------
__device__ __forceinline__ uint32_t smem_u32(const void* p) {
    uint32_t a;
    asm("{ .reg .u64 t; cvta.to.shared.u64 t, %1; cvt.u32.u64 %0, t; }" : "=r"(a) : "l"(p));
    return a;
}

#define CP_ASYNC16(dst, src) \
    asm volatile("cp.async.cg.shared.global [%0], [%1], 16;" :: "r"(dst), "l"(src))
#define CP_COMMIT() asm volatile("cp.async.commit_group;" ::: "memory")
#define CP_WAIT(N)  asm volatile("cp.async.wait_group %0;" :: "n"(N) : "memory")

#define LDSM_X4(r0, r1, r2, r3, addr) \
    asm volatile("ldmatrix.sync.aligned.m8n8.x4.shared.b16 {%0,%1,%2,%3}, [%4];" \
        : "=r"(r0), "=r"(r1), "=r"(r2), "=r"(r3) : "r"(addr))

#define LDSM_X4_T(r0, r1, r2, r3, addr) \
    asm volatile("ldmatrix.sync.aligned.m8n8.x4.trans.shared.b16 {%0,%1,%2,%3}, [%4];" \
        : "=r"(r0), "=r"(r1), "=r"(r2), "=r"(r3) : "r"(addr))

#define MMA_BF16(c, a, b0_, b1_) \
    asm volatile("mma.sync.aligned.m16n8k16.row.col.f32.bf16.bf16.f32 " \
        "{%0,%1,%2,%3}, {%4,%5,%6,%7}, {%8,%9}, {%0,%1,%2,%3};" \
        : "+f"((c)[0]), "+f"((c)[1]), "+f"((c)[2]), "+f"((c)[3]) \
        : "r"((a)[0]), "r"((a)[1]), "r"((a)[2]), "r"((a)[3]), "r"(b0_), "r"(b1_))

__device__ __forceinline__ uint32_t sw128(uint32_t off) {
    return off ^ ((off >> 3) & 0x70);
}

__device__ __forceinline__ uint32_t pack_bf16(float lo, float hi) {
    uint32_t d;
    asm("cvt.rn.bf16x2.f32 %0, %1, %2;" : "=r"(d) : "f"(hi), "f"(lo));
    return d;
}

__device__ __forceinline__ void sincos_rope(float fr, float* s, float* c) {
    float n  = rintf(fr * 0.15915494309189535f);
    float r1 = fmaf(n, -6.2831855f, fr);
    float r  = fmaf(n,  1.7484556e-7f, r1);
    __sincosf(r, s, c);
}

// ===========================================================================
// split fp32 -> bf16 hi + bf16 lo
// ===========================================================================
__global__ __launch_bounds__(256) void split_bf16(
    const float* __restrict__ s, __nv_bfloat16* __restrict__ hi,
    __nv_bfloat16* __restrict__ lo, int n4)
{
    int i = blockIdx.x * blockDim.x + threadIdx.x;
    if (i >= n4) return;
    float4 v = ((const float4*)s)[i];
    uint32_t h01 = pack_bf16(v.x, v.y);
    uint32_t h23 = pack_bf16(v.z, v.w);
    float f0 = __uint_as_float(h01 << 16), f1 = __uint_as_float(h01 & 0xFFFF0000u);
    float f2 = __uint_as_float(h23 << 16), f3 = __uint_as_float(h23 & 0xFFFF0000u);
    uint32_t l01 = pack_bf16(v.x - f0, v.y - f1);
    uint32_t l23 = pack_bf16(v.z - f2, v.w - f3);
    ((uint2*)hi)[i] = make_uint2(h01, h23);
    ((uint2*)lo)[i] = make_uint2(l01, l23);
}

// ===========================================================================
// Split-bf16 3-product GEMM via mma.sync (round-7 math exactly).
// NEW: 3-stage cp.async pipeline, ONE __syncthreads per chunk.
// stage(c) = c % 3; load(c+2) overwrites stage(c-1)'s buffer, which the
// top-of-loop sync already protects.
// ===========================================================================
#define GK_CHUNKS 24
#define TILE_B    16384
#define STAGE_B   (4 * TILE_B)            // 64 KB: Ah, Al, Bh, Bl
#define GEMM_SMEM (3 * STAGE_B)           // 192 KB

__global__ __launch_bounds__(256, 1) void gemm_bf16x3(
    const __nv_bfloat16* __restrict__ Ah, const __nv_bfloat16* __restrict__ Al,
    const __nv_bfloat16* __restrict__ Bh, const __nv_bfloat16* __restrict__ Bl,
    float* __restrict__ C,
    __nv_bfloat16* __restrict__ Chi, __nv_bfloat16* __restrict__ Clo,
    const int* __restrict__ pos, int N)
{
    const uint32_t sbu = smem_u32(dyn_smem);

    const int tid  = threadIdx.x;
    const int wid  = tid >> 5;
    const int lane = tid & 31;
    const int wm   = wid & 1;
    const int wn   = wid >> 1;
    const int m0   = blockIdx.y * 128;
    const int n0   = blockIdx.x * 128;

    const __nv_bfloat16* srcs[4] = {
        Ah + (size_t)m0 * K_DIM, Al + (size_t)m0 * K_DIM,
        Bh + (size_t)n0 * K_DIM, Bl + (size_t)n0 * K_DIM };

    int unit_row[4], unit_u[4];
#pragma unroll
    for (int i = 0; i < 4; i++) {
        int unit = tid + i * 256;
        unit_row[i] = unit >> 3;
        unit_u[i]   = unit & 7;
    }

    auto load_stage = [&](int c, int s) {
        uint32_t sb = sbu + s * STAGE_B;
#pragma unroll
        for (int op = 0; op < 4; op++) {
            const __nv_bfloat16* src = srcs[op] + c * 64;
            uint32_t ob = sb + op * TILE_B;
#pragma unroll
            for (int i = 0; i < 4; i++) {
                const __nv_bfloat16* g = src + (size_t)unit_row[i] * K_DIM + unit_u[i] * 8;
                uint32_t d = ob + sw128(unit_row[i] * 128 + unit_u[i] * 16);
                CP_ASYNC16(d, g);
            }
        }
        CP_COMMIT();
    };

    float acc[4][4][4];
#pragma unroll
    for (int i = 0; i < 4; i++)
#pragma unroll
        for (int j = 0; j < 4; j++)
#pragma unroll
            for (int k = 0; k < 4; k++) acc[i][j][k] = 0.f;

    load_stage(0, 0);
    load_stage(1, 1);

    const int lrow = lane & 15;
    const int lhalf = (lane >> 4) * 16;

    for (int c = 0; c < GK_CHUNKS; c++) {
        if (c + 1 < GK_CHUNKS) { CP_WAIT(1); } else { CP_WAIT(0); }
        __syncthreads();                              // single sync per chunk
        if (c + 2 < GK_CHUNKS) load_stage(c + 2, (c + 2) % 3);

        const uint32_t sb = sbu + (c % 3) * STAGE_B;
        const uint32_t aH = sb + 0 * TILE_B;
        const uint32_t aL = sb + 1 * TILE_B;
        const uint32_t bH = sb + 2 * TILE_B;
        const uint32_t bL = sb + 3 * TILE_B;

#pragma unroll
        for (int k16 = 0; k16 < 4; k16++) {
            const uint32_t kb = k16 * 32 + lhalf;
            uint32_t ah[4][4], al[4][4];
#pragma unroll
            for (int i = 0; i < 4; i++) {
                int row = wm * 64 + i * 16 + lrow;
                uint32_t o = sw128(row * 128 + kb);
                LDSM_X4(ah[i][0], ah[i][1], ah[i][2], ah[i][3], aH + o);
                LDSM_X4(al[i][0], al[i][1], al[i][2], al[i][3], aL + o);
            }
            uint32_t bh[2][4], bl[2][4];
#pragma unroll
            for (int j = 0; j < 2; j++) {
                int row = wn * 32 + j * 16 + lrow;
                uint32_t o = sw128(row * 128 + kb);
                LDSM_X4(bh[j][0], bh[j][1], bh[j][2], bh[j][3], bH + o);
                LDSM_X4(bl[j][0], bl[j][1], bl[j][2], bl[j][3], bL + o);
            }
#pragma unroll
            for (int i = 0; i < 4; i++) {
#pragma unroll
                for (int jn = 0; jn < 4; jn++) {
                    const int j = jn >> 1, s = jn & 1;
                    MMA_BF16(acc[i][jn], ah[i], bh[j][s], bh[j][s + 2]);
                    MMA_BF16(acc[i][jn], ah[i], bl[j][s], bl[j][s + 2]);
                    MMA_BF16(acc[i][jn], al[i], bh[j][s], bh[j][s + 2]);
                }
            }
        }
    }

    const int er = lane >> 2;
    const int ec = (lane & 3) * 2;

    if (!Chi) {
#pragma unroll
        for (int i = 0; i < 4; i++) {
            int r0 = m0 + wm * 64 + i * 16 + er;
#pragma unroll
            for (int jn = 0; jn < 4; jn++) {
                int col = n0 + wn * 32 + jn * 8 + ec;
                *(float2*)(C + (size_t)r0 * N + col)       = make_float2(acc[i][jn][0], acc[i][jn][1]);
                *(float2*)(C + (size_t)(r0 + 8) * N + col) = make_float2(acc[i][jn][2], acc[i][jn][3]);
            }
        }
    } else if (n0 >= 2 * D_MODEL) {
        // v section: direct register split-store (no rope)
#pragma unroll
        for (int i = 0; i < 4; i++) {
#pragma unroll
            for (int jn = 0; jn < 4; jn++) {
                int col = n0 + wn * 32 + jn * 8 + ec;
#pragma unroll
                for (int half = 0; half < 2; half++) {
                    int r = m0 + wm * 64 + i * 16 + er + half * 8;
                    float a0 = acc[i][jn][2 * half], a1 = acc[i][jn][2 * half + 1];
                    uint32_t hh = pack_bf16(a0, a1);
                    float f0 = __uint_as_float(hh << 16), f1 = __uint_as_float(hh & 0xFFFF0000u);
                    uint32_t ll = pack_bf16(a0 - f0, a1 - f1);
                    size_t o = (size_t)r * N + col;
                    *(uint32_t*)(Chi + o) = hh;
                    *(uint32_t*)(Clo + o) = ll;
                }
            }
        }
    } else {
        // q/k section: stage tile in smem, apply RoPE, split-store.
        // Safe to reuse smem: sync below orders all mainloop reads before RoPE reads,
        // and Ct writes only touch each thread's own fragment slots before that.
        float* Ct = (float*)dyn_smem;                    // [128][130]
        __syncthreads();                                  // all warps done with mainloop smem
#pragma unroll
        for (int i = 0; i < 4; i++) {
            int rl = wm * 64 + i * 16 + er;
#pragma unroll
            for (int jn = 0; jn < 4; jn++) {
                int cl = wn * 32 + jn * 8 + ec;
                Ct[rl * 130 + cl]           = acc[i][jn][0];
                Ct[rl * 130 + cl + 1]       = acc[i][jn][1];
                Ct[(rl + 8) * 130 + cl]     = acc[i][jn][2];
                Ct[(rl + 8) * 130 + cl + 1] = acc[i][jn][3];
            }
        }
        __syncthreads();
        const int po = *pos;
#pragma unroll
        for (int it = 0; it < 32; it++) {
            int idx = tid + it * 256;
            int hd  = idx & 63;
            int row = idx >> 6;
            int d   = hd & 31;
            int cl  = (hd >> 5) * 64 + d;
            float x1 = Ct[row * 130 + cl];
            float x2 = Ct[row * 130 + cl + 32];
            int l = (m0 + row) & (L_SEQ - 1);
            float s, c;
            sincos_rope((float)(l + po) * c_invf[d], &s, &c);
            float y1 = x1 * c - x2 * s;
            float y2 = x2 * c + x1 * s;
            __nv_bfloat16 h1 = __float2bfloat16_rn(y1);
            __nv_bfloat16 h2 = __float2bfloat16_rn(y2);
            size_t o = (size_t)(m0 + row) * N + n0 + cl;
            Chi[o]      = h1;
            Chi[o + 32] = h2;
            Clo[o]      = __float2bfloat16_rn(y1 - __bfloat162float(h1));
            Clo[o + 32] = __float2bfloat16_rn(y2 - __bfloat162float(h2));
        }
    }
}

// ===========================================================================
// Tensor-core causal flash attention (round-7 math exactly).
// NEW: 3-stage KV pipeline, ONE __syncthreads per KV tile.
// ===========================================================================
#define FQH 0
#define FQL 16384
#define FST 32768
#define FSTG 32768
#define FA_SMEM (FST + 3 * FSTG)   // 131072

__global__ __launch_bounds__(256, 1) void attn_mma(
    const __nv_bfloat16* __restrict__ qkvh,
    const __nv_bfloat16* __restrict__ qkvl,
    __nv_bfloat16* __restrict__ ohp,
    __nv_bfloat16* __restrict__ olp)
{
    const uint32_t sbu = smem_u32(dyn_smem);
    const int tid  = threadIdx.x;
    const int wid  = tid >> 5;
    const int lane = tid & 31;
    const int lrow = lane & 15;
    const int lhalf = (lane >> 4) * 16;

    const int qt = gridDim.x - 1 - blockIdx.x;
    const int bh = blockIdx.y;
    const int b  = bh / N_HEADS_C;
    const int h  = bh % N_HEADS_C;
    const size_t rowbase = (size_t)b * L_SEQ;

    {
        int op  = tid >> 7;
        int row = tid & 127;
        const __nv_bfloat16* src = (op ? qkvl : qkvh)
            + (rowbase + qt * 128 + row) * QKV_COLS + h * DH;
        uint32_t dstb = sbu + (op ? FQL : FQH);
#pragma unroll
        for (int c = 0; c < 8; c++)
            CP_ASYNC16(dstb + sw128(row * 128 + c * 16), src + c * 8);
        CP_COMMIT();
    }

    const int ktmax = 2 * qt + 1;

    auto load_kv = [&](int kt, int s) {
        int op  = tid >> 6;
        int row = tid & 63;
        const __nv_bfloat16* base = (op & 1) ? qkvl : qkvh;
        int colofs = (op >> 1) ? (2 * D_MODEL + h * DH) : (D_MODEL + h * DH);
        const __nv_bfloat16* src = base + (rowbase + kt * 64 + row) * QKV_COLS + colofs;
        uint32_t dstb = sbu + FST + s * FSTG + op * 8192;
#pragma unroll
        for (int c = 0; c < 8; c++)
            CP_ASYNC16(dstb + sw128(row * 128 + c * 16), src + c * 8);
        CP_COMMIT();
    };

    load_kv(0, 0);
    load_kv(1, 1);

    CP_WAIT(2);                         // Q group done (kv0, kv1 may be pending)
    __syncthreads();
    uint32_t qh[4][4], ql[4][4];
#pragma unroll
    for (int c = 0; c < 4; c++) {
        uint32_t o = sw128((wid * 16 + lrow) * 128 + c * 32 + lhalf);
        LDSM_X4(qh[c][0], qh[c][1], qh[c][2], qh[c][3], sbu + FQH + o);
        LDSM_X4(ql[c][0], ql[c][1], ql[c][2], ql[c][3], sbu + FQL + o);
    }

    float oa[8][4];
#pragma unroll
    for (int nt = 0; nt < 8; nt++)
#pragma unroll
        for (int r = 0; r < 4; r++) oa[nt][r] = 0.f;
    float m0 = -INFINITY, m1 = -INFINITY, l0 = 0.f, l1 = 0.f;

    const int row0 = qt * 128 + wid * 16 + (lane >> 2);
    const int row1 = row0 + 8;
    const int colq = 2 * (lane & 3);

    for (int kt = 0; kt <= ktmax; kt++) {
        if (kt + 1 <= ktmax) { CP_WAIT(1); } else { CP_WAIT(0); }
        __syncthreads();                              // single sync per tile
        if (kt + 2 <= ktmax) load_kv(kt + 2, (kt + 2) % 3);

        const uint32_t su = sbu + FST + (kt % 3) * FSTG;
        const uint32_t KH = su, KL = su + 8192, VH = su + 16384, VL = su + 24576;

        float sc[8][4];
#pragma unroll
        for (int nt = 0; nt < 8; nt++)
#pragma unroll
            for (int r = 0; r < 4; r++) sc[nt][r] = 0.f;

#pragma unroll
        for (int c = 0; c < 4; c++) {
            const uint32_t kb = c * 32 + lhalf;
#pragma unroll
            for (int g = 0; g < 4; g++) {
                uint32_t o = sw128((g * 16 + lrow) * 128 + kb);
                uint32_t kh4[4], kl4[4];
                LDSM_X4(kh4[0], kh4[1], kh4[2], kh4[3], KH + o);
                LDSM_X4(kl4[0], kl4[1], kl4[2], kl4[3], KL + o);
                MMA_BF16(sc[2 * g],     qh[c], kh4[0], kh4[2]);
                MMA_BF16(sc[2 * g + 1], qh[c], kh4[1], kh4[3]);
                MMA_BF16(sc[2 * g],     qh[c], kl4[0], kl4[2]);
                MMA_BF16(sc[2 * g + 1], qh[c], kl4[1], kl4[3]);
                MMA_BF16(sc[2 * g],     ql[c], kh4[0], kh4[2]);
                MMA_BF16(sc[2 * g + 1], ql[c], kh4[1], kh4[3]);
            }
        }

        const bool diag = (kt >= 2 * qt);
#pragma unroll
        for (int nt = 0; nt < 8; nt++) {
            int colg = kt * 64 + nt * 8 + colq;
#pragma unroll
            for (int r = 0; r < 4; r++) {
                float s = sc[nt][r] * 0.125f;
                if (diag) {
                    int cg = colg + (r & 1);
                    int rg = (r < 2) ? row0 : row1;
                    if (cg > rg) s = -1e30f;
                }
                sc[nt][r] = s;
            }
        }

        float rm0 = -INFINITY, rm1 = -INFINITY;
#pragma unroll
        for (int nt = 0; nt < 8; nt++) {
            rm0 = fmaxf(rm0, fmaxf(sc[nt][0], sc[nt][1]));
            rm1 = fmaxf(rm1, fmaxf(sc[nt][2], sc[nt][3]));
        }
        rm0 = fmaxf(rm0, __shfl_xor_sync(0xffffffffu, rm0, 1));
        rm0 = fmaxf(rm0, __shfl_xor_sync(0xffffffffu, rm0, 2));
        rm1 = fmaxf(rm1, __shfl_xor_sync(0xffffffffu, rm1, 1));
        rm1 = fmaxf(rm1, __shfl_xor_sync(0xffffffffu, rm1, 2));

        float m0n = fmaxf(m0, rm0), m1n = fmaxf(m1, rm1);
        float cr0 = __expf(m0 - m0n), cr1 = __expf(m1 - m1n);
        l0 *= cr0; l1 *= cr1;
#pragma unroll
        for (int nt = 0; nt < 8; nt++) {
            oa[nt][0] *= cr0; oa[nt][1] *= cr0;
            oa[nt][2] *= cr1; oa[nt][3] *= cr1;
        }
        m0 = m0n; m1 = m1n;

        uint32_t pha[8], phb[8], pla[8], plb[8];
#pragma unroll
        for (int nt = 0; nt < 8; nt++) {
            float p0 = __expf(sc[nt][0] - m0n);
            float p1 = __expf(sc[nt][1] - m0n);
            float p2 = __expf(sc[nt][2] - m1n);
            float p3 = __expf(sc[nt][3] - m1n);
            l0 += p0 + p1; l1 += p2 + p3;
            uint32_t h01 = pack_bf16(p0, p1);
            uint32_t h23 = pack_bf16(p2, p3);
            pha[nt] = h01; phb[nt] = h23;
            float f0 = __uint_as_float(h01 << 16), f1 = __uint_as_float(h01 & 0xFFFF0000u);
            float f2 = __uint_as_float(h23 << 16), f3 = __uint_as_float(h23 & 0xFFFF0000u);
            pla[nt] = pack_bf16(p0 - f0, p1 - f1);
            plb[nt] = pack_bf16(p2 - f2, p3 - f3);
        }

#pragma unroll
        for (int kc = 0; kc < 4; kc++) {
            uint32_t pah[4] = { pha[2 * kc], phb[2 * kc], pha[2 * kc + 1], phb[2 * kc + 1] };
            uint32_t pal[4] = { pla[2 * kc], plb[2 * kc], pla[2 * kc + 1], plb[2 * kc + 1] };
#pragma unroll
            for (int dp = 0; dp < 4; dp++) {
                uint32_t o = sw128((kc * 16 + lrow) * 128 + dp * 32 + lhalf);
                uint32_t vh4[4], vl4[4];
                LDSM_X4_T(vh4[0], vh4[1], vh4[2], vh4[3], VH + o);
                LDSM_X4_T(vl4[0], vl4[1], vl4[2], vl4[3], VL + o);
                MMA_BF16(oa[2 * dp],     pah, vh4[0], vh4[1]);
                MMA_BF16(oa[2 * dp + 1], pah, vh4[2], vh4[3]);
                MMA_BF16(oa[2 * dp],     pah, vl4[0], vl4[1]);
                MMA_BF16(oa[2 * dp + 1], pah, vl4[2], vl4[3]);
                MMA_BF16(oa[2 * dp],     pal, vh4[0], vh4[1]);
                MMA_BF16(oa[2 * dp + 1], pal, vh4[2], vh4[3]);
            }
        }
    }

    l0 += __shfl_xor_sync(0xffffffffu, l0, 1);
    l0 += __shfl_xor_sync(0xffffffffu, l0, 2);
    l1 += __shfl_xor_sync(0xffffffffu, l1, 1);
    l1 += __shfl_xor_sync(0xffffffffu, l1, 2);
    float i0 = 1.f / l0, i1 = 1.f / l1;

    size_t ob0 = (rowbase + row0) * D_MODEL + h * DH;
    size_t ob1 = (rowbase + row1) * D_MODEL + h * DH;
#pragma unroll
    for (int nt = 0; nt < 8; nt++) {
        int col = nt * 8 + colq;
        float a0 = oa[nt][0] * i0, a1 = oa[nt][1] * i0;
        float a2 = oa[nt][2] * i1, a3 = oa[nt][3] * i1;
        uint32_t h01 = pack_bf16(a0, a1);
        uint32_t h23 = pack_bf16(a2, a3);
        float f0 = __uint_as_float(h01 << 16), f1 = __uint_as_float(h01 & 0xFFFF0000u);
        float f2 = __uint_as_float(h23 << 16), f3 = __uint_as_float(h23 & 0xFFFF0000u);
        *(uint32_t*)(ohp + ob0 + col) = h01;
        *(uint32_t*)(olp + ob0 + col) = pack_bf16(a0 - f0, a1 - f1);
        *(uint32_t*)(ohp + ob1 + col) = h23;
        *(uint32_t*)(olp + ob1 + col) = pack_bf16(a2 - f2, a3 - f3);
    }
}

// ===========================================================================
// launch
// ===========================================================================
extern "C" void kernel_launch(void* const* d_in, const int* in_sizes, int n_in,
                              void* d_out, int out_size)
{
    const float* x     = (const float*)d_in[0];
    const float* w_qkv = (const float*)d_in[1];
    const float* w_out = (const float*)d_in[2];
    const int*   pos   = (const int*)d_in[3];
    float*       out   = (float*)d_out;

    __nv_bfloat16 *qkvh, *qkvl, *xh, *xl, *wqh, *wql, *ah, *al, *woh, *wol;
    cudaGetSymbolAddress((void**)&qkvh, g_qkvh); cudaGetSymbolAddress((void**)&qkvl, g_qkvl);
    cudaGetSymbolAddress((void**)&xh, g_xh);   cudaGetSymbolAddress((void**)&xl, g_xl);
    cudaGetSymbolAddress((void**)&wqh, g_wqh); cudaGetSymbolAddress((void**)&wql, g_wql);
    cudaGetSymbolAddress((void**)&ah, g_ah);   cudaGetSymbolAddress((void**)&al, g_al);
    cudaGetSymbolAddress((void**)&woh, g_woh); cudaGetSymbolAddress((void**)&wol, g_wol);

    cudaFuncSetAttribute(gemm_bf16x3, cudaFuncAttributeMaxDynamicSharedMemorySize, GEMM_SMEM);
    cudaFuncSetAttribute(attn_mma, cudaFuncAttributeMaxDynamicSharedMemorySize, FA_SMEM);

    // 1) split inputs to bf16 hi/lo
    split_bf16<<<(M_ROWS * K_DIM / 4 + 255) / 256, 256>>>(x, xh, xl, M_ROWS * K_DIM / 4);
    split_bf16<<<(QKV_COLS * K_DIM / 4 + 255) / 256, 256>>>(w_qkv, wqh, wql, QKV_COLS * K_DIM / 4);

    // 2) QKV projection with fused RoPE + hi/lo split epilogue
    gemm_bf16x3<<<dim3(QKV_COLS / 128, M_ROWS / 128), 256, GEMM_SMEM>>>(
        xh, xl, wqh, wql, nullptr, qkvh, qkvl, pos, QKV_COLS);

    // 3) tensor-core causal flash attention -> bf16 hi/lo
    attn_mma<<<dim3(L_SEQ / 128, B_SZ * N_HEADS_C), 256, FA_SMEM>>>(qkvh, qkvl, ah, al);

    // 4) output projection (plain fp32 epilogue to d_out)
    split_bf16<<<(D_MODEL * K_DIM / 4 + 255) / 256, 256>>>(w_out, woh, wol, D_MODEL * K_DIM / 4);
    gemm_bf16x3<<<dim3(D_MODEL / 128, M_ROWS / 128), 256, GEMM_SMEM>>>(
        ah, al, woh, wol, out, nullptr, nullptr, nullptr, D_MODEL);
}

// round 13
// speedup vs baseline: 2.3171x; 1.4761x over previous
#include <cuda_runtime.h>
#include <cuda_fp16.h>
#include <math.h>
#include <stdint.h>

// ---------------- problem constants ----------------
#define D_MODEL   1536
#define N_HEADS_C 24
#define DH        64
#define B_SZ      4
#define L_SEQ     2048
#define M_ROWS    (B_SZ * L_SEQ)     // 8192
#define QKV_COLS  (3 * D_MODEL)      // 4608
#define K_DIM     1536

// single dynamic smem symbol shared by all kernels
extern __shared__ char dyn_smem[];

// ---------------- scratch (device globals; no allocation allowed) ---------
__device__ __half g_qkvh[(size_t)M_ROWS * QKV_COLS];
__device__ __half g_qkvl[(size_t)M_ROWS * QKV_COLS];
__device__ __half g_xh[(size_t)M_ROWS * K_DIM];
__device__ __half g_xl[(size_t)M_ROWS * K_DIM];
__device__ __half g_wqh[(size_t)QKV_COLS * K_DIM];
__device__ __half g_ah[(size_t)M_ROWS * K_DIM];
__device__ __half g_al[(size_t)M_ROWS * K_DIM];
__device__ __half g_woh[(size_t)D_MODEL * K_DIM];

// inv_freq[d] = 10000^(-d/32) = 10^(-d/8)
__constant__ float c_invf[32] = {
    1.0f, 0.7498942093324559f, 0.5623413251903491f, 0.42169650342858224f,
    0.31622776601683794f, 0.23713737056616552f, 0.1778279410038923f, 0.1333521432163324f,
    0.1f, 0.07498942093324558f, 0.05623413251903491f, 0.042169650342858224f,
    0.031622776601683794f, 0.023713737056616552f, 0.01778279410038923f, 0.01333521432163324f,
    0.01f, 0.007498942093324558f, 0.005623413251903491f, 0.0042169650342858224f,
    0.0031622776601683794f, 0.0023713737056616552f, 0.001778279410038923f, 0.0013335214321633241f,
    0.001f, 0.0007498942093324558f, 0.0005623413251903491f, 0.00042169650342858224f,
    0.00031622776601683794f, 0.00023713737056616552f, 0.0001778279410038923f, 0.00013335214321633242f
};

// ---------------- helpers --------------------------------------------------
__device__ __forceinline__ uint32_t smem_u32(const void* p) {
    uint32_t a;
    asm("{ .reg .u64 t; cvta.to.shared.u64 t, %1; cvt.u32.u64 %0, t; }" : "=r"(a) : "l"(p));
    return a;
}

#define CP_ASYNC16(dst, src) \
    asm volatile("cp.async.cg.shared.global [%0], [%1], 16;" :: "r"(dst), "l"(src))
#define CP_COMMIT() asm volatile("cp.async.commit_group;" ::: "memory")
#define CP_WAIT(N)  asm volatile("cp.async.wait_group %0;" :: "n"(N) : "memory")

#define LDSM_X4(r0, r1, r2, r3, addr) \
    asm volatile("ldmatrix.sync.aligned.m8n8.x4.shared.b16 {%0,%1,%2,%3}, [%4];" \
        : "=r"(r0), "=r"(r1), "=r"(r2), "=r"(r3) : "r"(addr))

#define LDSM_X4_T(r0, r1, r2, r3, addr) \
    asm volatile("ldmatrix.sync.aligned.m8n8.x4.trans.shared.b16 {%0,%1,%2,%3}, [%4];" \
        : "=r"(r0), "=r"(r1), "=r"(r2), "=r"(r3) : "r"(addr))

#define MMA_F16(c, a, b0_, b1_) \
    asm volatile("mma.sync.aligned.m16n8k16.row.col.f32.f16.f16.f32 " \
        "{%0,%1,%2,%3}, {%4,%5,%6,%7}, {%8,%9}, {%0,%1,%2,%3};" \
        : "+f"((c)[0]), "+f"((c)[1]), "+f"((c)[2]), "+f"((c)[3]) \
        : "r"((a)[0]), "r"((a)[1]), "r"((a)[2]), "r"((a)[3]), "r"(b0_), "r"(b1_))

__device__ __forceinline__ uint32_t sw128(uint32_t off) {
    return off ^ ((off >> 3) & 0x70);
}

// pack two floats into fp16x2 (lo -> lower half, hi -> upper half)
__device__ __forceinline__ uint32_t pack_f16(float lo, float hi) {
    uint32_t d;
    asm("cvt.rn.f16x2.f32 %0, %1, %2;" : "=r"(d) : "f"(hi), "f"(lo));
    return d;
}

__device__ __forceinline__ void sincos_rope(float fr, float* s, float* c) {
    float n  = rintf(fr * 0.15915494309189535f);
    float r1 = fmaf(n, -6.2831855f, fr);
    float r  = fmaf(n,  1.7484556e-7f, r1);
    __sincosf(r, s, c);
}

// ===========================================================================
// split fp32 -> fp16 hi + fp16 lo
// ===========================================================================
__global__ __launch_bounds__(256) void split_f16(
    const float* __restrict__ s, __half* __restrict__ hi,
    __half* __restrict__ lo, int n4)
{
    int i = blockIdx.x * blockDim.x + threadIdx.x;
    if (i >= n4) return;
    float4 v = ((const float4*)s)[i];
    __half h0 = __float2half_rn(v.x), h1 = __float2half_rn(v.y);
    __half h2 = __float2half_rn(v.z), h3 = __float2half_rn(v.w);
    __half l0 = __float2half_rn(v.x - __half2float(h0));
    __half l1 = __float2half_rn(v.y - __half2float(h1));
    __half l2 = __float2half_rn(v.z - __half2float(h2));
    __half l3 = __float2half_rn(v.w - __half2float(h3));
    ((ushort4*)hi)[i] = make_ushort4(__half_as_ushort(h0), __half_as_ushort(h1),
                                     __half_as_ushort(h2), __half_as_ushort(h3));
    ((ushort4*)lo)[i] = make_ushort4(__half_as_ushort(l0), __half_as_ushort(l1),
                                     __half_as_ushort(l2), __half_as_ushort(l3));
}

// convert fp32 -> fp16 (hi only, for the B/weight side)
__global__ __launch_bounds__(256) void conv_f16(
    const float* __restrict__ s, __half* __restrict__ hi, int n4)
{
    int i = blockIdx.x * blockDim.x + threadIdx.x;
    if (i >= n4) return;
    float4 v = ((const float4*)s)[i];
    ((ushort4*)hi)[i] = make_ushort4(
        __half_as_ushort(__float2half_rn(v.x)), __half_as_ushort(__float2half_rn(v.y)),
        __half_as_ushort(__float2half_rn(v.z)), __half_as_ushort(__float2half_rn(v.w)));
}

// ===========================================================================
// fp16 2-product GEMM via mma.sync: C = (Ah+Al)[M,K] * Bh[N,K]^T
// BM=BN=128, BK=64, 3-stage cp.async pipeline, one sync per chunk.
// smem/stage: Ah 16K | Al 16K | Bh 16K = 48KB; 3 stages = 144KB.
// ===========================================================================
#define GK_CHUNKS 24
#define TILE_B    16384
#define STAGE_B   (3 * TILE_B)            // 48 KB
#define GEMM_SMEM (3 * STAGE_B)           // 144 KB

__global__ __launch_bounds__(256, 1) void gemm_f16x2(
    const __half* __restrict__ Ah, const __half* __restrict__ Al,
    const __half* __restrict__ Bh,
    float* __restrict__ C,
    __half* __restrict__ Chi, __half* __restrict__ Clo,
    const int* __restrict__ pos, int N)
{
    const uint32_t sbu = smem_u32(dyn_smem);

    const int tid  = threadIdx.x;
    const int wid  = tid >> 5;
    const int lane = tid & 31;
    const int wm   = wid & 1;
    const int wn   = wid >> 1;
    const int m0   = blockIdx.y * 128;
    const int n0   = blockIdx.x * 128;

    const __half* srcs[3] = {
        Ah + (size_t)m0 * K_DIM, Al + (size_t)m0 * K_DIM,
        Bh + (size_t)n0 * K_DIM };

    int unit_row[4], unit_u[4];
#pragma unroll
    for (int i = 0; i < 4; i++) {
        int unit = tid + i * 256;
        unit_row[i] = unit >> 3;
        unit_u[i]   = unit & 7;
    }

    auto load_stage = [&](int c, int s) {
        uint32_t sb = sbu + s * STAGE_B;
#pragma unroll
        for (int op = 0; op < 3; op++) {
            const __half* src = srcs[op] + c * 64;
            uint32_t ob = sb + op * TILE_B;
#pragma unroll
            for (int i = 0; i < 4; i++) {
                const __half* g = src + (size_t)unit_row[i] * K_DIM + unit_u[i] * 8;
                uint32_t d = ob + sw128(unit_row[i] * 128 + unit_u[i] * 16);
                CP_ASYNC16(d, g);
            }
        }
        CP_COMMIT();
    };

    float acc[4][4][4];
#pragma unroll
    for (int i = 0; i < 4; i++)
#pragma unroll
        for (int j = 0; j < 4; j++)
#pragma unroll
            for (int k = 0; k < 4; k++) acc[i][j][k] = 0.f;

    load_stage(0, 0);
    load_stage(1, 1);

    const int lrow = lane & 15;
    const int lhalf = (lane >> 4) * 16;

    for (int c = 0; c < GK_CHUNKS; c++) {
        if (c + 1 < GK_CHUNKS) { CP_WAIT(1); } else { CP_WAIT(0); }
        __syncthreads();
        if (c + 2 < GK_CHUNKS) load_stage(c + 2, (c + 2) % 3);

        const uint32_t sb = sbu + (c % 3) * STAGE_B;
        const uint32_t aH = sb + 0 * TILE_B;
        const uint32_t aL = sb + 1 * TILE_B;
        const uint32_t bH = sb + 2 * TILE_B;

#pragma unroll
        for (int k16 = 0; k16 < 4; k16++) {
            const uint32_t kb = k16 * 32 + lhalf;
            uint32_t ah[4][4], al[4][4];
#pragma unroll
            for (int i = 0; i < 4; i++) {
                int row = wm * 64 + i * 16 + lrow;
                uint32_t o = sw128(row * 128 + kb);
                LDSM_X4(ah[i][0], ah[i][1], ah[i][2], ah[i][3], aH + o);
                LDSM_X4(al[i][0], al[i][1], al[i][2], al[i][3], aL + o);
            }
            uint32_t bh[2][4];
#pragma unroll
            for (int j = 0; j < 2; j++) {
                int row = wn * 32 + j * 16 + lrow;
                uint32_t o = sw128(row * 128 + kb);
                LDSM_X4(bh[j][0], bh[j][1], bh[j][2], bh[j][3], bH + o);
            }
#pragma unroll
            for (int i = 0; i < 4; i++) {
#pragma unroll
                for (int jn = 0; jn < 4; jn++) {
                    const int j = jn >> 1, s = jn & 1;
                    MMA_F16(acc[i][jn], ah[i], bh[j][s], bh[j][s + 2]);
                    MMA_F16(acc[i][jn], al[i], bh[j][s], bh[j][s + 2]);
                }
            }
        }
    }

    const int er = lane >> 2;
    const int ec = (lane & 3) * 2;

    if (!Chi) {
        // plain fp32 epilogue
#pragma unroll
        for (int i = 0; i < 4; i++) {
            int r0 = m0 + wm * 64 + i * 16 + er;
#pragma unroll
            for (int jn = 0; jn < 4; jn++) {
                int col = n0 + wn * 32 + jn * 8 + ec;
                *(float2*)(C + (size_t)r0 * N + col)       = make_float2(acc[i][jn][0], acc[i][jn][1]);
                *(float2*)(C + (size_t)(r0 + 8) * N + col) = make_float2(acc[i][jn][2], acc[i][jn][3]);
            }
        }
    } else if (n0 >= 2 * D_MODEL) {
        // v section: hi only (V is a B-side operand downstream; lo never read)
#pragma unroll
        for (int i = 0; i < 4; i++) {
#pragma unroll
            for (int jn = 0; jn < 4; jn++) {
                int col = n0 + wn * 32 + jn * 8 + ec;
#pragma unroll
                for (int half = 0; half < 2; half++) {
                    int r = m0 + wm * 64 + i * 16 + er + half * 8;
                    float a0 = acc[i][jn][2 * half], a1 = acc[i][jn][2 * half + 1];
                    size_t o = (size_t)r * N + col;
                    *(uint32_t*)(Chi + o) = pack_f16(a0, a1);
                }
            }
        }
    } else {
        // q/k section: stage tile in smem, apply RoPE, store hi (+lo for q only)
        float* Ct = (float*)dyn_smem;                    // [128][130]
        __syncthreads();
#pragma unroll
        for (int i = 0; i < 4; i++) {
            int rl = wm * 64 + i * 16 + er;
#pragma unroll
            for (int jn = 0; jn < 4; jn++) {
                int cl = wn * 32 + jn * 8 + ec;
                Ct[rl * 130 + cl]           = acc[i][jn][0];
                Ct[rl * 130 + cl + 1]       = acc[i][jn][1];
                Ct[(rl + 8) * 130 + cl]     = acc[i][jn][2];
                Ct[(rl + 8) * 130 + cl + 1] = acc[i][jn][3];
            }
        }
        __syncthreads();
        const int po = *pos;
        const bool need_lo = (n0 < D_MODEL);             // only Q uses lo downstream
#pragma unroll
        for (int it = 0; it < 32; it++) {
            int idx = tid + it * 256;
            int hd  = idx & 63;
            int row = idx >> 6;
            int d   = hd & 31;
            int cl  = (hd >> 5) * 64 + d;
            float x1 = Ct[row * 130 + cl];
            float x2 = Ct[row * 130 + cl + 32];
            int l = (m0 + row) & (L_SEQ - 1);
            float s, c;
            sincos_rope((float)(l + po) * c_invf[d], &s, &c);
            float y1 = x1 * c - x2 * s;
            float y2 = x2 * c + x1 * s;
            __half h1 = __float2half_rn(y1);
            __half h2 = __float2half_rn(y2);
            size_t o = (size_t)(m0 + row) * N + n0 + cl;
            Chi[o]      = h1;
            Chi[o + 32] = h2;
            if (need_lo) {
                Clo[o]      = __float2half_rn(y1 - __half2float(h1));
                Clo[o + 32] = __float2half_rn(y2 - __half2float(h2));
            }
        }
    }
}

// ===========================================================================
// fp16 2-product causal flash attention.
// Q split (hi+lo in regs); K, V hi only. scores = (Qh+Ql)Kh; O = (Ph+Pl)Vh.
// 3-stage KV pipeline (16KB/stage), one sync per tile.
// ===========================================================================
#define FQH 0
#define FQL 16384
#define FST 32768
#define FSTG 16384
#define FA_SMEM (FST + 3 * FSTG)   // 81920

__global__ __launch_bounds__(256, 1) void attn_mma(
    const __half* __restrict__ qkvh,
    const __half* __restrict__ qkvl,
    __half* __restrict__ ohp,
    __half* __restrict__ olp)
{
    const uint32_t sbu = smem_u32(dyn_smem);
    const int tid  = threadIdx.x;
    const int wid  = tid >> 5;
    const int lane = tid & 31;
    const int lrow = lane & 15;
    const int lhalf = (lane >> 4) * 16;

    const int qt = gridDim.x - 1 - blockIdx.x;
    const int bh = blockIdx.y;
    const int b  = bh / N_HEADS_C;
    const int h  = bh % N_HEADS_C;
    const size_t rowbase = (size_t)b * L_SEQ;

    // queue Q tiles (hi, lo)
    {
        int op  = tid >> 7;
        int row = tid & 127;
        const __half* src = (op ? qkvl : qkvh)
            + (rowbase + qt * 128 + row) * QKV_COLS + h * DH;
        uint32_t dstb = sbu + (op ? FQL : FQH);
#pragma unroll
        for (int c = 0; c < 8; c++)
            CP_ASYNC16(dstb + sw128(row * 128 + c * 16), src + c * 8);
        CP_COMMIT();
    }

    const int ktmax = 2 * qt + 1;

    // KV stage: Kh 8KB + Vh 8KB = 16KB; 1024 16B-units / 256 thr = 4 each
    auto load_kv = [&](int kt, int s) {
#pragma unroll
        for (int i = 0; i < 4; i++) {
            int u = tid + i * 256;
            int t = u >> 9;                        // 0: K, 1: V
            int v = u & 511;
            int row = v >> 3;
            int q = v & 7;
            const __half* src = qkvh + (rowbase + kt * 64 + row) * QKV_COLS
                              + (1 + t) * D_MODEL + h * DH + q * 8;
            uint32_t dst = sbu + FST + s * FSTG + t * 8192 + sw128(row * 128 + q * 16);
            CP_ASYNC16(dst, src);
        }
        CP_COMMIT();
    };

    load_kv(0, 0);
    load_kv(1, 1);

    CP_WAIT(2);
    __syncthreads();
    uint32_t qh[4][4], ql[4][4];
#pragma unroll
    for (int c = 0; c < 4; c++) {
        uint32_t o = sw128((wid * 16 + lrow) * 128 + c * 32 + lhalf);
        LDSM_X4(qh[c][0], qh[c][1], qh[c][2], qh[c][3], sbu + FQH + o);
        LDSM_X4(ql[c][0], ql[c][1], ql[c][2], ql[c][3], sbu + FQL + o);
    }

    float oa[8][4];
#pragma unroll
    for (int nt = 0; nt < 8; nt++)
#pragma unroll
        for (int r = 0; r < 4; r++) oa[nt][r] = 0.f;
    float m0 = -INFINITY, m1 = -INFINITY, l0 = 0.f, l1 = 0.f;

    const int row0 = qt * 128 + wid * 16 + (lane >> 2);
    const int row1 = row0 + 8;
    const int colq = 2 * (lane & 3);

    for (int kt = 0; kt <= ktmax; kt++) {
        if (kt + 1 <= ktmax) { CP_WAIT(1); } else { CP_WAIT(0); }
        __syncthreads();
        if (kt + 2 <= ktmax) load_kv(kt + 2, (kt + 2) % 3);

        const uint32_t su = sbu + FST + (kt % 3) * FSTG;
        const uint32_t KH = su, VH = su + 8192;

        float sc[8][4];
#pragma unroll
        for (int nt = 0; nt < 8; nt++)
#pragma unroll
            for (int r = 0; r < 4; r++) sc[nt][r] = 0.f;

#pragma unroll
        for (int c = 0; c < 4; c++) {
            const uint32_t kb = c * 32 + lhalf;
#pragma unroll
            for (int g = 0; g < 4; g++) {
                uint32_t o = sw128((g * 16 + lrow) * 128 + kb);
                uint32_t kh4[4];
                LDSM_X4(kh4[0], kh4[1], kh4[2], kh4[3], KH + o);
                MMA_F16(sc[2 * g],     qh[c], kh4[0], kh4[2]);
                MMA_F16(sc[2 * g + 1], qh[c], kh4[1], kh4[3]);
                MMA_F16(sc[2 * g],     ql[c], kh4[0], kh4[2]);
                MMA_F16(sc[2 * g + 1], ql[c], kh4[1], kh4[3]);
            }
        }

        const bool diag = (kt >= 2 * qt);
#pragma unroll
        for (int nt = 0; nt < 8; nt++) {
            int colg = kt * 64 + nt * 8 + colq;
#pragma unroll
            for (int r = 0; r < 4; r++) {
                float s = sc[nt][r] * 0.125f;
                if (diag) {
                    int cg = colg + (r & 1);
                    int rg = (r < 2) ? row0 : row1;
                    if (cg > rg) s = -1e30f;
                }
                sc[nt][r] = s;
            }
        }

        float rm0 = -INFINITY, rm1 = -INFINITY;
#pragma unroll
        for (int nt = 0; nt < 8; nt++) {
            rm0 = fmaxf(rm0, fmaxf(sc[nt][0], sc[nt][1]));
            rm1 = fmaxf(rm1, fmaxf(sc[nt][2], sc[nt][3]));
        }
        rm0 = fmaxf(rm0, __shfl_xor_sync(0xffffffffu, rm0, 1));
        rm0 = fmaxf(rm0, __shfl_xor_sync(0xffffffffu, rm0, 2));
        rm1 = fmaxf(rm1, __shfl_xor_sync(0xffffffffu, rm1, 1));
        rm1 = fmaxf(rm1, __shfl_xor_sync(0xffffffffu, rm1, 2));

        float m0n = fmaxf(m0, rm0), m1n = fmaxf(m1, rm1);
        float cr0 = __expf(m0 - m0n), cr1 = __expf(m1 - m1n);
        l0 *= cr0; l1 *= cr1;
#pragma unroll
        for (int nt = 0; nt < 8; nt++) {
            oa[nt][0] *= cr0; oa[nt][1] *= cr0;
            oa[nt][2] *= cr1; oa[nt][3] *= cr1;
        }
        m0 = m0n; m1 = m1n;

        // p = exp(s - m); split to fp16 hi/lo
        uint32_t pha[8], phb[8], pla[8], plb[8];
#pragma unroll
        for (int nt = 0; nt < 8; nt++) {
            float p0 = __expf(sc[nt][0] - m0n);
            float p1 = __expf(sc[nt][1] - m0n);
            float p2 = __expf(sc[nt][2] - m1n);
            float p3 = __expf(sc[nt][3] - m1n);
            l0 += p0 + p1; l1 += p2 + p3;
            uint32_t h01 = pack_f16(p0, p1);
            uint32_t h23 = pack_f16(p2, p3);
            pha[nt] = h01; phb[nt] = h23;
            __half2 hh01 = *(__half2*)&h01;
            __half2 hh23 = *(__half2*)&h23;
            pla[nt] = pack_f16(p0 - __half2float(__low2half(hh01)),
                               p1 - __half2float(__high2half(hh01)));
            plb[nt] = pack_f16(p2 - __half2float(__low2half(hh23)),
                               p3 - __half2float(__high2half(hh23)));
        }

        // O += (Ph+Pl) * Vh
#pragma unroll
        for (int kc = 0; kc < 4; kc++) {
            uint32_t pah[4] = { pha[2 * kc], phb[2 * kc], pha[2 * kc + 1], phb[2 * kc + 1] };
            uint32_t pal[4] = { pla[2 * kc], plb[2 * kc], pla[2 * kc + 1], plb[2 * kc + 1] };
#pragma unroll
            for (int dp = 0; dp < 4; dp++) {
                uint32_t o = sw128((kc * 16 + lrow) * 128 + dp * 32 + lhalf);
                uint32_t vh4[4];
                LDSM_X4_T(vh4[0], vh4[1], vh4[2], vh4[3], VH + o);
                MMA_F16(oa[2 * dp],     pah, vh4[0], vh4[1]);
                MMA_F16(oa[2 * dp + 1], pah, vh4[2], vh4[3]);
                MMA_F16(oa[2 * dp],     pal, vh4[0], vh4[1]);
                MMA_F16(oa[2 * dp + 1], pal, vh4[2], vh4[3]);
            }
        }
    }

    l0 += __shfl_xor_sync(0xffffffffu, l0, 1);
    l0 += __shfl_xor_sync(0xffffffffu, l0, 2);
    l1 += __shfl_xor_sync(0xffffffffu, l1, 1);
    l1 += __shfl_xor_sync(0xffffffffu, l1, 2);
    float i0 = 1.f / l0, i1 = 1.f / l1;

    // epilogue: normalize, split to fp16 hi/lo (A-side of out-proj)
    size_t ob0 = (rowbase + row0) * D_MODEL + h * DH;
    size_t ob1 = (rowbase + row1) * D_MODEL + h * DH;
#pragma unroll
    for (int nt = 0; nt < 8; nt++) {
        int col = nt * 8 + colq;
        float a0 = oa[nt][0] * i0, a1 = oa[nt][1] * i0;
        float a2 = oa[nt][2] * i1, a3 = oa[nt][3] * i1;
        uint32_t h01 = pack_f16(a0, a1);
        uint32_t h23 = pack_f16(a2, a3);
        __half2 hh01 = *(__half2*)&h01;
        __half2 hh23 = *(__half2*)&h23;
        *(uint32_t*)(ohp + ob0 + col) = h01;
        *(uint32_t*)(olp + ob0 + col) = pack_f16(a0 - __half2float(__low2half(hh01)),
                                                 a1 - __half2float(__high2half(hh01)));
        *(uint32_t*)(ohp + ob1 + col) = h23;
        *(uint32_t*)(olp + ob1 + col) = pack_f16(a2 - __half2float(__low2half(hh23)),
                                                 a3 - __half2float(__high2half(hh23)));
    }
}

// ===========================================================================
// launch
// ===========================================================================
extern "C" void kernel_launch(void* const* d_in, const int* in_sizes, int n_in,
                              void* d_out, int out_size)
{
    const float* x     = (const float*)d_in[0];
    const float* w_qkv = (const float*)d_in[1];
    const float* w_out = (const float*)d_in[2];
    const int*   pos   = (const int*)d_in[3];
    float*       out   = (float*)d_out;

    __half *qkvh, *qkvl, *xh, *xl, *wqh, *ah, *al, *woh;
    cudaGetSymbolAddress((void**)&qkvh, g_qkvh); cudaGetSymbolAddress((void**)&qkvl, g_qkvl);
    cudaGetSymbolAddress((void**)&xh, g_xh);   cudaGetSymbolAddress((void**)&xl, g_xl);
    cudaGetSymbolAddress((void**)&wqh, g_wqh);
    cudaGetSymbolAddress((void**)&ah, g_ah);   cudaGetSymbolAddress((void**)&al, g_al);
    cudaGetSymbolAddress((void**)&woh, g_woh);

    cudaFuncSetAttribute(gemm_f16x2, cudaFuncAttributeMaxDynamicSharedMemorySize, GEMM_SMEM);
    cudaFuncSetAttribute(attn_mma, cudaFuncAttributeMaxDynamicSharedMemorySize, FA_SMEM);

    // 1) split x (A side); convert weights (B side, hi only)
    split_f16<<<(M_ROWS * K_DIM / 4 + 255) / 256, 256>>>(x, xh, xl, M_ROWS * K_DIM / 4);
    conv_f16<<<(QKV_COLS * K_DIM / 4 + 255) / 256, 256>>>(w_qkv, wqh, QKV_COLS * K_DIM / 4);

    // 2) QKV projection with fused RoPE + fp16 hi/lo epilogue
    gemm_f16x2<<<dim3(QKV_COLS / 128, M_ROWS / 128), 256, GEMM_SMEM>>>(
        xh, xl, wqh, nullptr, qkvh, qkvl, pos, QKV_COLS);

    // 3) fp16 2-product causal flash attention -> ah/al
    attn_mma<<<dim3(L_SEQ / 128, B_SZ * N_HEADS_C), 256, FA_SMEM>>>(qkvh, qkvl, ah, al);

    // 4) output projection (fp32 epilogue to d_out)
    conv_f16<<<(D_MODEL * K_DIM / 4 + 255) / 256, 256>>>(w_out, woh, D_MODEL * K_DIM / 4);
    gemm_f16x2<<<dim3(D_MODEL / 128, M_ROWS / 128), 256, GEMM_SMEM>>>(
        ah, al, woh, out, nullptr, nullptr, nullptr, D_MODEL);
}

// round 14
// speedup vs baseline: 2.5506x; 1.1008x over previous
#include <cuda_runtime.h>
#include <cuda_fp16.h>
#include <math.h>
#include <stdint.h>

// ---------------- problem constants ----------------
#define D_MODEL   1536
#define N_HEADS_C 24
#define DH        64
#define B_SZ      4
#define L_SEQ     2048
#define M_ROWS    (B_SZ * L_SEQ)     // 8192
#define QKV_COLS  (3 * D_MODEL)      // 4608
#define K_DIM     1536

// single dynamic smem symbol shared by all kernels
extern __shared__ char dyn_smem[];

// ---------------- scratch (device globals; no allocation allowed) ---------
__device__ __half g_qkvh[(size_t)M_ROWS * QKV_COLS];
__device__ __half g_xh[(size_t)M_ROWS * K_DIM];
__device__ __half g_xl[(size_t)M_ROWS * K_DIM];
__device__ __half g_wqh[(size_t)QKV_COLS * K_DIM];
__device__ __half g_ah[(size_t)M_ROWS * K_DIM];
__device__ __half g_al[(size_t)M_ROWS * K_DIM];
__device__ __half g_woh[(size_t)D_MODEL * K_DIM];

// inv_freq[d] = 10000^(-d/32) = 10^(-d/8)
__constant__ float c_invf[32] = {
    1.0f, 0.7498942093324559f, 0.5623413251903491f, 0.42169650342858224f,
    0.31622776601683794f, 0.23713737056616552f, 0.1778279410038923f, 0.1333521432163324f,
    0.1f, 0.07498942093324558f, 0.05623413251903491f, 0.042169650342858224f,
    0.031622776601683794f, 0.023713737056616552f, 0.01778279410038923f, 0.01333521432163324f,
    0.01f, 0.007498942093324558f, 0.005623413251903491f, 0.0042169650342858224f,
    0.0031622776601683794f, 0.0023713737056616552f, 0.001778279410038923f, 0.0013335214321633241f,
    0.001f, 0.0007498942093324558f, 0.0005623413251903491f, 0.00042169650342858224f,
    0.00031622776601683794f, 0.00023713737056616552f, 0.0001778279410038923f, 0.00013335214321633242f
};

// ---------------- helpers --------------------------------------------------
__device__ __forceinline__ uint32_t smem_u32(const void* p) {
    uint32_t a;
    asm("{ .reg .u64 t; cvta.to.shared.u64 t, %1; cvt.u32.u64 %0, t; }" : "=r"(a) : "l"(p));
    return a;
}

#define CP_ASYNC16(dst, src) \
    asm volatile("cp.async.cg.shared.global [%0], [%1], 16;" :: "r"(dst), "l"(src))
#define CP_COMMIT() asm volatile("cp.async.commit_group;" ::: "memory")
#define CP_WAIT(N)  asm volatile("cp.async.wait_group %0;" :: "n"(N) : "memory")

#define LDSM_X4(r0, r1, r2, r3, addr) \
    asm volatile("ldmatrix.sync.aligned.m8n8.x4.shared.b16 {%0,%1,%2,%3}, [%4];" \
        : "=r"(r0), "=r"(r1), "=r"(r2), "=r"(r3) : "r"(addr))

#define LDSM_X4_T(r0, r1, r2, r3, addr) \
    asm volatile("ldmatrix.sync.aligned.m8n8.x4.trans.shared.b16 {%0,%1,%2,%3}, [%4];" \
        : "=r"(r0), "=r"(r1), "=r"(r2), "=r"(r3) : "r"(addr))

#define MMA_F16(c, a, b0_, b1_) \
    asm volatile("mma.sync.aligned.m16n8k16.row.col.f32.f16.f16.f32 " \
        "{%0,%1,%2,%3}, {%4,%5,%6,%7}, {%8,%9}, {%0,%1,%2,%3};" \
        : "+f"((c)[0]), "+f"((c)[1]), "+f"((c)[2]), "+f"((c)[3]) \
        : "r"((a)[0]), "r"((a)[1]), "r"((a)[2]), "r"((a)[3]), "r"(b0_), "r"(b1_))

__device__ __forceinline__ uint32_t sw128(uint32_t off) {
    return off ^ ((off >> 3) & 0x70);
}

// pack two floats into fp16x2 (lo -> lower half, hi -> upper half)
__device__ __forceinline__ uint32_t pack_f16(float lo, float hi) {
    uint32_t d;
    asm("cvt.rn.f16x2.f32 %0, %1, %2;" : "=r"(d) : "f"(hi), "f"(lo));
    return d;
}

__device__ __forceinline__ void sincos_rope(float fr, float* s, float* c) {
    float n  = rintf(fr * 0.15915494309189535f);
    float r1 = fmaf(n, -6.2831855f, fr);
    float r  = fmaf(n,  1.7484556e-7f, r1);
    __sincosf(r, s, c);
}

// ===========================================================================
// split fp32 -> fp16 hi + fp16 lo
// ===========================================================================
__global__ __launch_bounds__(256) void split_f16(
    const float* __restrict__ s, __half* __restrict__ hi,
    __half* __restrict__ lo, int n4)
{
    int i = blockIdx.x * blockDim.x + threadIdx.x;
    if (i >= n4) return;
    float4 v = ((const float4*)s)[i];
    __half h0 = __float2half_rn(v.x), h1 = __float2half_rn(v.y);
    __half h2 = __float2half_rn(v.z), h3 = __float2half_rn(v.w);
    __half l0 = __float2half_rn(v.x - __half2float(h0));
    __half l1 = __float2half_rn(v.y - __half2float(h1));
    __half l2 = __float2half_rn(v.z - __half2float(h2));
    __half l3 = __float2half_rn(v.w - __half2float(h3));
    ((ushort4*)hi)[i] = make_ushort4(__half_as_ushort(h0), __half_as_ushort(h1),
                                     __half_as_ushort(h2), __half_as_ushort(h3));
    ((ushort4*)lo)[i] = make_ushort4(__half_as_ushort(l0), __half_as_ushort(l1),
                                     __half_as_ushort(l2), __half_as_ushort(l3));
}

// convert fp32 -> fp16 (hi only, for the B/weight side)
__global__ __launch_bounds__(256) void conv_f16(
    const float* __restrict__ s, __half* __restrict__ hi, int n4)
{
    int i = blockIdx.x * blockDim.x + threadIdx.x;
    if (i >= n4) return;
    float4 v = ((const float4*)s)[i];
    ((ushort4*)hi)[i] = make_ushort4(
        __half_as_ushort(__float2half_rn(v.x)), __half_as_ushort(__float2half_rn(v.y)),
        __half_as_ushort(__float2half_rn(v.z)), __half_as_ushort(__float2half_rn(v.w)));
}

// ===========================================================================
// fp16 2-product GEMM via mma.sync: C = (Ah+Al)[M,K] * Bh[N,K]^T
// BM=BN=128, BK=64, 3-stage cp.async pipeline, one sync per chunk.
// Epilogue: Chi==null -> fp32 to C; else fp16 hi only (q/k get RoPE).
// ===========================================================================
#define GK_CHUNKS 24
#define TILE_B    16384
#define STAGE_B   (3 * TILE_B)            // 48 KB
#define GEMM_SMEM (3 * STAGE_B)           // 144 KB

__global__ __launch_bounds__(256, 1) void gemm_f16x2(
    const __half* __restrict__ Ah, const __half* __restrict__ Al,
    const __half* __restrict__ Bh,
    float* __restrict__ C,
    __half* __restrict__ Chi,
    const int* __restrict__ pos, int N)
{
    const uint32_t sbu = smem_u32(dyn_smem);

    const int tid  = threadIdx.x;
    const int wid  = tid >> 5;
    const int lane = tid & 31;
    const int wm   = wid & 1;
    const int wn   = wid >> 1;
    const int m0   = blockIdx.y * 128;
    const int n0   = blockIdx.x * 128;

    const __half* srcs[3] = {
        Ah + (size_t)m0 * K_DIM, Al + (size_t)m0 * K_DIM,
        Bh + (size_t)n0 * K_DIM };

    int unit_row[4], unit_u[4];
#pragma unroll
    for (int i = 0; i < 4; i++) {
        int unit = tid + i * 256;
        unit_row[i] = unit >> 3;
        unit_u[i]   = unit & 7;
    }

    auto load_stage = [&](int c, int s) {
        uint32_t sb = sbu + s * STAGE_B;
#pragma unroll
        for (int op = 0; op < 3; op++) {
            const __half* src = srcs[op] + c * 64;
            uint32_t ob = sb + op * TILE_B;
#pragma unroll
            for (int i = 0; i < 4; i++) {
                const __half* g = src + (size_t)unit_row[i] * K_DIM + unit_u[i] * 8;
                uint32_t d = ob + sw128(unit_row[i] * 128 + unit_u[i] * 16);
                CP_ASYNC16(d, g);
            }
        }
        CP_COMMIT();
    };

    float acc[4][4][4];
#pragma unroll
    for (int i = 0; i < 4; i++)
#pragma unroll
        for (int j = 0; j < 4; j++)
#pragma unroll
            for (int k = 0; k < 4; k++) acc[i][j][k] = 0.f;

    load_stage(0, 0);
    load_stage(1, 1);

    const int lrow = lane & 15;
    const int lhalf = (lane >> 4) * 16;

    for (int c = 0; c < GK_CHUNKS; c++) {
        if (c + 1 < GK_CHUNKS) { CP_WAIT(1); } else { CP_WAIT(0); }
        __syncthreads();
        if (c + 2 < GK_CHUNKS) load_stage(c + 2, (c + 2) % 3);

        const uint32_t sb = sbu + (c % 3) * STAGE_B;
        const uint32_t aH = sb + 0 * TILE_B;
        const uint32_t aL = sb + 1 * TILE_B;
        const uint32_t bH = sb + 2 * TILE_B;

#pragma unroll
        for (int k16 = 0; k16 < 4; k16++) {
            const uint32_t kb = k16 * 32 + lhalf;
            uint32_t ah[4][4], al[4][4];
#pragma unroll
            for (int i = 0; i < 4; i++) {
                int row = wm * 64 + i * 16 + lrow;
                uint32_t o = sw128(row * 128 + kb);
                LDSM_X4(ah[i][0], ah[i][1], ah[i][2], ah[i][3], aH + o);
                LDSM_X4(al[i][0], al[i][1], al[i][2], al[i][3], aL + o);
            }
            uint32_t bh[2][4];
#pragma unroll
            for (int j = 0; j < 2; j++) {
                int row = wn * 32 + j * 16 + lrow;
                uint32_t o = sw128(row * 128 + kb);
                LDSM_X4(bh[j][0], bh[j][1], bh[j][2], bh[j][3], bH + o);
            }
#pragma unroll
            for (int i = 0; i < 4; i++) {
#pragma unroll
                for (int jn = 0; jn < 4; jn++) {
                    const int j = jn >> 1, s = jn & 1;
                    MMA_F16(acc[i][jn], ah[i], bh[j][s], bh[j][s + 2]);
                    MMA_F16(acc[i][jn], al[i], bh[j][s], bh[j][s + 2]);
                }
            }
        }
    }

    const int er = lane >> 2;
    const int ec = (lane & 3) * 2;

    if (!Chi) {
        // plain fp32 epilogue
#pragma unroll
        for (int i = 0; i < 4; i++) {
            int r0 = m0 + wm * 64 + i * 16 + er;
#pragma unroll
            for (int jn = 0; jn < 4; jn++) {
                int col = n0 + wn * 32 + jn * 8 + ec;
                *(float2*)(C + (size_t)r0 * N + col)       = make_float2(acc[i][jn][0], acc[i][jn][1]);
                *(float2*)(C + (size_t)(r0 + 8) * N + col) = make_float2(acc[i][jn][2], acc[i][jn][3]);
            }
        }
    } else if (n0 >= 2 * D_MODEL) {
        // v section: fp16 hi, direct register path
#pragma unroll
        for (int i = 0; i < 4; i++) {
#pragma unroll
            for (int jn = 0; jn < 4; jn++) {
                int col = n0 + wn * 32 + jn * 8 + ec;
#pragma unroll
                for (int half = 0; half < 2; half++) {
                    int r = m0 + wm * 64 + i * 16 + er + half * 8;
                    size_t o = (size_t)r * N + col;
                    *(uint32_t*)(Chi + o) = pack_f16(acc[i][jn][2 * half], acc[i][jn][2 * half + 1]);
                }
            }
        }
    } else {
        // q/k section: stage tile in smem, apply RoPE, store fp16 hi
        float* Ct = (float*)dyn_smem;                    // [128][130]
        __syncthreads();
#pragma unroll
        for (int i = 0; i < 4; i++) {
            int rl = wm * 64 + i * 16 + er;
#pragma unroll
            for (int jn = 0; jn < 4; jn++) {
                int cl = wn * 32 + jn * 8 + ec;
                Ct[rl * 130 + cl]           = acc[i][jn][0];
                Ct[rl * 130 + cl + 1]       = acc[i][jn][1];
                Ct[(rl + 8) * 130 + cl]     = acc[i][jn][2];
                Ct[(rl + 8) * 130 + cl + 1] = acc[i][jn][3];
            }
        }
        __syncthreads();
        const int po = *pos;
#pragma unroll
        for (int it = 0; it < 32; it++) {
            int idx = tid + it * 256;
            int hd  = idx & 63;
            int row = idx >> 6;
            int d   = hd & 31;
            int cl  = (hd >> 5) * 64 + d;
            float x1 = Ct[row * 130 + cl];
            float x2 = Ct[row * 130 + cl + 32];
            int l = (m0 + row) & (L_SEQ - 1);
            float s, c;
            sincos_rope((float)(l + po) * c_invf[d], &s, &c);
            size_t o = (size_t)(m0 + row) * N + n0 + cl;
            Chi[o]      = __float2half_rn(x1 * c - x2 * s);
            Chi[o + 32] = __float2half_rn(x2 * c + x1 * s);
        }
    }
}

// ===========================================================================
// fp16 1-product causal flash attention: S = Qh*Kh, O = Ph*Vh.
// Output still split to fp16 hi/lo (A-side of out-projection).
// 3-stage KV pipeline (16KB/stage), one sync per tile.
// ===========================================================================
#define FQ  0
#define FST 16384
#define FSTG 16384
#define FA_SMEM (FST + 3 * FSTG)   // 65536

__global__ __launch_bounds__(256, 1) void attn_mma(
    const __half* __restrict__ qkvh,
    __half* __restrict__ ohp,
    __half* __restrict__ olp)
{
    const uint32_t sbu = smem_u32(dyn_smem);
    const int tid  = threadIdx.x;
    const int wid  = tid >> 5;
    const int lane = tid & 31;
    const int lrow = lane & 15;
    const int lhalf = (lane >> 4) * 16;

    const int qt = gridDim.x - 1 - blockIdx.x;
    const int bh = blockIdx.y;
    const int b  = bh / N_HEADS_C;
    const int h  = bh % N_HEADS_C;
    const size_t rowbase = (size_t)b * L_SEQ;

    // queue Q tile (hi only): 1024 16B-units over 256 threads
#pragma unroll
    for (int i = 0; i < 4; i++) {
        int u = tid + i * 256;
        int row = u >> 3;
        int q = u & 7;
        const __half* src = qkvh + (rowbase + qt * 128 + row) * QKV_COLS + h * DH + q * 8;
        CP_ASYNC16(sbu + FQ + sw128(row * 128 + q * 16), src);
    }
    CP_COMMIT();

    const int ktmax = 2 * qt + 1;

    // KV stage: Kh 8KB + Vh 8KB = 16KB
    auto load_kv = [&](int kt, int s) {
#pragma unroll
        for (int i = 0; i < 4; i++) {
            int u = tid + i * 256;
            int t = u >> 9;                        // 0: K, 1: V
            int v = u & 511;
            int row = v >> 3;
            int q = v & 7;
            const __half* src = qkvh + (rowbase + kt * 64 + row) * QKV_COLS
                              + (1 + t) * D_MODEL + h * DH + q * 8;
            uint32_t dst = sbu + FST + s * FSTG + t * 8192 + sw128(row * 128 + q * 16);
            CP_ASYNC16(dst, src);
        }
        CP_COMMIT();
    };

    load_kv(0, 0);
    load_kv(1, 1);

    CP_WAIT(2);
    __syncthreads();
    uint32_t qh[4][4];
#pragma unroll
    for (int c = 0; c < 4; c++) {
        uint32_t o = sw128((wid * 16 + lrow) * 128 + c * 32 + lhalf);
        LDSM_X4(qh[c][0], qh[c][1], qh[c][2], qh[c][3], sbu + FQ + o);
    }

    float oa[8][4];
#pragma unroll
    for (int nt = 0; nt < 8; nt++)
#pragma unroll
        for (int r = 0; r < 4; r++) oa[nt][r] = 0.f;
    float m0 = -INFINITY, m1 = -INFINITY, l0 = 0.f, l1 = 0.f;

    const int row0 = qt * 128 + wid * 16 + (lane >> 2);
    const int row1 = row0 + 8;
    const int colq = 2 * (lane & 3);

    for (int kt = 0; kt <= ktmax; kt++) {
        if (kt + 1 <= ktmax) { CP_WAIT(1); } else { CP_WAIT(0); }
        __syncthreads();
        if (kt + 2 <= ktmax) load_kv(kt + 2, (kt + 2) % 3);

        const uint32_t su = sbu + FST + (kt % 3) * FSTG;
        const uint32_t KH = su, VH = su + 8192;

        float sc[8][4];
#pragma unroll
        for (int nt = 0; nt < 8; nt++)
#pragma unroll
            for (int r = 0; r < 4; r++) sc[nt][r] = 0.f;

        // scores: 1 product
#pragma unroll
        for (int c = 0; c < 4; c++) {
            const uint32_t kb = c * 32 + lhalf;
#pragma unroll
            for (int g = 0; g < 4; g++) {
                uint32_t o = sw128((g * 16 + lrow) * 128 + kb);
                uint32_t kh4[4];
                LDSM_X4(kh4[0], kh4[1], kh4[2], kh4[3], KH + o);
                MMA_F16(sc[2 * g],     qh[c], kh4[0], kh4[2]);
                MMA_F16(sc[2 * g + 1], qh[c], kh4[1], kh4[3]);
            }
        }

        const bool diag = (kt >= 2 * qt);
#pragma unroll
        for (int nt = 0; nt < 8; nt++) {
            int colg = kt * 64 + nt * 8 + colq;
#pragma unroll
            for (int r = 0; r < 4; r++) {
                float s = sc[nt][r] * 0.125f;
                if (diag) {
                    int cg = colg + (r & 1);
                    int rg = (r < 2) ? row0 : row1;
                    if (cg > rg) s = -1e30f;
                }
                sc[nt][r] = s;
            }
        }

        float rm0 = -INFINITY, rm1 = -INFINITY;
#pragma unroll
        for (int nt = 0; nt < 8; nt++) {
            rm0 = fmaxf(rm0, fmaxf(sc[nt][0], sc[nt][1]));
            rm1 = fmaxf(rm1, fmaxf(sc[nt][2], sc[nt][3]));
        }
        rm0 = fmaxf(rm0, __shfl_xor_sync(0xffffffffu, rm0, 1));
        rm0 = fmaxf(rm0, __shfl_xor_sync(0xffffffffu, rm0, 2));
        rm1 = fmaxf(rm1, __shfl_xor_sync(0xffffffffu, rm1, 1));
        rm1 = fmaxf(rm1, __shfl_xor_sync(0xffffffffu, rm1, 2));

        float m0n = fmaxf(m0, rm0), m1n = fmaxf(m1, rm1);
        float cr0 = __expf(m0 - m0n), cr1 = __expf(m1 - m1n);
        l0 *= cr0; l1 *= cr1;
#pragma unroll
        for (int nt = 0; nt < 8; nt++) {
            oa[nt][0] *= cr0; oa[nt][1] *= cr0;
            oa[nt][2] *= cr1; oa[nt][3] *= cr1;
        }
        m0 = m0n; m1 = m1n;

        // p = exp(s - m); fp16 hi only
        uint32_t pha[8], phb[8];
#pragma unroll
        for (int nt = 0; nt < 8; nt++) {
            float p0 = __expf(sc[nt][0] - m0n);
            float p1 = __expf(sc[nt][1] - m0n);
            float p2 = __expf(sc[nt][2] - m1n);
            float p3 = __expf(sc[nt][3] - m1n);
            l0 += p0 + p1; l1 += p2 + p3;
            pha[nt] = pack_f16(p0, p1);
            phb[nt] = pack_f16(p2, p3);
        }

        // O += Ph * Vh (1 product)
#pragma unroll
        for (int kc = 0; kc < 4; kc++) {
            uint32_t pah[4] = { pha[2 * kc], phb[2 * kc], pha[2 * kc + 1], phb[2 * kc + 1] };
#pragma unroll
            for (int dp = 0; dp < 4; dp++) {
                uint32_t o = sw128((kc * 16 + lrow) * 128 + dp * 32 + lhalf);
                uint32_t vh4[4];
                LDSM_X4_T(vh4[0], vh4[1], vh4[2], vh4[3], VH + o);
                MMA_F16(oa[2 * dp],     pah, vh4[0], vh4[1]);
                MMA_F16(oa[2 * dp + 1], pah, vh4[2], vh4[3]);
            }
        }
    }

    l0 += __shfl_xor_sync(0xffffffffu, l0, 1);
    l0 += __shfl_xor_sync(0xffffffffu, l0, 2);
    l1 += __shfl_xor_sync(0xffffffffu, l1, 1);
    l1 += __shfl_xor_sync(0xffffffffu, l1, 2);
    float i0 = 1.f / l0, i1 = 1.f / l1;

    // epilogue: normalize, split to fp16 hi/lo (A-side of out-proj keeps 2-product)
    size_t ob0 = (rowbase + row0) * D_MODEL + h * DH;
    size_t ob1 = (rowbase + row1) * D_MODEL + h * DH;
#pragma unroll
    for (int nt = 0; nt < 8; nt++) {
        int col = nt * 8 + colq;
        float a0 = oa[nt][0] * i0, a1 = oa[nt][1] * i0;
        float a2 = oa[nt][2] * i1, a3 = oa[nt][3] * i1;
        uint32_t h01 = pack_f16(a0, a1);
        uint32_t h23 = pack_f16(a2, a3);
        __half2 hh01 = *(__half2*)&h01;
        __half2 hh23 = *(__half2*)&h23;
        *(uint32_t*)(ohp + ob0 + col) = h01;
        *(uint32_t*)(olp + ob0 + col) = pack_f16(a0 - __half2float(__low2half(hh01)),
                                                 a1 - __half2float(__high2half(hh01)));
        *(uint32_t*)(ohp + ob1 + col) = h23;
        *(uint32_t*)(olp + ob1 + col) = pack_f16(a2 - __half2float(__low2half(hh23)),
                                                 a3 - __half2float(__high2half(hh23)));
    }
}

// ===========================================================================
// launch
// ===========================================================================
extern "C" void kernel_launch(void* const* d_in, const int* in_sizes, int n_in,
                              void* d_out, int out_size)
{
    const float* x     = (const float*)d_in[0];
    const float* w_qkv = (const float*)d_in[1];
    const float* w_out = (const float*)d_in[2];
    const int*   pos   = (const int*)d_in[3];
    float*       out   = (float*)d_out;

    __half *qkvh, *xh, *xl, *wqh, *ah, *al, *woh;
    cudaGetSymbolAddress((void**)&qkvh, g_qkvh);
    cudaGetSymbolAddress((void**)&xh, g_xh);   cudaGetSymbolAddress((void**)&xl, g_xl);
    cudaGetSymbolAddress((void**)&wqh, g_wqh);
    cudaGetSymbolAddress((void**)&ah, g_ah);   cudaGetSymbolAddress((void**)&al, g_al);
    cudaGetSymbolAddress((void**)&woh, g_woh);

    cudaFuncSetAttribute(gemm_f16x2, cudaFuncAttributeMaxDynamicSharedMemorySize, GEMM_SMEM);
    cudaFuncSetAttribute(attn_mma, cudaFuncAttributeMaxDynamicSharedMemorySize, FA_SMEM);

    // 1) split x (A side); convert weights (B side, hi only)
    split_f16<<<(M_ROWS * K_DIM / 4 + 255) / 256, 256>>>(x, xh, xl, M_ROWS * K_DIM / 4);
    conv_f16<<<(QKV_COLS * K_DIM / 4 + 255) / 256, 256>>>(w_qkv, wqh, QKV_COLS * K_DIM / 4);

    // 2) QKV projection with fused RoPE + fp16 epilogue
    gemm_f16x2<<<dim3(QKV_COLS / 128, M_ROWS / 128), 256, GEMM_SMEM>>>(
        xh, xl, wqh, nullptr, qkvh, pos, QKV_COLS);

    // 3) fp16 1-product causal flash attention -> ah/al
    attn_mma<<<dim3(L_SEQ / 128, B_SZ * N_HEADS_C), 256, FA_SMEM>>>(qkvh, ah, al);

    // 4) output projection (2-product, fp32 epilogue to d_out)
    conv_f16<<<(D_MODEL * K_DIM / 4 + 255) / 256, 256>>>(w_out, woh, D_MODEL * K_DIM / 4);
    gemm_f16x2<<<dim3(D_MODEL / 128, M_ROWS / 128), 256, GEMM_SMEM>>>(
        ah, al, woh, out, nullptr, nullptr, D_MODEL);
}

// round 15
// speedup vs baseline: 3.8736x; 1.5187x over previous
#include <cuda_runtime.h>
#include <cuda_fp16.h>
#include <math.h>
#include <stdint.h>

// ---------------- problem constants ----------------
#define D_MODEL   1536
#define N_HEADS_C 24
#define DH        64
#define B_SZ      4
#define L_SEQ     2048
#define M_ROWS    (B_SZ * L_SEQ)     // 8192
#define QKV_COLS  (3 * D_MODEL)      // 4608
#define K_DIM     1536

// single dynamic smem symbol shared by all kernels
extern __shared__ char dyn_smem[];

// ---------------- scratch (device globals; no allocation allowed) ---------
__device__ __half g_qkvh[(size_t)M_ROWS * QKV_COLS];
__device__ __half g_xh[(size_t)M_ROWS * K_DIM];
__device__ __half g_wqh[(size_t)QKV_COLS * K_DIM];
__device__ __half g_ah[(size_t)M_ROWS * K_DIM];
__device__ __half g_woh[(size_t)D_MODEL * K_DIM];

// inv_freq[d] = 10000^(-d/32) = 10^(-d/8)
__constant__ float c_invf[32] = {
    1.0f, 0.7498942093324559f, 0.5623413251903491f, 0.42169650342858224f,
    0.31622776601683794f, 0.23713737056616552f, 0.1778279410038923f, 0.1333521432163324f,
    0.1f, 0.07498942093324558f, 0.05623413251903491f, 0.042169650342858224f,
    0.031622776601683794f, 0.023713737056616552f, 0.01778279410038923f, 0.01333521432163324f,
    0.01f, 0.007498942093324558f, 0.005623413251903491f, 0.0042169650342858224f,
    0.0031622776601683794f, 0.0023713737056616552f, 0.001778279410038923f, 0.0013335214321633241f,
    0.001f, 0.0007498942093324558f, 0.0005623413251903491f, 0.00042169650342858224f,
    0.00031622776601683794f, 0.00023713737056616552f, 0.0001778279410038923f, 0.00013335214321633242f
};

// ---------------- helpers --------------------------------------------------
__device__ __forceinline__ uint32_t smem_u32(const void* p) {
    uint32_t a;
    asm("{ .reg .u64 t; cvta.to.shared.u64 t, %1; cvt.u32.u64 %0, t; }" : "=r"(a) : "l"(p));
    return a;
}

#define CP_ASYNC16(dst, src) \
    asm volatile("cp.async.cg.shared.global [%0], [%1], 16;" :: "r"(dst), "l"(src))
#define CP_COMMIT() asm volatile("cp.async.commit_group;" ::: "memory")
#define CP_WAIT(N)  asm volatile("cp.async.wait_group %0;" :: "n"(N) : "memory")

#define LDSM_X4(r0, r1, r2, r3, addr) \
    asm volatile("ldmatrix.sync.aligned.m8n8.x4.shared.b16 {%0,%1,%2,%3}, [%4];" \
        : "=r"(r0), "=r"(r1), "=r"(r2), "=r"(r3) : "r"(addr))

#define LDSM_X4_T(r0, r1, r2, r3, addr) \
    asm volatile("ldmatrix.sync.aligned.m8n8.x4.trans.shared.b16 {%0,%1,%2,%3}, [%4];" \
        : "=r"(r0), "=r"(r1), "=r"(r2), "=r"(r3) : "r"(addr))

#define MMA_F16(c, a, b0_, b1_) \
    asm volatile("mma.sync.aligned.m16n8k16.row.col.f32.f16.f16.f32 " \
        "{%0,%1,%2,%3}, {%4,%5,%6,%7}, {%8,%9}, {%0,%1,%2,%3};" \
        : "+f"((c)[0]), "+f"((c)[1]), "+f"((c)[2]), "+f"((c)[3]) \
        : "r"((a)[0]), "r"((a)[1]), "r"((a)[2]), "r"((a)[3]), "r"(b0_), "r"(b1_))

__device__ __forceinline__ uint32_t sw128(uint32_t off) {
    return off ^ ((off >> 3) & 0x70);
}

// pack two floats into fp16x2 (lo -> lower half, hi -> upper half)
__device__ __forceinline__ uint32_t pack_f16(float lo, float hi) {
    uint32_t d;
    asm("cvt.rn.f16x2.f32 %0, %1, %2;" : "=r"(d) : "f"(hi), "f"(lo));
    return d;
}

__device__ __forceinline__ void sincos_rope(float fr, float* s, float* c) {
    float n  = rintf(fr * 0.15915494309189535f);
    float r1 = fmaf(n, -6.2831855f, fr);
    float r  = fmaf(n,  1.7484556e-7f, r1);
    __sincosf(r, s, c);
}

// ===========================================================================
// convert fp32 -> fp16
// ===========================================================================
__global__ __launch_bounds__(256) void conv_f16(
    const float* __restrict__ s, __half* __restrict__ hi, int n4)
{
    int i = blockIdx.x * blockDim.x + threadIdx.x;
    if (i >= n4) return;
    float4 v = ((const float4*)s)[i];
    ((ushort4*)hi)[i] = make_ushort4(
        __half_as_ushort(__float2half_rn(v.x)), __half_as_ushort(__float2half_rn(v.y)),
        __half_as_ushort(__float2half_rn(v.z)), __half_as_ushort(__float2half_rn(v.w)));
}

// ===========================================================================
// fp16 1-product GEMM via mma.sync: C = Ah[M,K] * Bh[N,K]^T (fp32 accum)
// BM=BN=128, BK=64, 3-stage cp.async pipeline, one sync per chunk.
// Epilogue: Chi==null -> fp32 to C; else fp16 (q/k sections get RoPE).
// ===========================================================================
#define GK_CHUNKS 24
#define TILE_B    16384
#define STAGE_B   (2 * TILE_B)            // 32 KB: Ah, Bh
#define GEMM_SMEM (3 * STAGE_B)           // 96 KB

__global__ __launch_bounds__(256, 1) void gemm_f16(
    const __half* __restrict__ Ah, const __half* __restrict__ Bh,
    float* __restrict__ C,
    __half* __restrict__ Chi,
    const int* __restrict__ pos, int N)
{
    const uint32_t sbu = smem_u32(dyn_smem);

    const int tid  = threadIdx.x;
    const int wid  = tid >> 5;
    const int lane = tid & 31;
    const int wm   = wid & 1;
    const int wn   = wid >> 1;
    const int m0   = blockIdx.y * 128;
    const int n0   = blockIdx.x * 128;

    const __half* srcs[2] = { Ah + (size_t)m0 * K_DIM, Bh + (size_t)n0 * K_DIM };

    int unit_row[4], unit_u[4];
#pragma unroll
    for (int i = 0; i < 4; i++) {
        int unit = tid + i * 256;
        unit_row[i] = unit >> 3;
        unit_u[i]   = unit & 7;
    }

    auto load_stage = [&](int c, int s) {
        uint32_t sb = sbu + s * STAGE_B;
#pragma unroll
        for (int op = 0; op < 2; op++) {
            const __half* src = srcs[op] + c * 64;
            uint32_t ob = sb + op * TILE_B;
#pragma unroll
            for (int i = 0; i < 4; i++) {
                const __half* g = src + (size_t)unit_row[i] * K_DIM + unit_u[i] * 8;
                uint32_t d = ob + sw128(unit_row[i] * 128 + unit_u[i] * 16);
                CP_ASYNC16(d, g);
            }
        }
        CP_COMMIT();
    };

    float acc[4][4][4];
#pragma unroll
    for (int i = 0; i < 4; i++)
#pragma unroll
        for (int j = 0; j < 4; j++)
#pragma unroll
            for (int k = 0; k < 4; k++) acc[i][j][k] = 0.f;

    load_stage(0, 0);
    load_stage(1, 1);

    const int lrow = lane & 15;
    const int lhalf = (lane >> 4) * 16;

    for (int c = 0; c < GK_CHUNKS; c++) {
        if (c + 1 < GK_CHUNKS) { CP_WAIT(1); } else { CP_WAIT(0); }
        __syncthreads();
        if (c + 2 < GK_CHUNKS) load_stage(c + 2, (c + 2) % 3);

        const uint32_t sb = sbu + (c % 3) * STAGE_B;
        const uint32_t aH = sb;
        const uint32_t bH = sb + TILE_B;

#pragma unroll
        for (int k16 = 0; k16 < 4; k16++) {
            const uint32_t kb = k16 * 32 + lhalf;
            uint32_t ah[4][4];
#pragma unroll
            for (int i = 0; i < 4; i++) {
                int row = wm * 64 + i * 16 + lrow;
                uint32_t o = sw128(row * 128 + kb);
                LDSM_X4(ah[i][0], ah[i][1], ah[i][2], ah[i][3], aH + o);
            }
            uint32_t bh[2][4];
#pragma unroll
            for (int j = 0; j < 2; j++) {
                int row = wn * 32 + j * 16 + lrow;
                uint32_t o = sw128(row * 128 + kb);
                LDSM_X4(bh[j][0], bh[j][1], bh[j][2], bh[j][3], bH + o);
            }
#pragma unroll
            for (int i = 0; i < 4; i++) {
#pragma unroll
                for (int jn = 0; jn < 4; jn++) {
                    const int j = jn >> 1, s = jn & 1;
                    MMA_F16(acc[i][jn], ah[i], bh[j][s], bh[j][s + 2]);
                }
            }
        }
    }

    const int er = lane >> 2;
    const int ec = (lane & 3) * 2;

    if (!Chi) {
        // plain fp32 epilogue (final output projection)
#pragma unroll
        for (int i = 0; i < 4; i++) {
            int r0 = m0 + wm * 64 + i * 16 + er;
#pragma unroll
            for (int jn = 0; jn < 4; jn++) {
                int col = n0 + wn * 32 + jn * 8 + ec;
                *(float2*)(C + (size_t)r0 * N + col)       = make_float2(acc[i][jn][0], acc[i][jn][1]);
                *(float2*)(C + (size_t)(r0 + 8) * N + col) = make_float2(acc[i][jn][2], acc[i][jn][3]);
            }
        }
    } else if (n0 >= 2 * D_MODEL) {
        // v section: fp16, direct register path
#pragma unroll
        for (int i = 0; i < 4; i++) {
#pragma unroll
            for (int jn = 0; jn < 4; jn++) {
                int col = n0 + wn * 32 + jn * 8 + ec;
#pragma unroll
                for (int half = 0; half < 2; half++) {
                    int r = m0 + wm * 64 + i * 16 + er + half * 8;
                    size_t o = (size_t)r * N + col;
                    *(uint32_t*)(Chi + o) = pack_f16(acc[i][jn][2 * half], acc[i][jn][2 * half + 1]);
                }
            }
        }
    } else {
        // q/k section: stage tile in smem, apply RoPE, store fp16
        float* Ct = (float*)dyn_smem;                    // [128][130]
        __syncthreads();
#pragma unroll
        for (int i = 0; i < 4; i++) {
            int rl = wm * 64 + i * 16 + er;
#pragma unroll
            for (int jn = 0; jn < 4; jn++) {
                int cl = wn * 32 + jn * 8 + ec;
                Ct[rl * 130 + cl]           = acc[i][jn][0];
                Ct[rl * 130 + cl + 1]       = acc[i][jn][1];
                Ct[(rl + 8) * 130 + cl]     = acc[i][jn][2];
                Ct[(rl + 8) * 130 + cl + 1] = acc[i][jn][3];
            }
        }
        __syncthreads();
        const int po = *pos;
#pragma unroll
        for (int it = 0; it < 32; it++) {
            int idx = tid + it * 256;
            int hd  = idx & 63;
            int row = idx >> 6;
            int d   = hd & 31;
            int cl  = (hd >> 5) * 64 + d;
            float x1 = Ct[row * 130 + cl];
            float x2 = Ct[row * 130 + cl + 32];
            int l = (m0 + row) & (L_SEQ - 1);
            float s, c;
            sincos_rope((float)(l + po) * c_invf[d], &s, &c);
            size_t o = (size_t)(m0 + row) * N + n0 + cl;
            Chi[o]      = __float2half_rn(x1 * c - x2 * s);
            Chi[o + 32] = __float2half_rn(x2 * c + x1 * s);
        }
    }
}

// ===========================================================================
// fp16 1-product causal flash attention: S = Qh*Kh, O = Ph*Vh. Output fp16.
// 3-stage KV pipeline (16KB/stage), one sync per tile.
// ===========================================================================
#define FQ  0
#define FST 16384
#define FSTG 16384
#define FA_SMEM (FST + 3 * FSTG)   // 65536

__global__ __launch_bounds__(256, 1) void attn_mma(
    const __half* __restrict__ qkvh,
    __half* __restrict__ ohp)
{
    const uint32_t sbu = smem_u32(dyn_smem);
    const int tid  = threadIdx.x;
    const int wid  = tid >> 5;
    const int lane = tid & 31;
    const int lrow = lane & 15;
    const int lhalf = (lane >> 4) * 16;

    const int qt = gridDim.x - 1 - blockIdx.x;
    const int bh = blockIdx.y;
    const int b  = bh / N_HEADS_C;
    const int h  = bh % N_HEADS_C;
    const size_t rowbase = (size_t)b * L_SEQ;

    // queue Q tile: 1024 16B-units over 256 threads
#pragma unroll
    for (int i = 0; i < 4; i++) {
        int u = tid + i * 256;
        int row = u >> 3;
        int q = u & 7;
        const __half* src = qkvh + (rowbase + qt * 128 + row) * QKV_COLS + h * DH + q * 8;
        CP_ASYNC16(sbu + FQ + sw128(row * 128 + q * 16), src);
    }
    CP_COMMIT();

    const int ktmax = 2 * qt + 1;

    auto load_kv = [&](int kt, int s) {
#pragma unroll
        for (int i = 0; i < 4; i++) {
            int u = tid + i * 256;
            int t = u >> 9;                        // 0: K, 1: V
            int v = u & 511;
            int row = v >> 3;
            int q = v & 7;
            const __half* src = qkvh + (rowbase + kt * 64 + row) * QKV_COLS
                              + (1 + t) * D_MODEL + h * DH + q * 8;
            uint32_t dst = sbu + FST + s * FSTG + t * 8192 + sw128(row * 128 + q * 16);
            CP_ASYNC16(dst, src);
        }
        CP_COMMIT();
    };

    load_kv(0, 0);
    load_kv(1, 1);

    CP_WAIT(2);
    __syncthreads();
    uint32_t qh[4][4];
#pragma unroll
    for (int c = 0; c < 4; c++) {
        uint32_t o = sw128((wid * 16 + lrow) * 128 + c * 32 + lhalf);
        LDSM_X4(qh[c][0], qh[c][1], qh[c][2], qh[c][3], sbu + FQ + o);
    }

    float oa[8][4];
#pragma unroll
    for (int nt = 0; nt < 8; nt++)
#pragma unroll
        for (int r = 0; r < 4; r++) oa[nt][r] = 0.f;
    float m0 = -INFINITY, m1 = -INFINITY, l0 = 0.f, l1 = 0.f;

    const int row0 = qt * 128 + wid * 16 + (lane >> 2);
    const int row1 = row0 + 8;
    const int colq = 2 * (lane & 3);

    for (int kt = 0; kt <= ktmax; kt++) {
        if (kt + 1 <= ktmax) { CP_WAIT(1); } else { CP_WAIT(0); }
        __syncthreads();
        if (kt + 2 <= ktmax) load_kv(kt + 2, (kt + 2) % 3);

        const uint32_t su = sbu + FST + (kt % 3) * FSTG;
        const uint32_t KH = su, VH = su + 8192;

        float sc[8][4];
#pragma unroll
        for (int nt = 0; nt < 8; nt++)
#pragma unroll
            for (int r = 0; r < 4; r++) sc[nt][r] = 0.f;

#pragma unroll
        for (int c = 0; c < 4; c++) {
            const uint32_t kb = c * 32 + lhalf;
#pragma unroll
            for (int g = 0; g < 4; g++) {
                uint32_t o = sw128((g * 16 + lrow) * 128 + kb);
                uint32_t kh4[4];
                LDSM_X4(kh4[0], kh4[1], kh4[2], kh4[3], KH + o);
                MMA_F16(sc[2 * g],     qh[c], kh4[0], kh4[2]);
                MMA_F16(sc[2 * g + 1], qh[c], kh4[1], kh4[3]);
            }
        }

        const bool diag = (kt >= 2 * qt);
#pragma unroll
        for (int nt = 0; nt < 8; nt++) {
            int colg = kt * 64 + nt * 8 + colq;
#pragma unroll
            for (int r = 0; r < 4; r++) {
                float s = sc[nt][r] * 0.125f;
                if (diag) {
                    int cg = colg + (r & 1);
                    int rg = (r < 2) ? row0 : row1;
                    if (cg > rg) s = -1e30f;
                }
                sc[nt][r] = s;
            }
        }

        float rm0 = -INFINITY, rm1 = -INFINITY;
#pragma unroll
        for (int nt = 0; nt < 8; nt++) {
            rm0 = fmaxf(rm0, fmaxf(sc[nt][0], sc[nt][1]));
            rm1 = fmaxf(rm1, fmaxf(sc[nt][2], sc[nt][3]));
        }
        rm0 = fmaxf(rm0, __shfl_xor_sync(0xffffffffu, rm0, 1));
        rm0 = fmaxf(rm0, __shfl_xor_sync(0xffffffffu, rm0, 2));
        rm1 = fmaxf(rm1, __shfl_xor_sync(0xffffffffu, rm1, 1));
        rm1 = fmaxf(rm1, __shfl_xor_sync(0xffffffffu, rm1, 2));

        float m0n = fmaxf(m0, rm0), m1n = fmaxf(m1, rm1);
        float cr0 = __expf(m0 - m0n), cr1 = __expf(m1 - m1n);
        l0 *= cr0; l1 *= cr1;
#pragma unroll
        for (int nt = 0; nt < 8; nt++) {
            oa[nt][0] *= cr0; oa[nt][1] *= cr0;
            oa[nt][2] *= cr1; oa[nt][3] *= cr1;
        }
        m0 = m0n; m1 = m1n;

        uint32_t pha[8], phb[8];
#pragma unroll
        for (int nt = 0; nt < 8; nt++) {
            float p0 = __expf(sc[nt][0] - m0n);
            float p1 = __expf(sc[nt][1] - m0n);
            float p2 = __expf(sc[nt][2] - m1n);
            float p3 = __expf(sc[nt][3] - m1n);
            l0 += p0 + p1; l1 += p2 + p3;
            pha[nt] = pack_f16(p0, p1);
            phb[nt] = pack_f16(p2, p3);
        }

#pragma unroll
        for (int kc = 0; kc < 4; kc++) {
            uint32_t pah[4] = { pha[2 * kc], phb[2 * kc], pha[2 * kc + 1], phb[2 * kc + 1] };
#pragma unroll
            for (int dp = 0; dp < 4; dp++) {
                uint32_t o = sw128((kc * 16 + lrow) * 128 + dp * 32 + lhalf);
                uint32_t vh4[4];
                LDSM_X4_T(vh4[0], vh4[1], vh4[2], vh4[3], VH + o);
                MMA_F16(oa[2 * dp],     pah, vh4[0], vh4[1]);
                MMA_F16(oa[2 * dp + 1], pah, vh4[2], vh4[3]);
            }
        }
    }

    l0 += __shfl_xor_sync(0xffffffffu, l0, 1);
    l0 += __shfl_xor_sync(0xffffffffu, l0, 2);
    l1 += __shfl_xor_sync(0xffffffffu, l1, 1);
    l1 += __shfl_xor_sync(0xffffffffu, l1, 2);
    float i0 = 1.f / l0, i1 = 1.f / l1;

    size_t ob0 = (rowbase + row0) * D_MODEL + h * DH;
    size_t ob1 = (rowbase + row1) * D_MODEL + h * DH;
#pragma unroll
    for (int nt = 0; nt < 8; nt++) {
        int col = nt * 8 + colq;
        *(uint32_t*)(ohp + ob0 + col) = pack_f16(oa[nt][0] * i0, oa[nt][1] * i0);
        *(uint32_t*)(ohp + ob1 + col) = pack_f16(oa[nt][2] * i1, oa[nt][3] * i1);
    }
}

// ===========================================================================
// launch
// ===========================================================================
extern "C" void kernel_launch(void* const* d_in, const int* in_sizes, int n_in,
                              void* d_out, int out_size)
{
    const float* x     = (const float*)d_in[0];
    const float* w_qkv = (const float*)d_in[1];
    const float* w_out = (const float*)d_in[2];
    const int*   pos   = (const int*)d_in[3];
    float*       out   = (float*)d_out;

    __half *qkvh, *xh, *wqh, *ah, *woh;
    cudaGetSymbolAddress((void**)&qkvh, g_qkvh);
    cudaGetSymbolAddress((void**)&xh, g_xh);
    cudaGetSymbolAddress((void**)&wqh, g_wqh);
    cudaGetSymbolAddress((void**)&ah, g_ah);
    cudaGetSymbolAddress((void**)&woh, g_woh);

    cudaFuncSetAttribute(gemm_f16, cudaFuncAttributeMaxDynamicSharedMemorySize, GEMM_SMEM);
    cudaFuncSetAttribute(attn_mma, cudaFuncAttributeMaxDynamicSharedMemorySize, FA_SMEM);

    // 1) convert x and w_qkv to fp16
    conv_f16<<<(M_ROWS * K_DIM / 4 + 255) / 256, 256>>>(x, xh, M_ROWS * K_DIM / 4);
    conv_f16<<<(QKV_COLS * K_DIM / 4 + 255) / 256, 256>>>(w_qkv, wqh, QKV_COLS * K_DIM / 4);

    // 2) QKV projection with fused RoPE + fp16 epilogue
    gemm_f16<<<dim3(QKV_COLS / 128, M_ROWS / 128), 256, GEMM_SMEM>>>(
        xh, wqh, nullptr, qkvh, pos, QKV_COLS);

    // 3) fp16 causal flash attention -> ah
    attn_mma<<<dim3(L_SEQ / 128, B_SZ * N_HEADS_C), 256, FA_SMEM>>>(qkvh, ah);

    // 4) output projection (fp32 epilogue to d_out)
    conv_f16<<<(D_MODEL * K_DIM / 4 + 255) / 256, 256>>>(w_out, woh, D_MODEL * K_DIM / 4);
    gemm_f16<<<dim3(D_MODEL / 128, M_ROWS / 128), 256, GEMM_SMEM>>>(
        ah, woh, out, nullptr, nullptr, D_MODEL);
}

// round 17
// speedup vs baseline: 4.3330x; 1.1186x over previous
#include <cuda_runtime.h>
#include <cuda_fp16.h>
#include <math.h>
#include <stdint.h>

// ---------------- problem constants ----------------
#define D_MODEL   1536
#define N_HEADS_C 24
#define DH        64
#define B_SZ      4
#define L_SEQ     2048
#define M_ROWS    (B_SZ * L_SEQ)     // 8192
#define QKV_COLS  (3 * D_MODEL)      // 4608
#define K_DIM     1536

// single dynamic smem symbol shared by all kernels
extern __shared__ char dyn_smem[];

// ---------------- scratch (device globals; no allocation allowed) ---------
__device__ __half g_qkvh[(size_t)M_ROWS * QKV_COLS];
__device__ __half g_xh[(size_t)M_ROWS * K_DIM];
__device__ __half g_wqh[(size_t)QKV_COLS * K_DIM];
__device__ __half g_ah[(size_t)M_ROWS * K_DIM];
__device__ __half g_woh[(size_t)D_MODEL * K_DIM];

// inv_freq[d] = 10000^(-d/32) = 10^(-d/8)
__constant__ float c_invf[32] = {
    1.0f, 0.7498942093324559f, 0.5623413251903491f, 0.42169650342858224f,
    0.31622776601683794f, 0.23713737056616552f, 0.1778279410038923f, 0.1333521432163324f,
    0.1f, 0.07498942093324558f, 0.05623413251903491f, 0.042169650342858224f,
    0.031622776601683794f, 0.023713737056616552f, 0.01778279410038923f, 0.01333521432163324f,
    0.01f, 0.007498942093324558f, 0.005623413251903491f, 0.0042169650342858224f,
    0.0031622776601683794f, 0.0023713737056616552f, 0.001778279410038923f, 0.0013335214321633241f,
    0.001f, 0.0007498942093324558f, 0.0005623413251903491f, 0.00042169650342858224f,
    0.00031622776601683794f, 0.00023713737056616552f, 0.0001778279410038923f, 0.00013335214321633242f
};

// ---------------- helpers --------------------------------------------------
__device__ __forceinline__ uint32_t smem_u32(const void* p) {
    uint32_t a;
    asm("{ .reg .u64 t; cvta.to.shared.u64 t, %1; cvt.u32.u64 %0, t; }" : "=r"(a) : "l"(p));
    return a;
}

#define CP_ASYNC16(dst, src) \
    asm volatile("cp.async.cg.shared.global [%0], [%1], 16;" :: "r"(dst), "l"(src))
#define CP_COMMIT() asm volatile("cp.async.commit_group;" ::: "memory")
#define CP_WAIT(N)  asm volatile("cp.async.wait_group %0;" :: "n"(N) : "memory")

#define LDSM_X4(r0, r1, r2, r3, addr) \
    asm volatile("ldmatrix.sync.aligned.m8n8.x4.shared.b16 {%0,%1,%2,%3}, [%4];" \
        : "=r"(r0), "=r"(r1), "=r"(r2), "=r"(r3) : "r"(addr))

#define LDSM_X4_T(r0, r1, r2, r3, addr) \
    asm volatile("ldmatrix.sync.aligned.m8n8.x4.trans.shared.b16 {%0,%1,%2,%3}, [%4];" \
        : "=r"(r0), "=r"(r1), "=r"(r2), "=r"(r3) : "r"(addr))

#define MMA_F16(c, a, b0_, b1_) \
    asm volatile("mma.sync.aligned.m16n8k16.row.col.f32.f16.f16.f32 " \
        "{%0,%1,%2,%3}, {%4,%5,%6,%7}, {%8,%9}, {%0,%1,%2,%3};" \
        : "+f"((c)[0]), "+f"((c)[1]), "+f"((c)[2]), "+f"((c)[3]) \
        : "r"((a)[0]), "r"((a)[1]), "r"((a)[2]), "r"((a)[3]), "r"(b0_), "r"(b1_))

__device__ __forceinline__ uint32_t sw128(uint32_t off) {
    return off ^ ((off >> 3) & 0x70);
}

// pack two floats into fp16x2 (lo -> lower half, hi -> upper half)
__device__ __forceinline__ uint32_t pack_f16(float lo, float hi) {
    uint32_t d;
    asm("cvt.rn.f16x2.f32 %0, %1, %2;" : "=r"(d) : "f"(hi), "f"(lo));
    return d;
}

__device__ __forceinline__ void sincos_rope(float fr, float* s, float* c) {
    float n  = rintf(fr * 0.15915494309189535f);
    float r1 = fmaf(n, -6.2831855f, fr);
    float r  = fmaf(n,  1.7484556e-7f, r1);
    __sincosf(r, s, c);
}

// ===========================================================================
// convert fp32 -> fp16
// ===========================================================================
__global__ __launch_bounds__(256) void conv_f16(
    const float* __restrict__ s, __half* __restrict__ hi, int n4)
{
    int i = blockIdx.x * blockDim.x + threadIdx.x;
    if (i >= n4) return;
    float4 v = ((const float4*)s)[i];
    ((ushort4*)hi)[i] = make_ushort4(
        __half_as_ushort(__float2half_rn(v.x)), __half_as_ushort(__float2half_rn(v.y)),
        __half_as_ushort(__float2half_rn(v.z)), __half_as_ushort(__float2half_rn(v.w)));
}

// ===========================================================================
// fp16 1-product GEMM via mma.sync (round-15 exact: 1 CTA/SM, no reg cap)
// ===========================================================================
#define GK_CHUNKS 24
#define TILE_B    16384
#define STAGE_B   (2 * TILE_B)            // 32 KB: Ah, Bh
#define GEMM_SMEM (3 * STAGE_B)           // 96 KB

__global__ __launch_bounds__(256) void gemm_f16(
    const __half* __restrict__ Ah, const __half* __restrict__ Bh,
    float* __restrict__ C,
    __half* __restrict__ Chi,
    const int* __restrict__ pos, int N)
{
    const uint32_t sbu = smem_u32(dyn_smem);

    const int tid  = threadIdx.x;
    const int wid  = tid >> 5;
    const int lane = tid & 31;
    const int wm   = wid & 1;
    const int wn   = wid >> 1;
    const int m0   = blockIdx.y * 128;
    const int n0   = blockIdx.x * 128;

    const __half* srcs[2] = { Ah + (size_t)m0 * K_DIM, Bh + (size_t)n0 * K_DIM };

    int unit_row[4], unit_u[4];
#pragma unroll
    for (int i = 0; i < 4; i++) {
        int unit = tid + i * 256;
        unit_row[i] = unit >> 3;
        unit_u[i]   = unit & 7;
    }

    auto load_stage = [&](int c, int s) {
        uint32_t sb = sbu + s * STAGE_B;
#pragma unroll
        for (int op = 0; op < 2; op++) {
            const __half* src = srcs[op] + c * 64;
            uint32_t ob = sb + op * TILE_B;
#pragma unroll
            for (int i = 0; i < 4; i++) {
                const __half* g = src + (size_t)unit_row[i] * K_DIM + unit_u[i] * 8;
                uint32_t d = ob + sw128(unit_row[i] * 128 + unit_u[i] * 16);
                CP_ASYNC16(d, g);
            }
        }
        CP_COMMIT();
    };

    float acc[4][4][4];
#pragma unroll
    for (int i = 0; i < 4; i++)
#pragma unroll
        for (int j = 0; j < 4; j++)
#pragma unroll
            for (int k = 0; k < 4; k++) acc[i][j][k] = 0.f;

    load_stage(0, 0);
    load_stage(1, 1);

    const int lrow = lane & 15;
    const int lhalf = (lane >> 4) * 16;

    for (int c = 0; c < GK_CHUNKS; c++) {
        if (c + 1 < GK_CHUNKS) { CP_WAIT(1); } else { CP_WAIT(0); }
        __syncthreads();
        if (c + 2 < GK_CHUNKS) load_stage(c + 2, (c + 2) % 3);

        const uint32_t sb = sbu + (c % 3) * STAGE_B;
        const uint32_t aH = sb;
        const uint32_t bH = sb + TILE_B;

#pragma unroll
        for (int k16 = 0; k16 < 4; k16++) {
            const uint32_t kb = k16 * 32 + lhalf;
            uint32_t ah[4][4];
#pragma unroll
            for (int i = 0; i < 4; i++) {
                int row = wm * 64 + i * 16 + lrow;
                uint32_t o = sw128(row * 128 + kb);
                LDSM_X4(ah[i][0], ah[i][1], ah[i][2], ah[i][3], aH + o);
            }
            uint32_t bh[2][4];
#pragma unroll
            for (int j = 0; j < 2; j++) {
                int row = wn * 32 + j * 16 + lrow;
                uint32_t o = sw128(row * 128 + kb);
                LDSM_X4(bh[j][0], bh[j][1], bh[j][2], bh[j][3], bH + o);
            }
#pragma unroll
            for (int i = 0; i < 4; i++) {
#pragma unroll
                for (int jn = 0; jn < 4; jn++) {
                    const int j = jn >> 1, s = jn & 1;
                    MMA_F16(acc[i][jn], ah[i], bh[j][s], bh[j][s + 2]);
                }
            }
        }
    }

    const int er = lane >> 2;
    const int ec = (lane & 3) * 2;

    if (!Chi) {
        // plain fp32 epilogue (final output projection)
#pragma unroll
        for (int i = 0; i < 4; i++) {
            int r0 = m0 + wm * 64 + i * 16 + er;
#pragma unroll
            for (int jn = 0; jn < 4; jn++) {
                int col = n0 + wn * 32 + jn * 8 + ec;
                *(float2*)(C + (size_t)r0 * N + col)       = make_float2(acc[i][jn][0], acc[i][jn][1]);
                *(float2*)(C + (size_t)(r0 + 8) * N + col) = make_float2(acc[i][jn][2], acc[i][jn][3]);
            }
        }
    } else if (n0 >= 2 * D_MODEL) {
        // v section: fp16, direct register path
#pragma unroll
        for (int i = 0; i < 4; i++) {
#pragma unroll
            for (int jn = 0; jn < 4; jn++) {
                int col = n0 + wn * 32 + jn * 8 + ec;
#pragma unroll
                for (int half = 0; half < 2; half++) {
                    int r = m0 + wm * 64 + i * 16 + er + half * 8;
                    size_t o = (size_t)r * N + col;
                    *(uint32_t*)(Chi + o) = pack_f16(acc[i][jn][2 * half], acc[i][jn][2 * half + 1]);
                }
            }
        }
    } else {
        // q/k section: stage tile in smem, apply RoPE, store fp16
        float* Ct = (float*)dyn_smem;                    // [128][130]
        __syncthreads();
#pragma unroll
        for (int i = 0; i < 4; i++) {
            int rl = wm * 64 + i * 16 + er;
#pragma unroll
            for (int jn = 0; jn < 4; jn++) {
                int cl = wn * 32 + jn * 8 + ec;
                Ct[rl * 130 + cl]           = acc[i][jn][0];
                Ct[rl * 130 + cl + 1]       = acc[i][jn][1];
                Ct[(rl + 8) * 130 + cl]     = acc[i][jn][2];
                Ct[(rl + 8) * 130 + cl + 1] = acc[i][jn][3];
            }
        }
        __syncthreads();
        const int po = *pos;
#pragma unroll
        for (int it = 0; it < 32; it++) {
            int idx = tid + it * 256;
            int hd  = idx & 63;
            int row = idx >> 6;
            int d   = hd & 31;
            int cl  = (hd >> 5) * 64 + d;
            float x1 = Ct[row * 130 + cl];
            float x2 = Ct[row * 130 + cl + 32];
            int l = (m0 + row) & (L_SEQ - 1);
            float s, c;
            sincos_rope((float)(l + po) * c_invf[d], &s, &c);
            size_t o = (size_t)(m0 + row) * N + n0 + cl;
            Chi[o]      = __float2half_rn(x1 * c - x2 * s);
            Chi[o + 32] = __float2half_rn(x2 * c + x1 * s);
        }
    }
}

// ===========================================================================
// fp16 causal flash attention, base-2 softmax domain:
//   s2 = raw * (0.125 * log2(e));  p = exp2(s2 - m2)
// 3-stage KV pipeline (16KB/stage), one sync per tile.
// ===========================================================================
#define FQ  0
#define FST 16384
#define FSTG 16384
#define FA_SMEM (FST + 3 * FSTG)   // 65536
#define SCALE2 0.1803368801111244f   // 0.125 * log2(e)

__global__ __launch_bounds__(256, 1) void attn_mma(
    const __half* __restrict__ qkvh,
    __half* __restrict__ ohp)
{
    const uint32_t sbu = smem_u32(dyn_smem);
    const int tid  = threadIdx.x;
    const int wid  = tid >> 5;
    const int lane = tid & 31;
    const int lrow = lane & 15;
    const int lhalf = (lane >> 4) * 16;

    const int qt = gridDim.x - 1 - blockIdx.x;
    const int bh = blockIdx.y;
    const int b  = bh / N_HEADS_C;
    const int h  = bh % N_HEADS_C;
    const size_t rowbase = (size_t)b * L_SEQ;

    // queue Q tile: 1024 16B-units over 256 threads
#pragma unroll
    for (int i = 0; i < 4; i++) {
        int u = tid + i * 256;
        int row = u >> 3;
        int q = u & 7;
        const __half* src = qkvh + (rowbase + qt * 128 + row) * QKV_COLS + h * DH + q * 8;
        CP_ASYNC16(sbu + FQ + sw128(row * 128 + q * 16), src);
    }
    CP_COMMIT();

    const int ktmax = 2 * qt + 1;

    auto load_kv = [&](int kt, int s) {
#pragma unroll
        for (int i = 0; i < 4; i++) {
            int u = tid + i * 256;
            int t = u >> 9;                        // 0: K, 1: V
            int v = u & 511;
            int row = v >> 3;
            int q = v & 7;
            const __half* src = qkvh + (rowbase + kt * 64 + row) * QKV_COLS
                              + (1 + t) * D_MODEL + h * DH + q * 8;
            uint32_t dst = sbu + FST + s * FSTG + t * 8192 + sw128(row * 128 + q * 16);
            CP_ASYNC16(dst, src);
        }
        CP_COMMIT();
    };

    load_kv(0, 0);
    load_kv(1, 1);

    CP_WAIT(2);
    __syncthreads();
    uint32_t qh[4][4];
#pragma unroll
    for (int c = 0; c < 4; c++) {
        uint32_t o = sw128((wid * 16 + lrow) * 128 + c * 32 + lhalf);
        LDSM_X4(qh[c][0], qh[c][1], qh[c][2], qh[c][3], sbu + FQ + o);
    }

    float oa[8][4];
#pragma unroll
    for (int nt = 0; nt < 8; nt++)
#pragma unroll
        for (int r = 0; r < 4; r++) oa[nt][r] = 0.f;
    float m0 = -INFINITY, m1 = -INFINITY, l0 = 0.f, l1 = 0.f;

    const int row0 = qt * 128 + wid * 16 + (lane >> 2);
    const int row1 = row0 + 8;
    const int colq = 2 * (lane & 3);

    for (int kt = 0; kt <= ktmax; kt++) {
        if (kt + 1 <= ktmax) { CP_WAIT(1); } else { CP_WAIT(0); }
        __syncthreads();
        if (kt + 2 <= ktmax) load_kv(kt + 2, (kt + 2) % 3);

        const uint32_t su = sbu + FST + (kt % 3) * FSTG;
        const uint32_t KH = su, VH = su + 8192;

        float sc[8][4];
#pragma unroll
        for (int nt = 0; nt < 8; nt++)
#pragma unroll
            for (int r = 0; r < 4; r++) sc[nt][r] = 0.f;

#pragma unroll
        for (int c = 0; c < 4; c++) {
            const uint32_t kb = c * 32 + lhalf;
#pragma unroll
            for (int g = 0; g < 4; g++) {
                uint32_t o = sw128((g * 16 + lrow) * 128 + kb);
                uint32_t kh4[4];
                LDSM_X4(kh4[0], kh4[1], kh4[2], kh4[3], KH + o);
                MMA_F16(sc[2 * g],     qh[c], kh4[0], kh4[2]);
                MMA_F16(sc[2 * g + 1], qh[c], kh4[1], kh4[3]);
            }
        }

        // scale into base-2 domain + causal mask (diag tiles only)
        const bool diag = (kt >= 2 * qt);
#pragma unroll
        for (int nt = 0; nt < 8; nt++) {
            int colg = kt * 64 + nt * 8 + colq;
#pragma unroll
            for (int r = 0; r < 4; r++) {
                float s = sc[nt][r] * SCALE2;
                if (diag) {
                    int cg = colg + (r & 1);
                    int rg = (r < 2) ? row0 : row1;
                    if (cg > rg) s = -1e30f;
                }
                sc[nt][r] = s;
            }
        }

        float rm0 = -INFINITY, rm1 = -INFINITY;
#pragma unroll
        for (int nt = 0; nt < 8; nt++) {
            rm0 = fmaxf(rm0, fmaxf(sc[nt][0], sc[nt][1]));
            rm1 = fmaxf(rm1, fmaxf(sc[nt][2], sc[nt][3]));
        }
        rm0 = fmaxf(rm0, __shfl_xor_sync(0xffffffffu, rm0, 1));
        rm0 = fmaxf(rm0, __shfl_xor_sync(0xffffffffu, rm0, 2));
        rm1 = fmaxf(rm1, __shfl_xor_sync(0xffffffffu, rm1, 1));
        rm1 = fmaxf(rm1, __shfl_xor_sync(0xffffffffu, rm1, 2));

        float m0n = fmaxf(m0, rm0), m1n = fmaxf(m1, rm1);
        float cr0 = exp2f(m0 - m0n), cr1 = exp2f(m1 - m1n);
        l0 *= cr0; l1 *= cr1;
#pragma unroll
        for (int nt = 0; nt < 8; nt++) {
            oa[nt][0] *= cr0; oa[nt][1] *= cr0;
            oa[nt][2] *= cr1; oa[nt][3] *= cr1;
        }
        m0 = m0n; m1 = m1n;

        uint32_t pha[8], phb[8];
#pragma unroll
        for (int nt = 0; nt < 8; nt++) {
            float p0 = exp2f(sc[nt][0] - m0n);
            float p1 = exp2f(sc[nt][1] - m0n);
            float p2 = exp2f(sc[nt][2] - m1n);
            float p3 = exp2f(sc[nt][3] - m1n);
            l0 += p0 + p1; l1 += p2 + p3;
            pha[nt] = pack_f16(p0, p1);
            phb[nt] = pack_f16(p2, p3);
        }

#pragma unroll
        for (int kc = 0; kc < 4; kc++) {
            uint32_t pah[4] = { pha[2 * kc], phb[2 * kc], pha[2 * kc + 1], phb[2 * kc + 1] };
#pragma unroll
            for (int dp = 0; dp < 4; dp++) {
                uint32_t o = sw128((kc * 16 + lrow) * 128 + dp * 32 + lhalf);
                uint32_t vh4[4];
                LDSM_X4_T(vh4[0], vh4[1], vh4[2], vh4[3], VH + o);
                MMA_F16(oa[2 * dp],     pah, vh4[0], vh4[1]);
                MMA_F16(oa[2 * dp + 1], pah, vh4[2], vh4[3]);
            }
        }
    }

    l0 += __shfl_xor_sync(0xffffffffu, l0, 1);
    l0 += __shfl_xor_sync(0xffffffffu, l0, 2);
    l1 += __shfl_xor_sync(0xffffffffu, l1, 1);
    l1 += __shfl_xor_sync(0xffffffffu, l1, 2);
    float i0 = 1.f / l0, i1 = 1.f / l1;

    size_t ob0 = (rowbase + row0) * D_MODEL + h * DH;
    size_t ob1 = (rowbase + row1) * D_MODEL + h * DH;
#pragma unroll
    for (int nt = 0; nt < 8; nt++) {
        int col = nt * 8 + colq;
        *(uint32_t*)(ohp + ob0 + col) = pack_f16(oa[nt][0] * i0, oa[nt][1] * i0);
        *(uint32_t*)(ohp + ob1 + col) = pack_f16(oa[nt][2] * i1, oa[nt][3] * i1);
    }
}

// ===========================================================================
// launch
// ===========================================================================
extern "C" void kernel_launch(void* const* d_in, const int* in_sizes, int n_in,
                              void* d_out, int out_size)
{
    const float* x     = (const float*)d_in[0];
    const float* w_qkv = (const float*)d_in[1];
    const float* w_out = (const float*)d_in[2];
    const int*   pos   = (const int*)d_in[3];
    float*       out   = (float*)d_out;

    __half *qkvh, *xh, *wqh, *ah, *woh;
    cudaGetSymbolAddress((void**)&qkvh, g_qkvh);
    cudaGetSymbolAddress((void**)&xh, g_xh);
    cudaGetSymbolAddress((void**)&wqh, g_wqh);
    cudaGetSymbolAddress((void**)&ah, g_ah);
    cudaGetSymbolAddress((void**)&woh, g_woh);

    cudaFuncSetAttribute(gemm_f16, cudaFuncAttributeMaxDynamicSharedMemorySize, GEMM_SMEM);
    cudaFuncSetAttribute(attn_mma, cudaFuncAttributeMaxDynamicSharedMemorySize, FA_SMEM);

    // 1) converts
    conv_f16<<<(M_ROWS * K_DIM / 4 + 255) / 256, 256>>>(x, xh, M_ROWS * K_DIM / 4);
    conv_f16<<<(QKV_COLS * K_DIM / 4 + 255) / 256, 256>>>(w_qkv, wqh, QKV_COLS * K_DIM / 4);
    conv_f16<<<(D_MODEL * K_DIM / 4 + 255) / 256, 256>>>(w_out, woh, D_MODEL * K_DIM / 4);

    // 2) QKV projection with fused RoPE + fp16 epilogue
    gemm_f16<<<dim3(QKV_COLS / 128, M_ROWS / 128), 256, GEMM_SMEM>>>(
        xh, wqh, nullptr, qkvh, pos, QKV_COLS);

    // 3) fp16 causal flash attention -> ah
    attn_mma<<<dim3(L_SEQ / 128, B_SZ * N_HEADS_C), 256, FA_SMEM>>>(qkvh, ah);

    // 4) output projection (fp32 epilogue to d_out)
    gemm_f16<<<dim3(D_MODEL / 128, M_ROWS / 128), 256, GEMM_SMEM>>>(
        ah, woh, out, nullptr, nullptr, D_MODEL);
}